// round 12
// baseline (speedup 1.0000x reference)
#include <cuda_runtime.h>
#include <cuda_bf16.h>
#include <math.h>
#include <stdint.h>

// ---------------- problem constants ----------------
#define BATCH 4
#define TLEN  512
#define NTOK  (BATCH*TLEN)
#define DIN   80
#define KPAD  96
#define DOUT  4096
#define DMODEL 512
#define DHID  1024
#define NEXP  4
#define NLAYER 8
#define NHEAD 8
#define DH    64
#define MMEM  64
#define SFULL (TLEN+MMEM)
#define BSF   (BATCH*SFULL)
#define QKV_ROWS (NTOK + 2*BSF)

// ---------------- device scratch ----------------
__device__ float g_embed[NTOK*DMODEL];
__device__ float g_cur[NTOK*DMODEL];
__device__ float g_p[NTOK*DMODEL];
__device__ float g_tmp[NTOK*DMODEL];
__device__ float g_gtok[NLAYER*NTOK];
__device__ float g_imp[NLAYER*NEXP];
__device__ int   g_cnt[NLAYER*NEXP];
__device__ int   g_lists[NLAYER*NEXP*NTOK];
__device__ int   g_maps[3*NTOK];

#define WPOOL (40u*1024u*1024u)
__device__ __nv_bfloat16 g_whi[WPOOL];
__device__ __nv_bfloat16 g_wlo[WPOOL];
__device__ __nv_bfloat16 g_ahi[NTOK*DMODEL];
__device__ __nv_bfloat16 g_alo[NTOK*DMODEL];
__device__ __nv_bfloat16 g_bhi[NTOK*DHID];
__device__ __nv_bfloat16 g_blo[NTOK*DHID];
__device__ __nv_bfloat16 g_ehi[NTOK*DMODEL];
__device__ __nv_bfloat16 g_elo[NTOK*DMODEL];
__device__ __nv_bfloat16 g_xhi[NTOK*KPAD];
__device__ __nv_bfloat16 g_xlo[NTOK*KPAD];
__device__ __nv_bfloat16 g_qkvh[QKV_ROWS*DMODEL];
__device__ __nv_bfloat16 g_qkvl[QKV_ROWS*DMODEL];

#define OFF_EMBW2 0u
#define OFF_EMBWO (OFF_EMBW2 + 512u*1024u)
#define OFF_F0W2  (OFF_EMBWO + 4096u*512u)
#define OFF_FW1   (OFF_F0W2 + 4u*512u*1024u)
#define OFF_FW2   (OFF_FW1 + 28u*1024u*512u)
#define OFF_QKV   (OFF_FW2 + 28u*512u*1024u)
#define OFF_WO    (OFF_QKV + 6u*512u*512u)
#define OFF_OUTW  (OFF_WO + 2u*512u*512u)
#define OFF_EMBW1 (OFF_OUTW + 512u*4096u)
#define OFF_F0W1  (OFF_EMBW1 + 96u*1024u)
#define MAT_SZ    (512u*512u)

// ---------------- helpers ----------------
__device__ __forceinline__ uint32_t s2u(const void* p) {
    uint32_t a;
    asm("{ .reg .u64 t; cvta.to.shared.u64 t, %1; cvt.u32.u64 %0, t; }" : "=r"(a) : "l"(p));
    return a;
}
__device__ __forceinline__ void ldsm4(uint32_t* r, uint32_t addr) {
    asm volatile("ldmatrix.sync.aligned.m8n8.x4.shared.b16 {%0,%1,%2,%3}, [%4];"
        : "=r"(r[0]), "=r"(r[1]), "=r"(r[2]), "=r"(r[3]) : "r"(addr));
}
__device__ __forceinline__ void ldsm2(uint32_t* r, uint32_t addr) {
    asm volatile("ldmatrix.sync.aligned.m8n8.x2.shared.b16 {%0,%1}, [%2];"
        : "=r"(r[0]), "=r"(r[1]) : "r"(addr));
}
__device__ __forceinline__ void ldsm2t(uint32_t* r, uint32_t addr) {
    asm volatile("ldmatrix.sync.aligned.m8n8.x2.trans.shared.b16 {%0,%1}, [%2];"
        : "=r"(r[0]), "=r"(r[1]) : "r"(addr));
}
__device__ __forceinline__ void mma_bf16(float* c, const uint32_t* a, const uint32_t* b) {
    asm volatile("mma.sync.aligned.m16n8k16.row.col.f32.bf16.bf16.f32 "
        "{%0,%1,%2,%3}, {%4,%5,%6,%7}, {%8,%9}, {%0,%1,%2,%3};"
        : "+f"(c[0]), "+f"(c[1]), "+f"(c[2]), "+f"(c[3])
        : "r"(a[0]), "r"(a[1]), "r"(a[2]), "r"(a[3]), "r"(b[0]), "r"(b[1]));
}
__device__ __forceinline__ uint32_t packbf(float a, float b) {
    __nv_bfloat162 h = __floats2bfloat162_rn(a, b);
    return *(uint32_t*)&h;
}
__device__ __forceinline__ float bfres(float x) {
    return x - __bfloat162float(__float2bfloat16(x));
}
#define CPA(dst, src, sz) asm volatile("cp.async.ca.shared.global [%0], [%1], 16, %2;" \
    :: "r"(dst), "l"(src), "r"(sz))
#define CPC() asm volatile("cp.async.commit_group;" ::: "memory")
#define CPW0() asm volatile("cp.async.wait_group 0;" ::: "memory")
#define CPW1() asm volatile("cp.async.wait_group 1;" ::: "memory")

// ---------------- init ----------------
__global__ void init_kernel() {
    int t = threadIdx.x;
    if (t < NLAYER*NEXP) { g_cnt[t] = 0; g_imp[t] = 0.f; }
    for (int i = t; i < NTOK; i += blockDim.x) {
        int kv = (i >> 9) * SFULL + (i & 511);
        g_maps[i] = i;
        g_maps[NTOK + i] = NTOK + kv;
        g_maps[2 * NTOK + i] = NTOK + BSF + kv;
    }
}

// ---------------- streaming weight split ----------------
__global__ void wsplit(const float* __restrict__ W, __nv_bfloat16* __restrict__ hi,
                       __nv_bfloat16* __restrict__ lo, int n4)
{
    int i = blockIdx.x * 256 + threadIdx.x;
    if (i >= n4) return;
    float4 v = ((const float4*)W)[i];
    __nv_bfloat162 h01 = __floats2bfloat162_rn(v.x, v.y);
    __nv_bfloat162 h23 = __floats2bfloat162_rn(v.z, v.w);
    __nv_bfloat162 l01 = __floats2bfloat162_rn(v.x - __bfloat162float(h01.x),
                                               v.y - __bfloat162float(h01.y));
    __nv_bfloat162 l23 = __floats2bfloat162_rn(v.z - __bfloat162float(h23.x),
                                               v.w - __bfloat162float(h23.y));
    uint2 hw, lw;
    hw.x = *(uint32_t*)&h01; hw.y = *(uint32_t*)&h23;
    lw.x = *(uint32_t*)&l01; lw.y = *(uint32_t*)&l23;
    *(uint2*)(hi + (size_t)i * 4) = hw;
    *(uint2*)(lo + (size_t)i * 4) = lw;
}

// ---------------- weight split with K pad 80->96 ----------------
__global__ void wsplit_pad(const float* __restrict__ W, __nv_bfloat16* __restrict__ hi,
                           __nv_bfloat16* __restrict__ lo, int N, int total4)
{
    int i = blockIdx.x * 256 + threadIdx.x;
    if (i >= total4) return;
    int elem = i * 4;
    int z = elem / (KPAD * N);
    int rem = elem - z * KPAD * N;
    int k = rem / N, n = rem - k * N;
    float4 v = make_float4(0.f, 0.f, 0.f, 0.f);
    if (k < DIN) v = *(const float4*)(W + (size_t)z * DIN * N + (size_t)k * N + n);
    __nv_bfloat162 h01 = __floats2bfloat162_rn(v.x, v.y);
    __nv_bfloat162 h23 = __floats2bfloat162_rn(v.z, v.w);
    __nv_bfloat162 l01 = __floats2bfloat162_rn(v.x - __bfloat162float(h01.x),
                                               v.y - __bfloat162float(h01.y));
    __nv_bfloat162 l23 = __floats2bfloat162_rn(v.z - __bfloat162float(h23.x),
                                               v.w - __bfloat162float(h23.y));
    uint2 hw, lw;
    hw.x = *(uint32_t*)&h01; hw.y = *(uint32_t*)&h23;
    lw.x = *(uint32_t*)&l01; lw.y = *(uint32_t*)&l23;
    *(uint2*)(hi + (size_t)elem) = hw;
    *(uint2*)(lo + (size_t)elem) = lw;
}

// ---------------- x split with pad 80->96 ----------------
__global__ void xsplit(const float* __restrict__ x)
{
    int i = blockIdx.x * 256 + threadIdx.x;
    if (i >= NTOK * KPAD) return;
    int row = i / KPAD, c = i - row * KPAD;
    float v = (c < DIN) ? x[(size_t)row * DIN + c] : 0.f;
    __nv_bfloat16 h = __float2bfloat16(v);
    g_xhi[i] = h;
    g_xlo[i] = __float2bfloat16(v - __bfloat162float(h));
}

// ---------------- bf16 TC GEMM (3-stage cp.async pipeline) ----------------
#define KC 32
#define APITCHB 80
#define BPITCHB 272
#define A_TILE (128*APITCHB)
#define B_TILE (KC*BPITCHB)
#define STG (2*A_TILE + 2*B_TILE)
#define TG_SMEM (3*STG)
__global__ __launch_bounds__(256, 2)
void tgemm(const __nv_bfloat16* __restrict__ Ahi, const __nv_bfloat16* __restrict__ Alo,
           const __nv_bfloat16* __restrict__ Bhi, const __nv_bfloat16* __restrict__ Blo,
           float* __restrict__ C,
           __nv_bfloat16* __restrict__ Chi, __nv_bfloat16* __restrict__ Clo,
           int N, int K, int Mstatic,
           const float* __restrict__ bias, int doRelu,
           const int* __restrict__ gatherA, const int* __restrict__ scatterC,
           const float* __restrict__ rowScale, const float* __restrict__ residual,
           const int* __restrict__ Mdev, int strideB, int strideBias, int strideList)
{
    extern __shared__ char smem[];
    int e = blockIdx.z;
    const __nv_bfloat16* Bhz = Bhi + (size_t)e * strideB;
    const __nv_bfloat16* Blz = Blo + (size_t)e * strideB;
    const float* biasz = bias ? bias + (size_t)e * strideBias : (const float*)0;
    const int* gA = gatherA ? gatherA + (size_t)e * strideList : (const int*)0;
    const int* sC = scatterC ? scatterC + (size_t)e * strideList : (const int*)0;
    int Ml = Mdev ? Mdev[e] : Mstatic;
    int row0 = blockIdx.y * 128;
    if (row0 >= Ml) return;
    int col0 = blockIdx.x * 128;
    int tid = threadIdx.x, wid = tid >> 5, lane = tid & 31;
    uint32_t sb = s2u(smem);

    int arow[2], lr[2], lu[2];
    #pragma unroll
    for (int i = 0; i < 2; i++) {
        int unit = tid + i * 256;
        lr[i] = unit >> 2;
        lu[i] = unit & 3;
        int gr = row0 + lr[i];
        arow[i] = (gr < Ml) ? (gA ? gA[gr] : gr) : -1;
    }

    auto issue = [&](int c, int stage) {
        int k0 = c * KC;
        uint32_t base = sb + stage * STG;
        #pragma unroll
        for (int i = 0; i < 2; i++) {
            uint32_t offA = (uint32_t)(lr[i] * APITCHB + lu[i] * 16);
            int ar = arow[i] >= 0 ? arow[i] : 0;
            uint32_t asz = arow[i] >= 0 ? 16u : 0u;
            CPA(base + offA, (const char*)(Ahi + (size_t)ar * K + k0 + lu[i] * 8), asz);
            CPA(base + A_TILE + offA, (const char*)(Alo + (size_t)ar * K + k0 + lu[i] * 8), asz);
            int unit = tid + i * 256;
            int bk = unit >> 4, bc16 = unit & 15;
            uint32_t offB = (uint32_t)(bk * BPITCHB + bc16 * 16);
            const char* bh = (const char*)(Bhz + (size_t)(k0 + bk) * N + col0 + bc16 * 8);
            const char* bl = (const char*)(Blz + (size_t)(k0 + bk) * N + col0 + bc16 * 8);
            CPA(base + 2u * A_TILE + offB, bh, 16u);
            CPA(base + 2u * A_TILE + B_TILE + offB, bl, 16u);
        }
    };

    float acc[4][4][4] = {};
    int wm = wid >> 2, wn = wid & 3;
    int m_base = wm * 64, n_base = wn * 32;
    int l8 = lane & 7, mat = lane >> 3, bsel = (lane >> 3) & 1;

    int nc = K / KC;
    int stg = 0;   // stage of chunk c (c % 3)
    issue(0, 0); CPC();
    if (nc > 1) { issue(1, 1); CPC(); }

    for (int c = 0; c < nc; c++) {
        if (c + 1 < nc) CPW1(); else CPW0();
        __syncthreads();
        if (c + 2 < nc) {
            int ns = stg + 2; if (ns >= 3) ns -= 3;
            issue(c + 2, ns); CPC();
        }

        uint32_t base = sb + stg * STG;
        uint32_t ahB = base, alB = base + A_TILE;
        uint32_t bhB = base + 2u * A_TILE, blB = base + 2u * A_TILE + B_TILE;
        #pragma unroll
        for (int ks = 0; ks < 2; ks++) {
            int kb = ks * 16;
            uint32_t aoff = (uint32_t)(kb + (mat >> 1) * 8) * 2;
            uint32_t af[4][4], bfh[4][2], bfl[4][2];
            #pragma unroll
            for (int mf = 0; mf < 4; mf++)
                ldsm4(af[mf], ahB + (uint32_t)(m_base + mf * 16 + (mat & 1) * 8 + l8) * APITCHB + aoff);
            #pragma unroll
            for (int nf = 0; nf < 4; nf++)
                ldsm2t(bfh[nf], bhB + (uint32_t)(kb + bsel * 8 + l8) * BPITCHB
                                    + (uint32_t)(n_base + nf * 8) * 2);
            #pragma unroll
            for (int mf = 0; mf < 4; mf++)
                #pragma unroll
                for (int nf = 0; nf < 4; nf++)
                    mma_bf16(acc[mf][nf], af[mf], bfh[nf]);
            #pragma unroll
            for (int nf = 0; nf < 4; nf++)
                ldsm2t(bfl[nf], blB + (uint32_t)(kb + bsel * 8 + l8) * BPITCHB
                                    + (uint32_t)(n_base + nf * 8) * 2);
            #pragma unroll
            for (int mf = 0; mf < 4; mf++)
                #pragma unroll
                for (int nf = 0; nf < 4; nf++)
                    mma_bf16(acc[mf][nf], af[mf], bfl[nf]);
            #pragma unroll
            for (int mf = 0; mf < 4; mf++)
                ldsm4(af[mf], alB + (uint32_t)(m_base + mf * 16 + (mat & 1) * 8 + l8) * APITCHB + aoff);
            #pragma unroll
            for (int mf = 0; mf < 4; mf++)
                #pragma unroll
                for (int nf = 0; nf < 4; nf++)
                    mma_bf16(acc[mf][nf], af[mf], bfh[nf]);
        }
        stg++; if (stg >= 3) stg = 0;
    }

    int g = lane >> 2, t2 = (lane & 3) * 2;
    #pragma unroll
    for (int mf = 0; mf < 4; mf++) {
        #pragma unroll
        for (int half = 0; half < 2; half++) {
            int r = row0 + m_base + mf * 16 + g + half * 8;
            if (r >= Ml) continue;
            int orow = sC ? sC[r] : r;
            float sc = rowScale ? rowScale[orow] : 1.f;
            size_t rb = (size_t)orow * N;
            #pragma unroll
            for (int nf = 0; nf < 4; nf++) {
                int cc = col0 + n_base + nf * 8 + t2;
                float v0 = acc[mf][nf][half * 2 + 0] * sc;
                float v1 = acc[mf][nf][half * 2 + 1] * sc;
                if (biasz) { v0 += biasz[cc]; v1 += biasz[cc + 1]; }
                if (residual) { v0 += residual[rb + cc]; v1 += residual[rb + cc + 1]; }
                if (doRelu) { v0 = fmaxf(v0, 0.f); v1 = fmaxf(v1, 0.f); }
                if (C) *(float2*)(C + rb + cc) = make_float2(v0, v1);
                if (Chi) {
                    *(uint32_t*)(Chi + rb + cc) = packbf(v0, v1);
                    *(uint32_t*)(Clo + rb + cc) = packbf(bfres(v0), bfres(v1));
                }
            }
        }
    }
}

// ---------------- fused router (all layers) ----------------
__global__ void router_all(const float* __restrict__ embed, const float* __restrict__ f0r,
                           const float* __restrict__ fr, const int* __restrict__ seqlen,
                           float* __restrict__ gtokA, int* __restrict__ listsA,
                           int* __restrict__ cntA, float* __restrict__ impA)
{
    int l = blockIdx.y;
    const float* R = (l == 0) ? f0r : fr + (size_t)(l - 1) * DMODEL * NEXP;
    float* gtok = gtokA + (size_t)l * NTOK;
    int* lists = listsA + (size_t)l * NEXP * NTOK;
    int* cnt = cntA + l * NEXP;
    float* imp = impA + l * NEXP;

    int gw = (blockIdx.x * blockDim.x + threadIdx.x) >> 5;
    int lane = threadIdx.x & 31;
    if (gw >= NTOK) return;
    const float* xr = embed + (size_t)gw * DMODEL;
    float l0 = 0, l1 = 0, l2 = 0, l3 = 0;
    for (int d = lane; d < DMODEL; d += 32) {
        float v = xr[d];
        const float* rr = R + d * 4;
        l0 += v * rr[0]; l1 += v * rr[1]; l2 += v * rr[2]; l3 += v * rr[3];
    }
    for (int off = 16; off; off >>= 1) {
        l0 += __shfl_xor_sync(0xffffffffu, l0, off);
        l1 += __shfl_xor_sync(0xffffffffu, l1, off);
        l2 += __shfl_xor_sync(0xffffffffu, l2, off);
        l3 += __shfl_xor_sync(0xffffffffu, l3, off);
    }
    if (lane == 0) {
        float mx = fmaxf(fmaxf(l0, l1), fmaxf(l2, l3));
        float e0 = __expf(l0 - mx), e1 = __expf(l1 - mx);
        float e2 = __expf(l2 - mx), e3 = __expf(l3 - mx);
        float inv = 1.f / (e0 + e1 + e2 + e3);
        float s0 = e0 * inv, s1 = e1 * inv, s2 = e2 * inv, s3 = e3 * inv;
        int em = 0; float gm = s0;
        if (s1 > gm) { gm = s1; em = 1; }
        if (s2 > gm) { gm = s2; em = 2; }
        if (s3 > gm) { gm = s3; em = 3; }
        int b = gw >> 9, t = gw & 511;
        if (t < seqlen[b]) {
            atomicAdd(&imp[0], s0); atomicAdd(&imp[1], s1);
            atomicAdd(&imp[2], s2); atomicAdd(&imp[3], s3);
        }
        gtok[gw] = gm;
        int slot = atomicAdd(&cnt[em], 1);
        lists[em * NTOK + slot] = gw;
    }
}

// ---------------- FSMN (+optional PE, emits split(cur)) ----------------
__global__ void fsmn_kernel(const float* __restrict__ P, const float* __restrict__ fb,
                            const float* __restrict__ fa, const float* __restrict__ skipin,
                            float* __restrict__ outp, int doPE)
{
    int idx = blockIdx.x * 256 + threadIdx.x;
    if (idx >= NTOK * DMODEL) return;
    int d = idx & 511;
    int t = (idx >> 9) & 511;
    float v = P[idx];
    #pragma unroll
    for (int k = 0; k < 4; k++) {
        int off = (k + 1) * 2;
        if (t - off >= 0) v += fb[k * DMODEL + d] * P[idx - off * DMODEL];
    }
    if (t + 1 < TLEN) v += fa[d] * P[idx + DMODEL];
    if (skipin) v += skipin[idx];
    if (doPE) {
        int i = d >> 1;
        float div = __expf(-(float)(2 * i) * (9.2103403719761836f / 512.f));
        float a = (float)t * div;
        v += (d & 1) ? cosf(a) : sinf(a);
    }
    outp[idx] = v;
    __nv_bfloat16 h = __float2bfloat16(v);
    g_ahi[idx] = h;
    g_alo[idx] = __float2bfloat16(v - __bfloat162float(h));
}

// ---------------- memory KV rows ----------------
__global__ void memrows_kernel(const float* __restrict__ mk, const float* __restrict__ mv)
{
    int idx = blockIdx.x * 256 + threadIdx.x;
    if (idx >= BATCH * MMEM * DMODEL) return;
    int d = idx & 511;
    int r = idx >> 9;
    int m = r & 63;
    int b = r >> 6;
    size_t krow = (size_t)(NTOK + b * SFULL + TLEN + m);
    size_t vrow = krow + BSF;
    float kv = mk[m * DMODEL + d];
    float vv = mv[m * DMODEL + d];
    __nv_bfloat16 hk = __float2bfloat16(kv);
    g_qkvh[krow * DMODEL + d] = hk;
    g_qkvl[krow * DMODEL + d] = __float2bfloat16(kv - __bfloat162float(hk));
    __nv_bfloat16 hv = __float2bfloat16(vv);
    g_qkvh[vrow * DMODEL + d] = hv;
    g_qkvl[vrow * DMODEL + d] = __float2bfloat16(vv - __bfloat162float(hv));
}

// ---------------- tensor-core flash attention (skips fully-masked tiles) ----------------
#define AT_PITCH 72
#define AT_QH 0
#define AT_QL (128*AT_PITCH)
#define AT_KH (2*128*AT_PITCH)
#define AT_KL (AT_KH + 64*AT_PITCH)
#define AT_VH (AT_KL + 64*AT_PITCH)
#define AT_VL (AT_VH + 64*AT_PITCH)
#define ATTN_SMEM ((AT_VL + 64*AT_PITCH) * 2)
__global__ __launch_bounds__(256, 1)
void attn_mma(const __nv_bfloat16* __restrict__ qh, const __nv_bfloat16* __restrict__ ql,
              const __nv_bfloat16* __restrict__ kh, const __nv_bfloat16* __restrict__ kl,
              const __nv_bfloat16* __restrict__ vh, const __nv_bfloat16* __restrict__ vl,
              const int* __restrict__ seqlen,
              __nv_bfloat16* __restrict__ Ohi, __nv_bfloat16* __restrict__ Olo)
{
    extern __shared__ __nv_bfloat16 sb[];
    int q0 = blockIdx.x * 128, h = blockIdx.y, b = blockIdx.z;
    int tid = threadIdx.x, wid = tid >> 5, lane = tid & 31;
    int slen = seqlen[b];
    int l8 = lane & 7, mat = lane >> 3, g = lane >> 2, t2 = (lane & 3) * 2;
    int mrow = wid * 16;

    #pragma unroll
    for (int i = 0; i < 4; i++) {
        int u = i * 256 + tid;
        int r = u >> 3, c8 = u & 7;
        size_t src = ((size_t)(b * TLEN + q0 + r)) * DMODEL + h * DH + c8 * 8;
        *(uint4*)&sb[AT_QH + r * AT_PITCH + c8 * 8] = *(const uint4*)(qh + src);
        *(uint4*)&sb[AT_QL + r * AT_PITCH + c8 * 8] = *(const uint4*)(ql + src);
    }

    uint32_t QhB = s2u(sb + AT_QH), QlB = s2u(sb + AT_QL);
    uint32_t KhB = s2u(sb + AT_KH), KlB = s2u(sb + AT_KL);
    uint32_t VhB = s2u(sb + AT_VH), VlB = s2u(sb + AT_VL);

    float o[8][4] = {};
    float m0 = -1e30f, m1 = -1e30f, l0 = 0.f, l1 = 0.f;

    for (int s0 = 0; s0 < SFULL; s0 += 64) {
        if (s0 >= slen && s0 + 64 <= TLEN) continue;
        __syncthreads();
        #pragma unroll
        for (int i = 0; i < 2; i++) {
            int u = i * 256 + tid;
            int r = u >> 3, c8 = u & 7;
            size_t src = ((size_t)(b * SFULL + s0 + r)) * DMODEL + h * DH + c8 * 8;
            uint32_t dst = r * AT_PITCH + c8 * 8;
            *(uint4*)&sb[AT_KH + dst] = *(const uint4*)(kh + src);
            *(uint4*)&sb[AT_KL + dst] = *(const uint4*)(kl + src);
            *(uint4*)&sb[AT_VH + dst] = *(const uint4*)(vh + src);
            *(uint4*)&sb[AT_VL + dst] = *(const uint4*)(vl + src);
        }
        __syncthreads();

        float sc[8][4] = {};
        #pragma unroll
        for (int pass = 0; pass < 3; pass++) {
            uint32_t aB = (pass == 2) ? QlB : QhB;
            uint32_t bB = (pass == 1) ? KlB : KhB;
            #pragma unroll
            for (int kc = 0; kc < 4; kc++) {
                uint32_t af[4];
                ldsm4(af, aB + (uint32_t)((mrow + (mat & 1) * 8 + l8) * AT_PITCH
                                          + kc * 16 + (mat >> 1) * 8) * 2);
                #pragma unroll
                for (int nf = 0; nf < 8; nf++) {
                    uint32_t bf2[2];
                    ldsm2(bf2, bB + (uint32_t)((nf * 8 + l8) * AT_PITCH
                                               + kc * 16 + ((lane >> 3) & 1) * 8) * 2);
                    mma_bf16(sc[nf], af, bf2);
                }
            }
        }

        float rm0 = -1e30f, rm1 = -1e30f;
        #pragma unroll
        for (int nf = 0; nf < 8; nf++) {
            #pragma unroll
            for (int j = 0; j < 4; j++) {
                int sg = s0 + nf * 8 + t2 + (j & 1);
                float v = sc[nf][j] * 0.125f;
                sc[nf][j] = (sg >= slen && sg < TLEN) ? -1e9f : v;
            }
            rm0 = fmaxf(rm0, fmaxf(sc[nf][0], sc[nf][1]));
            rm1 = fmaxf(rm1, fmaxf(sc[nf][2], sc[nf][3]));
        }
        rm0 = fmaxf(rm0, __shfl_xor_sync(0xffffffffu, rm0, 1));
        rm0 = fmaxf(rm0, __shfl_xor_sync(0xffffffffu, rm0, 2));
        rm1 = fmaxf(rm1, __shfl_xor_sync(0xffffffffu, rm1, 1));
        rm1 = fmaxf(rm1, __shfl_xor_sync(0xffffffffu, rm1, 2));
        float mn0 = fmaxf(m0, rm0), mn1 = fmaxf(m1, rm1);
        float e0 = __expf(m0 - mn0), e1 = __expf(m1 - mn1);
        float rs0 = 0.f, rs1 = 0.f;
        #pragma unroll
        for (int nf = 0; nf < 8; nf++) {
            sc[nf][0] = __expf(sc[nf][0] - mn0); rs0 += sc[nf][0];
            sc[nf][1] = __expf(sc[nf][1] - mn0); rs0 += sc[nf][1];
            sc[nf][2] = __expf(sc[nf][2] - mn1); rs1 += sc[nf][2];
            sc[nf][3] = __expf(sc[nf][3] - mn1); rs1 += sc[nf][3];
        }
        rs0 += __shfl_xor_sync(0xffffffffu, rs0, 1);
        rs0 += __shfl_xor_sync(0xffffffffu, rs0, 2);
        rs1 += __shfl_xor_sync(0xffffffffu, rs1, 1);
        rs1 += __shfl_xor_sync(0xffffffffu, rs1, 2);
        l0 = l0 * e0 + rs0; l1 = l1 * e1 + rs1;
        m0 = mn0; m1 = mn1;
        #pragma unroll
        for (int nf = 0; nf < 8; nf++) {
            o[nf][0] *= e0; o[nf][1] *= e0; o[nf][2] *= e1; o[nf][3] *= e1;
        }

        uint32_t phi[4][4], plo[4][4];
        #pragma unroll
        for (int kc = 0; kc < 4; kc++) {
            float* A = sc[2 * kc];
            float* B = sc[2 * kc + 1];
            phi[kc][0] = packbf(A[0], A[1]); phi[kc][1] = packbf(A[2], A[3]);
            phi[kc][2] = packbf(B[0], B[1]); phi[kc][3] = packbf(B[2], B[3]);
            plo[kc][0] = packbf(bfres(A[0]), bfres(A[1]));
            plo[kc][1] = packbf(bfres(A[2]), bfres(A[3]));
            plo[kc][2] = packbf(bfres(B[0]), bfres(B[1]));
            plo[kc][3] = packbf(bfres(B[2]), bfres(B[3]));
        }

        #pragma unroll
        for (int pass = 0; pass < 3; pass++) {
            uint32_t vB = (pass == 1) ? VlB : VhB;
            #pragma unroll
            for (int kc = 0; kc < 4; kc++) {
                const uint32_t* pf = (pass == 2) ? plo[kc] : phi[kc];
                #pragma unroll
                for (int nf = 0; nf < 8; nf++) {
                    uint32_t bf2[2];
                    ldsm2t(bf2, vB + (uint32_t)((kc * 16 + ((lane >> 3) & 1) * 8 + l8) * AT_PITCH
                                                + nf * 8) * 2);
                    mma_bf16(o[nf], pf, bf2);
                }
            }
        }
    }

    float inv0 = 1.f / l0, inv1 = 1.f / l1;
    int r0 = q0 + mrow + g;
    #pragma unroll
    for (int nf = 0; nf < 8; nf++) {
        int cc = h * DH + nf * 8 + t2;
        size_t i0 = ((size_t)(b * TLEN + r0)) * DMODEL + cc;
        size_t i1 = ((size_t)(b * TLEN + r0 + 8)) * DMODEL + cc;
        float v0 = o[nf][0] * inv0, v1 = o[nf][1] * inv0;
        float w0 = o[nf][2] * inv1, w1 = o[nf][3] * inv1;
        *(uint32_t*)(Ohi + i0) = packbf(v0, v1);
        *(uint32_t*)(Olo + i0) = packbf(bfres(v0), bfres(v1));
        *(uint32_t*)(Ohi + i1) = packbf(w0, w1);
        *(uint32_t*)(Olo + i1) = packbf(bfres(w0), bfres(w1));
    }
}

// ---------------- layernorm (emits split(cur)) ----------------
__global__ void ln_kernel(const float* __restrict__ X, float* __restrict__ Y,
                          const float* __restrict__ gw, const float* __restrict__ bw)
{
    __shared__ float red[128];
    int row = blockIdx.x, tid = threadIdx.x;
    const float* xr = X + (size_t)row * DMODEL;
    float v[4]; float s = 0.f;
    #pragma unroll
    for (int i = 0; i < 4; i++) { v[i] = xr[tid + 128 * i]; s += v[i]; }
    red[tid] = s; __syncthreads();
    for (int off = 64; off > 0; off >>= 1) {
        if (tid < off) red[tid] += red[tid + off];
        __syncthreads();
    }
    float mu = red[0] * (1.f / 512.f);
    __syncthreads();
    float s2 = 0.f;
    #pragma unroll
    for (int i = 0; i < 4; i++) { float d = v[i] - mu; s2 += d * d; }
    red[tid] = s2; __syncthreads();
    for (int off = 64; off > 0; off >>= 1) {
        if (tid < off) red[tid] += red[tid + off];
        __syncthreads();
    }
    float inv = rsqrtf(red[0] * (1.f / 512.f) + 1e-5f);
    #pragma unroll
    for (int i = 0; i < 4; i++) {
        int c = tid + 128 * i;
        float y = (v[i] - mu) * inv * gw[c] + bw[c];
        size_t idx = (size_t)row * DMODEL + c;
        Y[idx] = y;
        __nv_bfloat16 h = __float2bfloat16(y);
        g_ahi[idx] = h;
        g_alo[idx] = __float2bfloat16(y - __bfloat162float(h));
    }
}

// ---------------- aux ----------------
__global__ void aux_kernel(float* __restrict__ dst)
{
    float tot = 0.f;
    for (int l = 0; l < NLAYER; l++) {
        float m = 0.f;
        for (int e = 0; e < NEXP; e++) m += g_imp[l * 4 + e];
        m *= 0.25f;
        float var = 0.f;
        for (int e = 0; e < NEXP; e++) { float d = g_imp[l * 4 + e] - m; var += d * d; }
        var *= 0.25f;
        tot += var / (m * m + 1e-9f);
    }
    dst[0] = tot;
}

// ---------------- launcher (R9 schedule) ----------------
extern "C" void kernel_launch(void* const* d_in, const int* in_sizes, int n_in,
                              void* d_out, int out_size)
{
    const float* x         = (const float*)d_in[0];
    const int*   seq       = (const int*)  d_in[1];
    const float* emb_w1    = (const float*)d_in[2];
    const float* emb_b1    = (const float*)d_in[3];
    const float* emb_w2    = (const float*)d_in[4];
    const float* emb_wo    = (const float*)d_in[5];
    const float* f0_w1     = (const float*)d_in[6];
    const float* f0_b1     = (const float*)d_in[7];
    const float* f0_w2     = (const float*)d_in[8];
    const float* f0_router = (const float*)d_in[9];
    const float* f0_fb     = (const float*)d_in[10];
    const float* f0_fa     = (const float*)d_in[11];
    const float* f_w1      = (const float*)d_in[12];
    const float* f_b1      = (const float*)d_in[13];
    const float* f_w2      = (const float*)d_in[14];
    const float* f_router  = (const float*)d_in[15];
    const float* f_fb      = (const float*)d_in[16];
    const float* f_fa      = (const float*)d_in[17];
    const float* wq        = (const float*)d_in[18];
    const float* wk        = (const float*)d_in[19];
    const float* wv        = (const float*)d_in[20];
    const float* wvo       = (const float*)d_in[21];
    const float* mk        = (const float*)d_in[22];
    const float* mv        = (const float*)d_in[23];
    const float* lng       = (const float*)d_in[24];
    const float* lnb       = (const float*)d_in[25];
    const float* out_w     = (const float*)d_in[26];
    const float* out_b     = (const float*)d_in[27];
    float* out = (float*)d_out;

    float *embed, *cur, *p, *tmp, *gtok, *imp;
    int *cnt, *lists, *maps;
    __nv_bfloat16 *whi, *wlo, *ahi, *alo, *bhi, *blo, *ehi, *elo, *xhi, *xlo, *qkvh, *qkvl;
    cudaGetSymbolAddress((void**)&embed, g_embed);
    cudaGetSymbolAddress((void**)&cur,   g_cur);
    cudaGetSymbolAddress((void**)&p,     g_p);
    cudaGetSymbolAddress((void**)&tmp,   g_tmp);
    cudaGetSymbolAddress((void**)&gtok,  g_gtok);
    cudaGetSymbolAddress((void**)&imp,   g_imp);
    cudaGetSymbolAddress((void**)&cnt,   g_cnt);
    cudaGetSymbolAddress((void**)&lists, g_lists);
    cudaGetSymbolAddress((void**)&maps,  g_maps);
    cudaGetSymbolAddress((void**)&whi,   g_whi);
    cudaGetSymbolAddress((void**)&wlo,   g_wlo);
    cudaGetSymbolAddress((void**)&ahi,   g_ahi);
    cudaGetSymbolAddress((void**)&alo,   g_alo);
    cudaGetSymbolAddress((void**)&bhi,   g_bhi);
    cudaGetSymbolAddress((void**)&blo,   g_blo);
    cudaGetSymbolAddress((void**)&ehi,   g_ehi);
    cudaGetSymbolAddress((void**)&elo,   g_elo);
    cudaGetSymbolAddress((void**)&xhi,   g_xhi);
    cudaGetSymbolAddress((void**)&xlo,   g_xlo);
    cudaGetSymbolAddress((void**)&qkvh,  g_qkvh);
    cudaGetSymbolAddress((void**)&qkvl,  g_qkvl);

    cudaFuncSetAttribute(attn_mma, cudaFuncAttributeMaxDynamicSharedMemorySize, ATTN_SMEM);
    cudaFuncSetAttribute(tgemm, cudaFuncAttributeMaxDynamicSharedMemorySize, TG_SMEM);

    cudaStream_t s1;
    cudaStreamCreate(&s1);
    cudaEvent_t evF, evJ, evE0, evE1;
    cudaEventCreateWithFlags(&evF, cudaEventDisableTiming);
    cudaEventCreateWithFlags(&evJ, cudaEventDisableTiming);
    cudaEventCreateWithFlags(&evE0, cudaEventDisableTiming);
    cudaEventCreateWithFlags(&evE1, cudaEventDisableTiming);

    auto TG = [&](unsigned woff, const __nv_bfloat16* Ah, const __nv_bfloat16* Al,
                  float* C, __nv_bfloat16* Ch, __nv_bfloat16* Cl,
                  int M, int N, int K,
                  const float* bias, int relu, const int* ga, const int* sc,
                  const float* rs, const float* res, const int* Md,
                  int E = 1, int sB = 0, int sBias = 0, int sList = 0,
                  cudaStream_t st = 0) {
        dim3 grid(N / 128, (M + 127) / 128, E);
        tgemm<<<grid, 256, TG_SMEM, st>>>(Ah, Al, whi + woff, wlo + woff, C, Ch, Cl,
                                          N, K, M, bias, relu, ga, sc, rs, res, Md,
                                          sB, sBias, sList);
    };
    auto WS = [&](const float* W, unsigned off, int nelem, cudaStream_t st) {
        wsplit<<<(nelem / 4 + 255) / 256, 256, 0, st>>>(W, whi + off, wlo + off, nelem / 4);
    };

    init_kernel<<<1, 1024>>>();

    // main-stream prep
    xsplit<<<(NTOK * KPAD + 255) / 256, 256>>>(x);
    wsplit_pad<<<(KPAD * 1024 / 4 + 255) / 256, 256>>>(emb_w1, whi + OFF_EMBW1,
                                                       wlo + OFF_EMBW1, 1024, KPAD * 1024 / 4);
    wsplit_pad<<<(NEXP * KPAD * 1024 / 4 + 255) / 256, 256>>>(f0_w1, whi + OFF_F0W1,
                                                              wlo + OFF_F0W1, 1024,
                                                              NEXP * KPAD * 1024 / 4);
    WS(emb_w2, OFF_EMBW2, 1024 * 512, 0);
    WS(f0_w2,  OFF_F0W2, 4 * 1024 * 512, 0);

    // side-stream weight splits
    cudaEventRecord(evF, 0);
    cudaStreamWaitEvent(s1, evF, 0);
    WS(emb_wo, OFF_EMBWO, 512 * 4096, s1);
    WS(f_w1, OFF_FW1, 28 * 512 * 1024, s1);
    WS(f_w2, OFF_FW2, 28 * 1024 * 512, s1);
    for (int bi = 0; bi < 2; bi++) {
        WS(wq + (size_t)bi * MAT_SZ, OFF_QKV + bi * 3u * MAT_SZ + 0u * MAT_SZ, MAT_SZ, s1);
        WS(wk + (size_t)bi * MAT_SZ, OFF_QKV + bi * 3u * MAT_SZ + 1u * MAT_SZ, MAT_SZ, s1);
        WS(wv + (size_t)bi * MAT_SZ, OFF_QKV + bi * 3u * MAT_SZ + 2u * MAT_SZ, MAT_SZ, s1);
    }
    WS(wvo,   OFF_WO, 2 * 512 * 512, s1);
    WS(out_w, OFF_OUTW, 512 * 4096, s1);
    cudaEventRecord(evJ, s1);

    // embed sub-network
    TG(OFF_EMBW1, xhi, xlo, 0, bhi, blo, NTOK, DHID, KPAD, emb_b1, 1, 0, 0, 0, 0, 0);
    TG(OFF_EMBW2, bhi, blo, embed, ehi, elo, NTOK, DMODEL, DHID, 0, 0, 0, 0, 0, 0, 0);
    cudaEventRecord(evE0, 0);

    // embed_out on side stream
    cudaStreamWaitEvent(s1, evE0, 0);
    TG(OFF_EMBWO, ehi, elo, out + (size_t)NTOK * DOUT, 0, 0, NTOK, DOUT, DMODEL,
       0, 0, 0, 0, 0, 0, 0, 1, 0, 0, 0, s1);
    cudaEventRecord(evE1, s1);

    router_all<<<dim3(NTOK / 8, NLAYER), 256>>>(embed, f0_router, f_router, seq,
                                                gtok, lists, cnt, imp);

    for (int l = 0; l < NLAYER; l++) {
        int* lst = lists + (size_t)l * NEXP * NTOK;
        float* gt = gtok + (size_t)l * NTOK;
        int* ct = cnt + l * 4;

        if (l == 1) cudaStreamWaitEvent(0, evJ, 0);

        if (l == 0) {
            TG(OFF_F0W1, xhi, xlo, 0, bhi, blo, NTOK, DHID, KPAD,
               f0_b1, 1, lst, lst, 0, 0, ct, NEXP, KPAD * DHID, DHID, NTOK);
            TG(OFF_F0W2, bhi, blo, p, 0, 0, NTOK, DMODEL, DHID, 0, 0, lst, lst,
               gt, 0, ct, NEXP, DMODEL * DHID, 0, NTOK);
        } else {
            TG(OFF_FW1 + (unsigned)(l - 1) * 4u * DMODEL * DHID, ahi, alo,
               0, bhi, blo, NTOK, DHID, DMODEL,
               f_b1 + (size_t)(l - 1) * NEXP * DHID, 1, lst, lst, 0, 0, ct,
               NEXP, DMODEL * DHID, DHID, NTOK);
            TG(OFF_FW2 + (unsigned)(l - 1) * 4u * DHID * DMODEL, bhi, blo,
               p, 0, 0, NTOK, DMODEL, DHID,
               0, 0, lst, lst, gt, 0, ct,
               NEXP, DHID * DMODEL, 0, NTOK);
        }
        const float* fbL = (l == 0) ? f0_fb : f_fb + (size_t)(l - 1) * 4 * DMODEL;
        const float* faL = (l == 0) ? f0_fa : f_fa + (size_t)(l - 1) * DMODEL;
        fsmn_kernel<<<NTOK * DMODEL / 256, 256>>>(p, fbL, faL,
                                                  (l == 0) ? (const float*)0 : cur, cur,
                                                  l == 3 ? 1 : 0);

        if (l == 3 || l == 7) {
            int bi = l / 4;
            TG(OFF_QKV + (unsigned)bi * 3u * MAT_SZ, ahi, alo, 0, qkvh, qkvl,
               NTOK, DMODEL, DMODEL, 0, 0, 0, maps, 0, 0, 0, 3, MAT_SZ, 0, NTOK);
            memrows_kernel<<<BATCH * MMEM * DMODEL / 256, 256>>>(
                mk + (size_t)bi * MMEM * DMODEL, mv + (size_t)bi * MMEM * DMODEL);
            attn_mma<<<dim3(TLEN / 128, NHEAD, BATCH), 256, ATTN_SMEM>>>(
                qkvh, qkvl,
                qkvh + (size_t)NTOK * DMODEL, qkvl + (size_t)NTOK * DMODEL,
                qkvh + (size_t)(NTOK + BSF) * DMODEL, qkvl + (size_t)(NTOK + BSF) * DMODEL,
                seq, bhi, blo);
            TG(OFF_WO + (unsigned)bi * MAT_SZ, bhi, blo, tmp, 0, 0,
               NTOK, DMODEL, DMODEL, 0, 0, 0, 0, 0, cur, 0);
            ln_kernel<<<NTOK, 128>>>(tmp, cur, lng + bi * DMODEL, lnb + bi * DMODEL);
        }
    }

    TG(OFF_OUTW, ahi, alo, out, 0, 0, NTOK, DOUT, DMODEL, out_b, 0, 0, 0, 0, 0, 0);
    cudaStreamWaitEvent(0, evE1, 0);
    aux_kernel<<<1, 1>>>(out + 2 * (size_t)NTOK * DOUT);
}

// round 13
// speedup vs baseline: 1.1442x; 1.1442x over previous
#include <cuda_runtime.h>
#include <cuda_bf16.h>
#include <math.h>
#include <stdint.h>

// ---------------- problem constants ----------------
#define BATCH 4
#define TLEN  512
#define NTOK  (BATCH*TLEN)
#define DIN   80
#define KPAD  96
#define DOUT  4096
#define DMODEL 512
#define DHID  1024
#define NEXP  4
#define NLAYER 8
#define NHEAD 8
#define DH    64
#define MMEM  64
#define SFULL (TLEN+MMEM)
#define BSF   (BATCH*SFULL)
#define QKV_ROWS (NTOK + 2*BSF)

// ---------------- device scratch ----------------
__device__ float g_embed[NTOK*DMODEL];
__device__ float g_cur[NTOK*DMODEL];
__device__ float g_p[NTOK*DMODEL];
__device__ float g_tmp[NTOK*DMODEL];
__device__ float g_gtok[NLAYER*NTOK];
__device__ float g_imp[NLAYER*NEXP];
__device__ int   g_cnt[NLAYER*NEXP];
__device__ int   g_lists[NLAYER*NEXP*NTOK];
__device__ int   g_maps[3*NTOK];

#define WPOOL (40u*1024u*1024u)
__device__ __nv_bfloat16 g_whi[WPOOL];
__device__ __nv_bfloat16 g_wlo[WPOOL];
__device__ __nv_bfloat16 g_ahi[NTOK*DMODEL];
__device__ __nv_bfloat16 g_alo[NTOK*DMODEL];
__device__ __nv_bfloat16 g_bhi[NTOK*DHID];
__device__ __nv_bfloat16 g_blo[NTOK*DHID];
__device__ __nv_bfloat16 g_ehi[NTOK*DMODEL];
__device__ __nv_bfloat16 g_elo[NTOK*DMODEL];
__device__ __nv_bfloat16 g_xhi[NTOK*KPAD];
__device__ __nv_bfloat16 g_xlo[NTOK*KPAD];
__device__ __nv_bfloat16 g_qkvh[QKV_ROWS*DMODEL];
__device__ __nv_bfloat16 g_qkvl[QKV_ROWS*DMODEL];

#define OFF_EMBW2 0u
#define OFF_EMBWO (OFF_EMBW2 + 512u*1024u)
#define OFF_F0W2  (OFF_EMBWO + 4096u*512u)
#define OFF_FW1   (OFF_F0W2 + 4u*512u*1024u)
#define OFF_FW2   (OFF_FW1 + 28u*1024u*512u)
#define OFF_QKV   (OFF_FW2 + 28u*512u*1024u)
#define OFF_WO    (OFF_QKV + 6u*512u*512u)
#define OFF_OUTW  (OFF_WO + 2u*512u*512u)
#define OFF_EMBW1 (OFF_OUTW + 512u*4096u)
#define OFF_F0W1  (OFF_EMBW1 + 96u*1024u)
#define MAT_SZ    (512u*512u)

// ---------------- helpers ----------------
__device__ __forceinline__ uint32_t s2u(const void* p) {
    uint32_t a;
    asm("{ .reg .u64 t; cvta.to.shared.u64 t, %1; cvt.u32.u64 %0, t; }" : "=r"(a) : "l"(p));
    return a;
}
__device__ __forceinline__ void ldsm4(uint32_t* r, uint32_t addr) {
    asm volatile("ldmatrix.sync.aligned.m8n8.x4.shared.b16 {%0,%1,%2,%3}, [%4];"
        : "=r"(r[0]), "=r"(r[1]), "=r"(r[2]), "=r"(r[3]) : "r"(addr));
}
__device__ __forceinline__ void ldsm2(uint32_t* r, uint32_t addr) {
    asm volatile("ldmatrix.sync.aligned.m8n8.x2.shared.b16 {%0,%1}, [%2];"
        : "=r"(r[0]), "=r"(r[1]) : "r"(addr));
}
__device__ __forceinline__ void ldsm2t(uint32_t* r, uint32_t addr) {
    asm volatile("ldmatrix.sync.aligned.m8n8.x2.trans.shared.b16 {%0,%1}, [%2];"
        : "=r"(r[0]), "=r"(r[1]) : "r"(addr));
}
__device__ __forceinline__ void mma_bf16(float* c, const uint32_t* a, const uint32_t* b) {
    asm volatile("mma.sync.aligned.m16n8k16.row.col.f32.bf16.bf16.f32 "
        "{%0,%1,%2,%3}, {%4,%5,%6,%7}, {%8,%9}, {%0,%1,%2,%3};"
        : "+f"(c[0]), "+f"(c[1]), "+f"(c[2]), "+f"(c[3])
        : "r"(a[0]), "r"(a[1]), "r"(a[2]), "r"(a[3]), "r"(b[0]), "r"(b[1]));
}
__device__ __forceinline__ uint32_t packbf(float a, float b) {
    __nv_bfloat162 h = __floats2bfloat162_rn(a, b);
    return *(uint32_t*)&h;
}
__device__ __forceinline__ float bfres(float x) {
    return x - __bfloat162float(__float2bfloat16(x));
}
#define CPA(dst, src, sz) asm volatile("cp.async.ca.shared.global [%0], [%1], 16, %2;" \
    :: "r"(dst), "l"(src), "r"(sz))
#define CPC() asm volatile("cp.async.commit_group;" ::: "memory")
#define CPW() asm volatile("cp.async.wait_group 0;" ::: "memory")

// ---------------- init ----------------
__global__ void init_kernel() {
    int t = threadIdx.x;
    if (t < NLAYER*NEXP) { g_cnt[t] = 0; g_imp[t] = 0.f; }
    for (int i = t; i < NTOK; i += blockDim.x) {
        int kv = (i >> 9) * SFULL + (i & 511);
        g_maps[i] = i;
        g_maps[NTOK + i] = NTOK + kv;
        g_maps[2 * NTOK + i] = NTOK + BSF + kv;
    }
}

// ---------------- streaming weight split ----------------
__global__ void wsplit(const float* __restrict__ W, __nv_bfloat16* __restrict__ hi,
                       __nv_bfloat16* __restrict__ lo, int n4)
{
    int i = blockIdx.x * 256 + threadIdx.x;
    if (i >= n4) return;
    float4 v = ((const float4*)W)[i];
    __nv_bfloat162 h01 = __floats2bfloat162_rn(v.x, v.y);
    __nv_bfloat162 h23 = __floats2bfloat162_rn(v.z, v.w);
    __nv_bfloat162 l01 = __floats2bfloat162_rn(v.x - __bfloat162float(h01.x),
                                               v.y - __bfloat162float(h01.y));
    __nv_bfloat162 l23 = __floats2bfloat162_rn(v.z - __bfloat162float(h23.x),
                                               v.w - __bfloat162float(h23.y));
    uint2 hw, lw;
    hw.x = *(uint32_t*)&h01; hw.y = *(uint32_t*)&h23;
    lw.x = *(uint32_t*)&l01; lw.y = *(uint32_t*)&l23;
    *(uint2*)(hi + (size_t)i * 4) = hw;
    *(uint2*)(lo + (size_t)i * 4) = lw;
}

// ---------------- weight split with K pad 80->96 ----------------
__global__ void wsplit_pad(const float* __restrict__ W, __nv_bfloat16* __restrict__ hi,
                           __nv_bfloat16* __restrict__ lo, int N, int total4)
{
    int i = blockIdx.x * 256 + threadIdx.x;
    if (i >= total4) return;
    int elem = i * 4;
    int z = elem / (KPAD * N);
    int rem = elem - z * KPAD * N;
    int k = rem / N, n = rem - k * N;
    float4 v = make_float4(0.f, 0.f, 0.f, 0.f);
    if (k < DIN) v = *(const float4*)(W + (size_t)z * DIN * N + (size_t)k * N + n);
    __nv_bfloat162 h01 = __floats2bfloat162_rn(v.x, v.y);
    __nv_bfloat162 h23 = __floats2bfloat162_rn(v.z, v.w);
    __nv_bfloat162 l01 = __floats2bfloat162_rn(v.x - __bfloat162float(h01.x),
                                               v.y - __bfloat162float(h01.y));
    __nv_bfloat162 l23 = __floats2bfloat162_rn(v.z - __bfloat162float(h23.x),
                                               v.w - __bfloat162float(h23.y));
    uint2 hw, lw;
    hw.x = *(uint32_t*)&h01; hw.y = *(uint32_t*)&h23;
    lw.x = *(uint32_t*)&l01; lw.y = *(uint32_t*)&l23;
    *(uint2*)(hi + (size_t)elem) = hw;
    *(uint2*)(lo + (size_t)elem) = lw;
}

// ---------------- x split with pad 80->96 ----------------
__global__ void xsplit(const float* __restrict__ x)
{
    int i = blockIdx.x * 256 + threadIdx.x;
    if (i >= NTOK * KPAD) return;
    int row = i / KPAD, c = i - row * KPAD;
    float v = (c < DIN) ? x[(size_t)row * DIN + c] : 0.f;
    __nv_bfloat16 h = __float2bfloat16(v);
    g_xhi[i] = h;
    g_xlo[i] = __float2bfloat16(v - __bfloat162float(h));
}

// ---------------- bf16 TC GEMM (2-stage cp.async pipeline) ----------------
#define KC 32
#define APITCHB 80
#define BPITCHB 272
#define A_TILE (128*APITCHB)
#define B_TILE (KC*BPITCHB)
#define STG (2*A_TILE + 2*B_TILE)
#define TG_SMEM (2*STG)
__global__ __launch_bounds__(256, 2)
void tgemm(const __nv_bfloat16* __restrict__ Ahi, const __nv_bfloat16* __restrict__ Alo,
           const __nv_bfloat16* __restrict__ Bhi, const __nv_bfloat16* __restrict__ Blo,
           float* __restrict__ C,
           __nv_bfloat16* __restrict__ Chi, __nv_bfloat16* __restrict__ Clo,
           int N, int K, int Mstatic,
           const float* __restrict__ bias, int doRelu,
           const int* __restrict__ gatherA, const int* __restrict__ scatterC,
           const float* __restrict__ rowScale, const float* __restrict__ residual,
           const int* __restrict__ Mdev, int strideB, int strideBias, int strideList)
{
    extern __shared__ char smem[];
    int e = blockIdx.z;
    const __nv_bfloat16* Bhz = Bhi + (size_t)e * strideB;
    const __nv_bfloat16* Blz = Blo + (size_t)e * strideB;
    const float* biasz = bias ? bias + (size_t)e * strideBias : (const float*)0;
    const int* gA = gatherA ? gatherA + (size_t)e * strideList : (const int*)0;
    const int* sC = scatterC ? scatterC + (size_t)e * strideList : (const int*)0;
    int Ml = Mdev ? Mdev[e] : Mstatic;
    int row0 = blockIdx.y * 128;
    if (row0 >= Ml) return;
    int col0 = blockIdx.x * 128;
    int tid = threadIdx.x, wid = tid >> 5, lane = tid & 31;
    uint32_t sb = s2u(smem);

    int arow[2], lr[2], lu[2];
    #pragma unroll
    for (int i = 0; i < 2; i++) {
        int unit = tid + i * 256;
        lr[i] = unit >> 2;
        lu[i] = unit & 3;
        int gr = row0 + lr[i];
        arow[i] = (gr < Ml) ? (gA ? gA[gr] : gr) : -1;
    }

    auto issue = [&](int c, int stage) {
        int k0 = c * KC;
        uint32_t base = sb + stage * STG;
        #pragma unroll
        for (int i = 0; i < 2; i++) {
            uint32_t offA = (uint32_t)(lr[i] * APITCHB + lu[i] * 16);
            int ar = arow[i] >= 0 ? arow[i] : 0;
            uint32_t asz = arow[i] >= 0 ? 16u : 0u;
            CPA(base + offA, (const char*)(Ahi + (size_t)ar * K + k0 + lu[i] * 8), asz);
            CPA(base + A_TILE + offA, (const char*)(Alo + (size_t)ar * K + k0 + lu[i] * 8), asz);
            int unit = tid + i * 256;
            int bk = unit >> 4, bc16 = unit & 15;
            uint32_t offB = (uint32_t)(bk * BPITCHB + bc16 * 16);
            const char* bh = (const char*)(Bhz + (size_t)(k0 + bk) * N + col0 + bc16 * 8);
            const char* bl = (const char*)(Blz + (size_t)(k0 + bk) * N + col0 + bc16 * 8);
            CPA(base + 2u * A_TILE + offB, bh, 16u);
            CPA(base + 2u * A_TILE + B_TILE + offB, bl, 16u);
        }
    };

    float acc[4][4][4] = {};
    int wm = wid >> 2, wn = wid & 3;
    int m_base = wm * 64, n_base = wn * 32;
    int l8 = lane & 7, mat = lane >> 3, bsel = (lane >> 3) & 1;

    int nc = K / KC;
    issue(0, 0); CPC();

    for (int c = 0; c < nc; c++) {
        CPW();
        __syncthreads();
        if (c + 1 < nc) { issue(c + 1, (c + 1) & 1); CPC(); }

        uint32_t base = sb + (c & 1) * STG;
        uint32_t ahB = base, alB = base + A_TILE;
        uint32_t bhB = base + 2u * A_TILE, blB = base + 2u * A_TILE + B_TILE;
        #pragma unroll
        for (int ks = 0; ks < 2; ks++) {
            int kb = ks * 16;
            uint32_t aoff = (uint32_t)(kb + (mat >> 1) * 8) * 2;
            uint32_t af[4][4], bfh[4][2], bfl[4][2];
            #pragma unroll
            for (int mf = 0; mf < 4; mf++)
                ldsm4(af[mf], ahB + (uint32_t)(m_base + mf * 16 + (mat & 1) * 8 + l8) * APITCHB + aoff);
            #pragma unroll
            for (int nf = 0; nf < 4; nf++)
                ldsm2t(bfh[nf], bhB + (uint32_t)(kb + bsel * 8 + l8) * BPITCHB
                                    + (uint32_t)(n_base + nf * 8) * 2);
            #pragma unroll
            for (int mf = 0; mf < 4; mf++)
                #pragma unroll
                for (int nf = 0; nf < 4; nf++)
                    mma_bf16(acc[mf][nf], af[mf], bfh[nf]);
            #pragma unroll
            for (int nf = 0; nf < 4; nf++)
                ldsm2t(bfl[nf], blB + (uint32_t)(kb + bsel * 8 + l8) * BPITCHB
                                    + (uint32_t)(n_base + nf * 8) * 2);
            #pragma unroll
            for (int mf = 0; mf < 4; mf++)
                #pragma unroll
                for (int nf = 0; nf < 4; nf++)
                    mma_bf16(acc[mf][nf], af[mf], bfl[nf]);
            #pragma unroll
            for (int mf = 0; mf < 4; mf++)
                ldsm4(af[mf], alB + (uint32_t)(m_base + mf * 16 + (mat & 1) * 8 + l8) * APITCHB + aoff);
            #pragma unroll
            for (int mf = 0; mf < 4; mf++)
                #pragma unroll
                for (int nf = 0; nf < 4; nf++)
                    mma_bf16(acc[mf][nf], af[mf], bfh[nf]);
        }
    }

    int g = lane >> 2, t2 = (lane & 3) * 2;
    #pragma unroll
    for (int mf = 0; mf < 4; mf++) {
        #pragma unroll
        for (int half = 0; half < 2; half++) {
            int r = row0 + m_base + mf * 16 + g + half * 8;
            if (r >= Ml) continue;
            int orow = sC ? sC[r] : r;
            float sc = rowScale ? rowScale[orow] : 1.f;
            size_t rb = (size_t)orow * N;
            #pragma unroll
            for (int nf = 0; nf < 4; nf++) {
                int cc = col0 + n_base + nf * 8 + t2;
                float v0 = acc[mf][nf][half * 2 + 0] * sc;
                float v1 = acc[mf][nf][half * 2 + 1] * sc;
                if (biasz) { v0 += biasz[cc]; v1 += biasz[cc + 1]; }
                if (residual) { v0 += residual[rb + cc]; v1 += residual[rb + cc + 1]; }
                if (doRelu) { v0 = fmaxf(v0, 0.f); v1 = fmaxf(v1, 0.f); }
                if (C) *(float2*)(C + rb + cc) = make_float2(v0, v1);
                if (Chi) {
                    *(uint32_t*)(Chi + rb + cc) = packbf(v0, v1);
                    *(uint32_t*)(Clo + rb + cc) = packbf(bfres(v0), bfres(v1));
                }
            }
        }
    }
}

// ---------------- fused router (all layers) ----------------
__global__ void router_all(const float* __restrict__ embed, const float* __restrict__ f0r,
                           const float* __restrict__ fr, const int* __restrict__ seqlen,
                           float* __restrict__ gtokA, int* __restrict__ listsA,
                           int* __restrict__ cntA, float* __restrict__ impA)
{
    int l = blockIdx.y;
    const float* R = (l == 0) ? f0r : fr + (size_t)(l - 1) * DMODEL * NEXP;
    float* gtok = gtokA + (size_t)l * NTOK;
    int* lists = listsA + (size_t)l * NEXP * NTOK;
    int* cnt = cntA + l * NEXP;
    float* imp = impA + l * NEXP;

    int gw = (blockIdx.x * blockDim.x + threadIdx.x) >> 5;
    int lane = threadIdx.x & 31;
    if (gw >= NTOK) return;
    const float* xr = embed + (size_t)gw * DMODEL;
    float l0 = 0, l1 = 0, l2 = 0, l3 = 0;
    for (int d = lane; d < DMODEL; d += 32) {
        float v = xr[d];
        const float* rr = R + d * 4;
        l0 += v * rr[0]; l1 += v * rr[1]; l2 += v * rr[2]; l3 += v * rr[3];
    }
    for (int off = 16; off; off >>= 1) {
        l0 += __shfl_xor_sync(0xffffffffu, l0, off);
        l1 += __shfl_xor_sync(0xffffffffu, l1, off);
        l2 += __shfl_xor_sync(0xffffffffu, l2, off);
        l3 += __shfl_xor_sync(0xffffffffu, l3, off);
    }
    if (lane == 0) {
        float mx = fmaxf(fmaxf(l0, l1), fmaxf(l2, l3));
        float e0 = __expf(l0 - mx), e1 = __expf(l1 - mx);
        float e2 = __expf(l2 - mx), e3 = __expf(l3 - mx);
        float inv = 1.f / (e0 + e1 + e2 + e3);
        float s0 = e0 * inv, s1 = e1 * inv, s2 = e2 * inv, s3 = e3 * inv;
        int em = 0; float gm = s0;
        if (s1 > gm) { gm = s1; em = 1; }
        if (s2 > gm) { gm = s2; em = 2; }
        if (s3 > gm) { gm = s3; em = 3; }
        int b = gw >> 9, t = gw & 511;
        if (t < seqlen[b]) {
            atomicAdd(&imp[0], s0); atomicAdd(&imp[1], s1);
            atomicAdd(&imp[2], s2); atomicAdd(&imp[3], s3);
        }
        gtok[gw] = gm;
        int slot = atomicAdd(&cnt[em], 1);
        lists[em * NTOK + slot] = gw;
    }
}

// ---------------- FSMN (+optional PE, emits split(cur)) ----------------
__global__ void fsmn_kernel(const float* __restrict__ P, const float* __restrict__ fb,
                            const float* __restrict__ fa, const float* __restrict__ skipin,
                            float* __restrict__ outp, int doPE)
{
    int idx = blockIdx.x * 256 + threadIdx.x;
    if (idx >= NTOK * DMODEL) return;
    int d = idx & 511;
    int t = (idx >> 9) & 511;
    float v = P[idx];
    #pragma unroll
    for (int k = 0; k < 4; k++) {
        int off = (k + 1) * 2;
        if (t - off >= 0) v += fb[k * DMODEL + d] * P[idx - off * DMODEL];
    }
    if (t + 1 < TLEN) v += fa[d] * P[idx + DMODEL];
    if (skipin) v += skipin[idx];
    if (doPE) {
        int i = d >> 1;
        float div = __expf(-(float)(2 * i) * (9.2103403719761836f / 512.f));
        float a = (float)t * div;
        v += (d & 1) ? cosf(a) : sinf(a);
    }
    outp[idx] = v;
    __nv_bfloat16 h = __float2bfloat16(v);
    g_ahi[idx] = h;
    g_alo[idx] = __float2bfloat16(v - __bfloat162float(h));
}

// ---------------- memory KV rows ----------------
__global__ void memrows_kernel(const float* __restrict__ mk, const float* __restrict__ mv)
{
    int idx = blockIdx.x * 256 + threadIdx.x;
    if (idx >= BATCH * MMEM * DMODEL) return;
    int d = idx & 511;
    int r = idx >> 9;
    int m = r & 63;
    int b = r >> 6;
    size_t krow = (size_t)(NTOK + b * SFULL + TLEN + m);
    size_t vrow = krow + BSF;
    float kv = mk[m * DMODEL + d];
    float vv = mv[m * DMODEL + d];
    __nv_bfloat16 hk = __float2bfloat16(kv);
    g_qkvh[krow * DMODEL + d] = hk;
    g_qkvl[krow * DMODEL + d] = __float2bfloat16(kv - __bfloat162float(hk));
    __nv_bfloat16 hv = __float2bfloat16(vv);
    g_qkvh[vrow * DMODEL + d] = hv;
    g_qkvl[vrow * DMODEL + d] = __float2bfloat16(vv - __bfloat162float(hv));
}

// ---------------- tensor-core flash attention (skips fully-masked tiles) ----------------
#define AT_PITCH 72
#define AT_QH 0
#define AT_QL (128*AT_PITCH)
#define AT_KH (2*128*AT_PITCH)
#define AT_KL (AT_KH + 64*AT_PITCH)
#define AT_VH (AT_KL + 64*AT_PITCH)
#define AT_VL (AT_VH + 64*AT_PITCH)
#define ATTN_SMEM ((AT_VL + 64*AT_PITCH) * 2)
__global__ __launch_bounds__(256, 1)
void attn_mma(const __nv_bfloat16* __restrict__ qh, const __nv_bfloat16* __restrict__ ql,
              const __nv_bfloat16* __restrict__ kh, const __nv_bfloat16* __restrict__ kl,
              const __nv_bfloat16* __restrict__ vh, const __nv_bfloat16* __restrict__ vl,
              const int* __restrict__ seqlen,
              __nv_bfloat16* __restrict__ Ohi, __nv_bfloat16* __restrict__ Olo)
{
    extern __shared__ __nv_bfloat16 sb[];
    int q0 = blockIdx.x * 128, h = blockIdx.y, b = blockIdx.z;
    int tid = threadIdx.x, wid = tid >> 5, lane = tid & 31;
    int slen = seqlen[b];
    int l8 = lane & 7, mat = lane >> 3, g = lane >> 2, t2 = (lane & 3) * 2;
    int mrow = wid * 16;

    #pragma unroll
    for (int i = 0; i < 4; i++) {
        int u = i * 256 + tid;
        int r = u >> 3, c8 = u & 7;
        size_t src = ((size_t)(b * TLEN + q0 + r)) * DMODEL + h * DH + c8 * 8;
        *(uint4*)&sb[AT_QH + r * AT_PITCH + c8 * 8] = *(const uint4*)(qh + src);
        *(uint4*)&sb[AT_QL + r * AT_PITCH + c8 * 8] = *(const uint4*)(ql + src);
    }

    uint32_t QhB = s2u(sb + AT_QH), QlB = s2u(sb + AT_QL);
    uint32_t KhB = s2u(sb + AT_KH), KlB = s2u(sb + AT_KL);
    uint32_t VhB = s2u(sb + AT_VH), VlB = s2u(sb + AT_VL);

    float o[8][4] = {};
    float m0 = -1e30f, m1 = -1e30f, l0 = 0.f, l1 = 0.f;

    for (int s0 = 0; s0 < SFULL; s0 += 64) {
        if (s0 >= slen && s0 + 64 <= TLEN) continue;
        __syncthreads();
        #pragma unroll
        for (int i = 0; i < 2; i++) {
            int u = i * 256 + tid;
            int r = u >> 3, c8 = u & 7;
            size_t src = ((size_t)(b * SFULL + s0 + r)) * DMODEL + h * DH + c8 * 8;
            uint32_t dst = r * AT_PITCH + c8 * 8;
            *(uint4*)&sb[AT_KH + dst] = *(const uint4*)(kh + src);
            *(uint4*)&sb[AT_KL + dst] = *(const uint4*)(kl + src);
            *(uint4*)&sb[AT_VH + dst] = *(const uint4*)(vh + src);
            *(uint4*)&sb[AT_VL + dst] = *(const uint4*)(vl + src);
        }
        __syncthreads();

        float sc[8][4] = {};
        #pragma unroll
        for (int pass = 0; pass < 3; pass++) {
            uint32_t aB = (pass == 2) ? QlB : QhB;
            uint32_t bB = (pass == 1) ? KlB : KhB;
            #pragma unroll
            for (int kc = 0; kc < 4; kc++) {
                uint32_t af[4];
                ldsm4(af, aB + (uint32_t)((mrow + (mat & 1) * 8 + l8) * AT_PITCH
                                          + kc * 16 + (mat >> 1) * 8) * 2);
                #pragma unroll
                for (int nf = 0; nf < 8; nf++) {
                    uint32_t bf2[2];
                    ldsm2(bf2, bB + (uint32_t)((nf * 8 + l8) * AT_PITCH
                                               + kc * 16 + ((lane >> 3) & 1) * 8) * 2);
                    mma_bf16(sc[nf], af, bf2);
                }
            }
        }

        float rm0 = -1e30f, rm1 = -1e30f;
        #pragma unroll
        for (int nf = 0; nf < 8; nf++) {
            #pragma unroll
            for (int j = 0; j < 4; j++) {
                int sg = s0 + nf * 8 + t2 + (j & 1);
                float v = sc[nf][j] * 0.125f;
                sc[nf][j] = (sg >= slen && sg < TLEN) ? -1e9f : v;
            }
            rm0 = fmaxf(rm0, fmaxf(sc[nf][0], sc[nf][1]));
            rm1 = fmaxf(rm1, fmaxf(sc[nf][2], sc[nf][3]));
        }
        rm0 = fmaxf(rm0, __shfl_xor_sync(0xffffffffu, rm0, 1));
        rm0 = fmaxf(rm0, __shfl_xor_sync(0xffffffffu, rm0, 2));
        rm1 = fmaxf(rm1, __shfl_xor_sync(0xffffffffu, rm1, 1));
        rm1 = fmaxf(rm1, __shfl_xor_sync(0xffffffffu, rm1, 2));
        float mn0 = fmaxf(m0, rm0), mn1 = fmaxf(m1, rm1);
        float e0 = __expf(m0 - mn0), e1 = __expf(m1 - mn1);
        float rs0 = 0.f, rs1 = 0.f;
        #pragma unroll
        for (int nf = 0; nf < 8; nf++) {
            sc[nf][0] = __expf(sc[nf][0] - mn0); rs0 += sc[nf][0];
            sc[nf][1] = __expf(sc[nf][1] - mn0); rs0 += sc[nf][1];
            sc[nf][2] = __expf(sc[nf][2] - mn1); rs1 += sc[nf][2];
            sc[nf][3] = __expf(sc[nf][3] - mn1); rs1 += sc[nf][3];
        }
        rs0 += __shfl_xor_sync(0xffffffffu, rs0, 1);
        rs0 += __shfl_xor_sync(0xffffffffu, rs0, 2);
        rs1 += __shfl_xor_sync(0xffffffffu, rs1, 1);
        rs1 += __shfl_xor_sync(0xffffffffu, rs1, 2);
        l0 = l0 * e0 + rs0; l1 = l1 * e1 + rs1;
        m0 = mn0; m1 = mn1;
        #pragma unroll
        for (int nf = 0; nf < 8; nf++) {
            o[nf][0] *= e0; o[nf][1] *= e0; o[nf][2] *= e1; o[nf][3] *= e1;
        }

        uint32_t phi[4][4], plo[4][4];
        #pragma unroll
        for (int kc = 0; kc < 4; kc++) {
            float* A = sc[2 * kc];
            float* B = sc[2 * kc + 1];
            phi[kc][0] = packbf(A[0], A[1]); phi[kc][1] = packbf(A[2], A[3]);
            phi[kc][2] = packbf(B[0], B[1]); phi[kc][3] = packbf(B[2], B[3]);
            plo[kc][0] = packbf(bfres(A[0]), bfres(A[1]));
            plo[kc][1] = packbf(bfres(A[2]), bfres(A[3]));
            plo[kc][2] = packbf(bfres(B[0]), bfres(B[1]));
            plo[kc][3] = packbf(bfres(B[2]), bfres(B[3]));
        }

        #pragma unroll
        for (int pass = 0; pass < 3; pass++) {
            uint32_t vB = (pass == 1) ? VlB : VhB;
            #pragma unroll
            for (int kc = 0; kc < 4; kc++) {
                const uint32_t* pf = (pass == 2) ? plo[kc] : phi[kc];
                #pragma unroll
                for (int nf = 0; nf < 8; nf++) {
                    uint32_t bf2[2];
                    ldsm2t(bf2, vB + (uint32_t)((kc * 16 + ((lane >> 3) & 1) * 8 + l8) * AT_PITCH
                                                + nf * 8) * 2);
                    mma_bf16(o[nf], pf, bf2);
                }
            }
        }
    }

    float inv0 = 1.f / l0, inv1 = 1.f / l1;
    int r0 = q0 + mrow + g;
    #pragma unroll
    for (int nf = 0; nf < 8; nf++) {
        int cc = h * DH + nf * 8 + t2;
        size_t i0 = ((size_t)(b * TLEN + r0)) * DMODEL + cc;
        size_t i1 = ((size_t)(b * TLEN + r0 + 8)) * DMODEL + cc;
        float v0 = o[nf][0] * inv0, v1 = o[nf][1] * inv0;
        float w0 = o[nf][2] * inv1, w1 = o[nf][3] * inv1;
        *(uint32_t*)(Ohi + i0) = packbf(v0, v1);
        *(uint32_t*)(Olo + i0) = packbf(bfres(v0), bfres(v1));
        *(uint32_t*)(Ohi + i1) = packbf(w0, w1);
        *(uint32_t*)(Olo + i1) = packbf(bfres(w0), bfres(w1));
    }
}

// ---------------- layernorm (emits split(cur)) ----------------
__global__ void ln_kernel(const float* __restrict__ X, float* __restrict__ Y,
                          const float* __restrict__ gw, const float* __restrict__ bw)
{
    __shared__ float red[128];
    int row = blockIdx.x, tid = threadIdx.x;
    const float* xr = X + (size_t)row * DMODEL;
    float v[4]; float s = 0.f;
    #pragma unroll
    for (int i = 0; i < 4; i++) { v[i] = xr[tid + 128 * i]; s += v[i]; }
    red[tid] = s; __syncthreads();
    for (int off = 64; off > 0; off >>= 1) {
        if (tid < off) red[tid] += red[tid + off];
        __syncthreads();
    }
    float mu = red[0] * (1.f / 512.f);
    __syncthreads();
    float s2 = 0.f;
    #pragma unroll
    for (int i = 0; i < 4; i++) { float d = v[i] - mu; s2 += d * d; }
    red[tid] = s2; __syncthreads();
    for (int off = 64; off > 0; off >>= 1) {
        if (tid < off) red[tid] += red[tid + off];
        __syncthreads();
    }
    float inv = rsqrtf(red[0] * (1.f / 512.f) + 1e-5f);
    #pragma unroll
    for (int i = 0; i < 4; i++) {
        int c = tid + 128 * i;
        float y = (v[i] - mu) * inv * gw[c] + bw[c];
        size_t idx = (size_t)row * DMODEL + c;
        Y[idx] = y;
        __nv_bfloat16 h = __float2bfloat16(y);
        g_ahi[idx] = h;
        g_alo[idx] = __float2bfloat16(y - __bfloat162float(h));
    }
}

// ---------------- aux ----------------
__global__ void aux_kernel(float* __restrict__ dst)
{
    float tot = 0.f;
    for (int l = 0; l < NLAYER; l++) {
        float m = 0.f;
        for (int e = 0; e < NEXP; e++) m += g_imp[l * 4 + e];
        m *= 0.25f;
        float var = 0.f;
        for (int e = 0; e < NEXP; e++) { float d = g_imp[l * 4 + e] - m; var += d * d; }
        var *= 0.25f;
        tot += var / (m * m + 1e-9f);
    }
    dst[0] = tot;
}

// ---------------- launcher (R9 schedule) ----------------
extern "C" void kernel_launch(void* const* d_in, const int* in_sizes, int n_in,
                              void* d_out, int out_size)
{
    const float* x         = (const float*)d_in[0];
    const int*   seq       = (const int*)  d_in[1];
    const float* emb_w1    = (const float*)d_in[2];
    const float* emb_b1    = (const float*)d_in[3];
    const float* emb_w2    = (const float*)d_in[4];
    const float* emb_wo    = (const float*)d_in[5];
    const float* f0_w1     = (const float*)d_in[6];
    const float* f0_b1     = (const float*)d_in[7];
    const float* f0_w2     = (const float*)d_in[8];
    const float* f0_router = (const float*)d_in[9];
    const float* f0_fb     = (const float*)d_in[10];
    const float* f0_fa     = (const float*)d_in[11];
    const float* f_w1      = (const float*)d_in[12];
    const float* f_b1      = (const float*)d_in[13];
    const float* f_w2      = (const float*)d_in[14];
    const float* f_router  = (const float*)d_in[15];
    const float* f_fb      = (const float*)d_in[16];
    const float* f_fa      = (const float*)d_in[17];
    const float* wq        = (const float*)d_in[18];
    const float* wk        = (const float*)d_in[19];
    const float* wv        = (const float*)d_in[20];
    const float* wvo       = (const float*)d_in[21];
    const float* mk        = (const float*)d_in[22];
    const float* mv        = (const float*)d_in[23];
    const float* lng       = (const float*)d_in[24];
    const float* lnb       = (const float*)d_in[25];
    const float* out_w     = (const float*)d_in[26];
    const float* out_b     = (const float*)d_in[27];
    float* out = (float*)d_out;

    float *embed, *cur, *p, *tmp, *gtok, *imp;
    int *cnt, *lists, *maps;
    __nv_bfloat16 *whi, *wlo, *ahi, *alo, *bhi, *blo, *ehi, *elo, *xhi, *xlo, *qkvh, *qkvl;
    cudaGetSymbolAddress((void**)&embed, g_embed);
    cudaGetSymbolAddress((void**)&cur,   g_cur);
    cudaGetSymbolAddress((void**)&p,     g_p);
    cudaGetSymbolAddress((void**)&tmp,   g_tmp);
    cudaGetSymbolAddress((void**)&gtok,  g_gtok);
    cudaGetSymbolAddress((void**)&imp,   g_imp);
    cudaGetSymbolAddress((void**)&cnt,   g_cnt);
    cudaGetSymbolAddress((void**)&lists, g_lists);
    cudaGetSymbolAddress((void**)&maps,  g_maps);
    cudaGetSymbolAddress((void**)&whi,   g_whi);
    cudaGetSymbolAddress((void**)&wlo,   g_wlo);
    cudaGetSymbolAddress((void**)&ahi,   g_ahi);
    cudaGetSymbolAddress((void**)&alo,   g_alo);
    cudaGetSymbolAddress((void**)&bhi,   g_bhi);
    cudaGetSymbolAddress((void**)&blo,   g_blo);
    cudaGetSymbolAddress((void**)&ehi,   g_ehi);
    cudaGetSymbolAddress((void**)&elo,   g_elo);
    cudaGetSymbolAddress((void**)&xhi,   g_xhi);
    cudaGetSymbolAddress((void**)&xlo,   g_xlo);
    cudaGetSymbolAddress((void**)&qkvh,  g_qkvh);
    cudaGetSymbolAddress((void**)&qkvl,  g_qkvl);

    cudaFuncSetAttribute(attn_mma, cudaFuncAttributeMaxDynamicSharedMemorySize, ATTN_SMEM);
    cudaFuncSetAttribute(tgemm, cudaFuncAttributeMaxDynamicSharedMemorySize, TG_SMEM);

    cudaStream_t s1;
    cudaStreamCreate(&s1);
    cudaEvent_t evF, evJ, evE0, evE1;
    cudaEventCreateWithFlags(&evF, cudaEventDisableTiming);
    cudaEventCreateWithFlags(&evJ, cudaEventDisableTiming);
    cudaEventCreateWithFlags(&evE0, cudaEventDisableTiming);
    cudaEventCreateWithFlags(&evE1, cudaEventDisableTiming);

    auto TG = [&](unsigned woff, const __nv_bfloat16* Ah, const __nv_bfloat16* Al,
                  float* C, __nv_bfloat16* Ch, __nv_bfloat16* Cl,
                  int M, int N, int K,
                  const float* bias, int relu, const int* ga, const int* sc,
                  const float* rs, const float* res, const int* Md,
                  int E = 1, int sB = 0, int sBias = 0, int sList = 0,
                  cudaStream_t st = 0) {
        dim3 grid(N / 128, (M + 127) / 128, E);
        tgemm<<<grid, 256, TG_SMEM, st>>>(Ah, Al, whi + woff, wlo + woff, C, Ch, Cl,
                                          N, K, M, bias, relu, ga, sc, rs, res, Md,
                                          sB, sBias, sList);
    };
    auto WS = [&](const float* W, unsigned off, int nelem, cudaStream_t st) {
        wsplit<<<(nelem / 4 + 255) / 256, 256, 0, st>>>(W, whi + off, wlo + off, nelem / 4);
    };

    init_kernel<<<1, 1024>>>();

    // main-stream prep
    xsplit<<<(NTOK * KPAD + 255) / 256, 256>>>(x);
    wsplit_pad<<<(KPAD * 1024 / 4 + 255) / 256, 256>>>(emb_w1, whi + OFF_EMBW1,
                                                       wlo + OFF_EMBW1, 1024, KPAD * 1024 / 4);
    wsplit_pad<<<(NEXP * KPAD * 1024 / 4 + 255) / 256, 256>>>(f0_w1, whi + OFF_F0W1,
                                                              wlo + OFF_F0W1, 1024,
                                                              NEXP * KPAD * 1024 / 4);
    WS(emb_w2, OFF_EMBW2, 1024 * 512, 0);
    WS(f0_w2,  OFF_F0W2, 4 * 1024 * 512, 0);

    // side-stream weight splits
    cudaEventRecord(evF, 0);
    cudaStreamWaitEvent(s1, evF, 0);
    WS(emb_wo, OFF_EMBWO, 512 * 4096, s1);
    WS(f_w1, OFF_FW1, 28 * 512 * 1024, s1);
    WS(f_w2, OFF_FW2, 28 * 1024 * 512, s1);
    for (int bi = 0; bi < 2; bi++) {
        WS(wq + (size_t)bi * MAT_SZ, OFF_QKV + bi * 3u * MAT_SZ + 0u * MAT_SZ, MAT_SZ, s1);
        WS(wk + (size_t)bi * MAT_SZ, OFF_QKV + bi * 3u * MAT_SZ + 1u * MAT_SZ, MAT_SZ, s1);
        WS(wv + (size_t)bi * MAT_SZ, OFF_QKV + bi * 3u * MAT_SZ + 2u * MAT_SZ, MAT_SZ, s1);
    }
    WS(wvo,   OFF_WO, 2 * 512 * 512, s1);
    WS(out_w, OFF_OUTW, 512 * 4096, s1);
    cudaEventRecord(evJ, s1);

    // embed sub-network
    TG(OFF_EMBW1, xhi, xlo, 0, bhi, blo, NTOK, DHID, KPAD, emb_b1, 1, 0, 0, 0, 0, 0);
    TG(OFF_EMBW2, bhi, blo, embed, ehi, elo, NTOK, DMODEL, DHID, 0, 0, 0, 0, 0, 0, 0);
    cudaEventRecord(evE0, 0);

    // embed_out on side stream
    cudaStreamWaitEvent(s1, evE0, 0);
    TG(OFF_EMBWO, ehi, elo, out + (size_t)NTOK * DOUT, 0, 0, NTOK, DOUT, DMODEL,
       0, 0, 0, 0, 0, 0, 0, 1, 0, 0, 0, s1);
    cudaEventRecord(evE1, s1);

    router_all<<<dim3(NTOK / 8, NLAYER), 256>>>(embed, f0_router, f_router, seq,
                                                gtok, lists, cnt, imp);

    for (int l = 0; l < NLAYER; l++) {
        int* lst = lists + (size_t)l * NEXP * NTOK;
        float* gt = gtok + (size_t)l * NTOK;
        int* ct = cnt + l * 4;

        if (l == 1) cudaStreamWaitEvent(0, evJ, 0);

        if (l == 0) {
            TG(OFF_F0W1, xhi, xlo, 0, bhi, blo, NTOK, DHID, KPAD,
               f0_b1, 1, lst, lst, 0, 0, ct, NEXP, KPAD * DHID, DHID, NTOK);
            TG(OFF_F0W2, bhi, blo, p, 0, 0, NTOK, DMODEL, DHID, 0, 0, lst, lst,
               gt, 0, ct, NEXP, DMODEL * DHID, 0, NTOK);
        } else {
            TG(OFF_FW1 + (unsigned)(l - 1) * 4u * DMODEL * DHID, ahi, alo,
               0, bhi, blo, NTOK, DHID, DMODEL,
               f_b1 + (size_t)(l - 1) * NEXP * DHID, 1, lst, lst, 0, 0, ct,
               NEXP, DMODEL * DHID, DHID, NTOK);
            TG(OFF_FW2 + (unsigned)(l - 1) * 4u * DHID * DMODEL, bhi, blo,
               p, 0, 0, NTOK, DMODEL, DHID,
               0, 0, lst, lst, gt, 0, ct,
               NEXP, DHID * DMODEL, 0, NTOK);
        }
        const float* fbL = (l == 0) ? f0_fb : f_fb + (size_t)(l - 1) * 4 * DMODEL;
        const float* faL = (l == 0) ? f0_fa : f_fa + (size_t)(l - 1) * DMODEL;
        fsmn_kernel<<<NTOK * DMODEL / 256, 256>>>(p, fbL, faL,
                                                  (l == 0) ? (const float*)0 : cur, cur,
                                                  l == 3 ? 1 : 0);

        if (l == 3 || l == 7) {
            int bi = l / 4;
            TG(OFF_QKV + (unsigned)bi * 3u * MAT_SZ, ahi, alo, 0, qkvh, qkvl,
               NTOK, DMODEL, DMODEL, 0, 0, 0, maps, 0, 0, 0, 3, MAT_SZ, 0, NTOK);
            memrows_kernel<<<BATCH * MMEM * DMODEL / 256, 256>>>(
                mk + (size_t)bi * MMEM * DMODEL, mv + (size_t)bi * MMEM * DMODEL);
            attn_mma<<<dim3(TLEN / 128, NHEAD, BATCH), 256, ATTN_SMEM>>>(
                qkvh, qkvl,
                qkvh + (size_t)NTOK * DMODEL, qkvl + (size_t)NTOK * DMODEL,
                qkvh + (size_t)(NTOK + BSF) * DMODEL, qkvl + (size_t)(NTOK + BSF) * DMODEL,
                seq, bhi, blo);
            TG(OFF_WO + (unsigned)bi * MAT_SZ, bhi, blo, tmp, 0, 0,
               NTOK, DMODEL, DMODEL, 0, 0, 0, 0, 0, cur, 0);
            ln_kernel<<<NTOK, 128>>>(tmp, cur, lng + bi * DMODEL, lnb + bi * DMODEL);
        }
    }

    TG(OFF_OUTW, ahi, alo, out, 0, 0, NTOK, DOUT, DMODEL, out_b, 0, 0, 0, 0, 0, 0);
    cudaStreamWaitEvent(0, evE1, 0);
    aux_kernel<<<1, 1>>>(out + 2 * (size_t)NTOK * DOUT);
}

// round 14
// speedup vs baseline: 1.4114x; 1.2335x over previous
#include <cuda_runtime.h>
#include <cuda_bf16.h>
#include <math.h>
#include <stdint.h>

// ---------------- problem constants ----------------
#define BATCH 4
#define TLEN  512
#define NTOK  (BATCH*TLEN)
#define DIN   80
#define KPAD  96
#define DOUT  4096
#define DMODEL 512
#define DHID  1024
#define NEXP  4
#define NLAYER 8
#define NHEAD 8
#define DH    64
#define MMEM  64
#define SFULL (TLEN+MMEM)
#define BSF   (BATCH*SFULL)
#define QKV_ROWS (NTOK + 2*BSF)

// ---------------- device scratch ----------------
__device__ float g_embed[NTOK*DMODEL];
__device__ float g_cur[NTOK*DMODEL];
__device__ float g_p[NTOK*DMODEL];
__device__ float g_tmp[NTOK*DMODEL];
__device__ float g_gtok[NLAYER*NTOK];
__device__ float g_imp[NLAYER*NEXP];
__device__ int   g_cnt[NLAYER*NEXP];
__device__ int   g_lists[NLAYER*NEXP*NTOK];
__device__ int   g_maps[3*NTOK];

#define WPOOL (40u*1024u*1024u)
__device__ __nv_bfloat16 g_whi[WPOOL];
__device__ __nv_bfloat16 g_wlo[WPOOL];
__device__ __nv_bfloat16 g_ahi[NTOK*DMODEL];
__device__ __nv_bfloat16 g_alo[NTOK*DMODEL];
__device__ __nv_bfloat16 g_bhi[NTOK*DHID];
__device__ __nv_bfloat16 g_blo[NTOK*DHID];
__device__ __nv_bfloat16 g_ehi[NTOK*DMODEL];
__device__ __nv_bfloat16 g_elo[NTOK*DMODEL];
__device__ __nv_bfloat16 g_xhi[NTOK*KPAD];
__device__ __nv_bfloat16 g_xlo[NTOK*KPAD];
__device__ __nv_bfloat16 g_qkvh[QKV_ROWS*DMODEL];
__device__ __nv_bfloat16 g_qkvl[QKV_ROWS*DMODEL];

#define OFF_EMBW2 0u
#define OFF_EMBWO (OFF_EMBW2 + 512u*1024u)
#define OFF_F0W2  (OFF_EMBWO + 4096u*512u)
#define OFF_FW1   (OFF_F0W2 + 4u*512u*1024u)
#define OFF_FW2   (OFF_FW1 + 28u*1024u*512u)
#define OFF_QKV   (OFF_FW2 + 28u*512u*1024u)
#define OFF_WO    (OFF_QKV + 6u*512u*512u)
#define OFF_OUTW  (OFF_WO + 2u*512u*512u)
#define OFF_EMBW1 (OFF_OUTW + 512u*4096u)
#define OFF_F0W1  (OFF_EMBW1 + 96u*1024u)
#define MAT_SZ    (512u*512u)

// ---------------- helpers ----------------
__device__ __forceinline__ uint32_t s2u(const void* p) {
    uint32_t a;
    asm("{ .reg .u64 t; cvta.to.shared.u64 t, %1; cvt.u32.u64 %0, t; }" : "=r"(a) : "l"(p));
    return a;
}
__device__ __forceinline__ void ldsm4(uint32_t* r, uint32_t addr) {
    asm volatile("ldmatrix.sync.aligned.m8n8.x4.shared.b16 {%0,%1,%2,%3}, [%4];"
        : "=r"(r[0]), "=r"(r[1]), "=r"(r[2]), "=r"(r[3]) : "r"(addr));
}
__device__ __forceinline__ void ldsm2(uint32_t* r, uint32_t addr) {
    asm volatile("ldmatrix.sync.aligned.m8n8.x2.shared.b16 {%0,%1}, [%2];"
        : "=r"(r[0]), "=r"(r[1]) : "r"(addr));
}
__device__ __forceinline__ void ldsm2t(uint32_t* r, uint32_t addr) {
    asm volatile("ldmatrix.sync.aligned.m8n8.x2.trans.shared.b16 {%0,%1}, [%2];"
        : "=r"(r[0]), "=r"(r[1]) : "r"(addr));
}
__device__ __forceinline__ void mma_bf16(float* c, const uint32_t* a, const uint32_t* b) {
    asm volatile("mma.sync.aligned.m16n8k16.row.col.f32.bf16.bf16.f32 "
        "{%0,%1,%2,%3}, {%4,%5,%6,%7}, {%8,%9}, {%0,%1,%2,%3};"
        : "+f"(c[0]), "+f"(c[1]), "+f"(c[2]), "+f"(c[3])
        : "r"(a[0]), "r"(a[1]), "r"(a[2]), "r"(a[3]), "r"(b[0]), "r"(b[1]));
}
__device__ __forceinline__ uint32_t packbf(float a, float b) {
    __nv_bfloat162 h = __floats2bfloat162_rn(a, b);
    return *(uint32_t*)&h;
}
__device__ __forceinline__ float bfres(float x) {
    return x - __bfloat162float(__float2bfloat16(x));
}
#define CPA(dst, src, sz) asm volatile("cp.async.ca.shared.global [%0], [%1], 16, %2;" \
    :: "r"(dst), "l"(src), "r"(sz))
#define CPC() asm volatile("cp.async.commit_group;" ::: "memory")
#define CPW() asm volatile("cp.async.wait_group 0;" ::: "memory")

// ---------------- init ----------------
__global__ void init_kernel() {
    int t = threadIdx.x;
    if (t < NLAYER*NEXP) { g_cnt[t] = 0; g_imp[t] = 0.f; }
    for (int i = t; i < NTOK; i += blockDim.x) {
        int kv = (i >> 9) * SFULL + (i & 511);
        g_maps[i] = i;
        g_maps[NTOK + i] = NTOK + kv;
        g_maps[2 * NTOK + i] = NTOK + BSF + kv;
    }
}

// ---------------- streaming weight split ----------------
__global__ void wsplit(const float* __restrict__ W, __nv_bfloat16* __restrict__ hi,
                       __nv_bfloat16* __restrict__ lo, int n4)
{
    int i = blockIdx.x * 256 + threadIdx.x;
    if (i >= n4) return;
    float4 v = ((const float4*)W)[i];
    __nv_bfloat162 h01 = __floats2bfloat162_rn(v.x, v.y);
    __nv_bfloat162 h23 = __floats2bfloat162_rn(v.z, v.w);
    __nv_bfloat162 l01 = __floats2bfloat162_rn(v.x - __bfloat162float(h01.x),
                                               v.y - __bfloat162float(h01.y));
    __nv_bfloat162 l23 = __floats2bfloat162_rn(v.z - __bfloat162float(h23.x),
                                               v.w - __bfloat162float(h23.y));
    uint2 hw, lw;
    hw.x = *(uint32_t*)&h01; hw.y = *(uint32_t*)&h23;
    lw.x = *(uint32_t*)&l01; lw.y = *(uint32_t*)&l23;
    *(uint2*)(hi + (size_t)i * 4) = hw;
    *(uint2*)(lo + (size_t)i * 4) = lw;
}

// ---------------- weight split with K pad 80->96 ----------------
__global__ void wsplit_pad(const float* __restrict__ W, __nv_bfloat16* __restrict__ hi,
                           __nv_bfloat16* __restrict__ lo, int N, int total4)
{
    int i = blockIdx.x * 256 + threadIdx.x;
    if (i >= total4) return;
    int elem = i * 4;
    int z = elem / (KPAD * N);
    int rem = elem - z * KPAD * N;
    int k = rem / N, n = rem - k * N;
    float4 v = make_float4(0.f, 0.f, 0.f, 0.f);
    if (k < DIN) v = *(const float4*)(W + (size_t)z * DIN * N + (size_t)k * N + n);
    __nv_bfloat162 h01 = __floats2bfloat162_rn(v.x, v.y);
    __nv_bfloat162 h23 = __floats2bfloat162_rn(v.z, v.w);
    __nv_bfloat162 l01 = __floats2bfloat162_rn(v.x - __bfloat162float(h01.x),
                                               v.y - __bfloat162float(h01.y));
    __nv_bfloat162 l23 = __floats2bfloat162_rn(v.z - __bfloat162float(h23.x),
                                               v.w - __bfloat162float(h23.y));
    uint2 hw, lw;
    hw.x = *(uint32_t*)&h01; hw.y = *(uint32_t*)&h23;
    lw.x = *(uint32_t*)&l01; lw.y = *(uint32_t*)&l23;
    *(uint2*)(hi + (size_t)elem) = hw;
    *(uint2*)(lo + (size_t)elem) = lw;
}

// ---------------- x split with pad 80->96 ----------------
__global__ void xsplit(const float* __restrict__ x)
{
    int i = blockIdx.x * 256 + threadIdx.x;
    if (i >= NTOK * KPAD) return;
    int row = i / KPAD, c = i - row * KPAD;
    float v = (c < DIN) ? x[(size_t)row * DIN + c] : 0.f;
    __nv_bfloat16 h = __float2bfloat16(v);
    g_xhi[i] = h;
    g_xlo[i] = __float2bfloat16(v - __bfloat162float(h));
}

// ---------------- bf16 TC GEMM (2-stage cp.async, templated M tile) ----------------
#define KC 32
#define APITCHB 80
#define BPITCHB 272
#define B_TILE (KC*BPITCHB)
#define TG_SMEM128 (2*(2*128*APITCHB + 2*B_TILE))
#define TG_SMEM64  (2*(2*64*APITCHB + 2*B_TILE))
template<int MTILE>
__global__ __launch_bounds__(256, 2)
void tgemm(const __nv_bfloat16* __restrict__ Ahi, const __nv_bfloat16* __restrict__ Alo,
           const __nv_bfloat16* __restrict__ Bhi, const __nv_bfloat16* __restrict__ Blo,
           float* __restrict__ C,
           __nv_bfloat16* __restrict__ Chi, __nv_bfloat16* __restrict__ Clo,
           int N, int K, int Mstatic,
           const float* __restrict__ bias, int doRelu,
           const int* __restrict__ gatherA, const int* __restrict__ scatterC,
           const float* __restrict__ rowScale, const float* __restrict__ residual,
           const int* __restrict__ Mdev, int strideB, int strideBias, int strideList)
{
    constexpr int MF = MTILE / 32;               // 16-row frags per warp
    constexpr int A_T = MTILE * APITCHB;
    constexpr int STG_T = 2 * A_T + 2 * B_TILE;
    extern __shared__ char smem[];
    int e = blockIdx.z;
    const __nv_bfloat16* Bhz = Bhi + (size_t)e * strideB;
    const __nv_bfloat16* Blz = Blo + (size_t)e * strideB;
    const float* biasz = bias ? bias + (size_t)e * strideBias : (const float*)0;
    const int* gA = gatherA ? gatherA + (size_t)e * strideList : (const int*)0;
    const int* sC = scatterC ? scatterC + (size_t)e * strideList : (const int*)0;
    int Ml = Mdev ? Mdev[e] : Mstatic;
    int row0 = blockIdx.y * MTILE;
    if (row0 >= Ml) return;
    int col0 = blockIdx.x * 128;
    int tid = threadIdx.x, wid = tid >> 5, lane = tid & 31;
    uint32_t sb = s2u(smem);

    int arow[2], lr[2], lu[2];
    bool aok[2];
    #pragma unroll
    for (int i = 0; i < 2; i++) {
        int unit = tid + i * 256;
        aok[i] = (unit < MTILE * 4);
        lr[i] = unit >> 2;
        lu[i] = unit & 3;
        int gr = row0 + lr[i];
        arow[i] = (aok[i] && gr < Ml) ? (gA ? gA[gr] : gr) : -1;
    }

    auto issue = [&](int c, int stage) {
        int k0 = c * KC;
        uint32_t base = sb + stage * STG_T;
        #pragma unroll
        for (int i = 0; i < 2; i++) {
            if (aok[i]) {
                uint32_t offA = (uint32_t)(lr[i] * APITCHB + lu[i] * 16);
                int ar = arow[i] >= 0 ? arow[i] : 0;
                uint32_t asz = arow[i] >= 0 ? 16u : 0u;
                CPA(base + offA, (const char*)(Ahi + (size_t)ar * K + k0 + lu[i] * 8), asz);
                CPA(base + A_T + offA, (const char*)(Alo + (size_t)ar * K + k0 + lu[i] * 8), asz);
            }
            int unit = tid + i * 256;
            int bk = unit >> 4, bc16 = unit & 15;
            uint32_t offB = (uint32_t)(bk * BPITCHB + bc16 * 16);
            const char* bh = (const char*)(Bhz + (size_t)(k0 + bk) * N + col0 + bc16 * 8);
            const char* bl = (const char*)(Blz + (size_t)(k0 + bk) * N + col0 + bc16 * 8);
            CPA(base + 2u * A_T + offB, bh, 16u);
            CPA(base + 2u * A_T + B_TILE + offB, bl, 16u);
        }
    };

    float acc[MF][4][4] = {};
    int wm = wid >> 2, wn = wid & 3;
    int m_base = wm * (MTILE / 2), n_base = wn * 32;
    int l8 = lane & 7, mat = lane >> 3, bsel = (lane >> 3) & 1;

    int nc = K / KC;
    issue(0, 0); CPC();

    for (int c = 0; c < nc; c++) {
        CPW();
        __syncthreads();
        if (c + 1 < nc) { issue(c + 1, (c + 1) & 1); CPC(); }

        uint32_t base = sb + (c & 1) * STG_T;
        uint32_t ahB = base, alB = base + A_T;
        uint32_t bhB = base + 2u * A_T, blB = base + 2u * A_T + B_TILE;
        #pragma unroll
        for (int ks = 0; ks < 2; ks++) {
            int kb = ks * 16;
            uint32_t aoff = (uint32_t)(kb + (mat >> 1) * 8) * 2;
            uint32_t af[MF][4], bfh[4][2], bfl[4][2];
            #pragma unroll
            for (int mf = 0; mf < MF; mf++)
                ldsm4(af[mf], ahB + (uint32_t)(m_base + mf * 16 + (mat & 1) * 8 + l8) * APITCHB + aoff);
            #pragma unroll
            for (int nf = 0; nf < 4; nf++)
                ldsm2t(bfh[nf], bhB + (uint32_t)(kb + bsel * 8 + l8) * BPITCHB
                                    + (uint32_t)(n_base + nf * 8) * 2);
            #pragma unroll
            for (int mf = 0; mf < MF; mf++)
                #pragma unroll
                for (int nf = 0; nf < 4; nf++)
                    mma_bf16(acc[mf][nf], af[mf], bfh[nf]);
            #pragma unroll
            for (int nf = 0; nf < 4; nf++)
                ldsm2t(bfl[nf], blB + (uint32_t)(kb + bsel * 8 + l8) * BPITCHB
                                    + (uint32_t)(n_base + nf * 8) * 2);
            #pragma unroll
            for (int mf = 0; mf < MF; mf++)
                #pragma unroll
                for (int nf = 0; nf < 4; nf++)
                    mma_bf16(acc[mf][nf], af[mf], bfl[nf]);
            #pragma unroll
            for (int mf = 0; mf < MF; mf++)
                ldsm4(af[mf], alB + (uint32_t)(m_base + mf * 16 + (mat & 1) * 8 + l8) * APITCHB + aoff);
            #pragma unroll
            for (int mf = 0; mf < MF; mf++)
                #pragma unroll
                for (int nf = 0; nf < 4; nf++)
                    mma_bf16(acc[mf][nf], af[mf], bfh[nf]);
        }
    }

    int g = lane >> 2, t2 = (lane & 3) * 2;
    #pragma unroll
    for (int mf = 0; mf < MF; mf++) {
        #pragma unroll
        for (int half = 0; half < 2; half++) {
            int r = row0 + m_base + mf * 16 + g + half * 8;
            if (r >= Ml) continue;
            int orow = sC ? sC[r] : r;
            float sc = rowScale ? rowScale[orow] : 1.f;
            size_t rb = (size_t)orow * N;
            #pragma unroll
            for (int nf = 0; nf < 4; nf++) {
                int cc = col0 + n_base + nf * 8 + t2;
                float v0 = acc[mf][nf][half * 2 + 0] * sc;
                float v1 = acc[mf][nf][half * 2 + 1] * sc;
                if (biasz) { v0 += biasz[cc]; v1 += biasz[cc + 1]; }
                if (residual) { v0 += residual[rb + cc]; v1 += residual[rb + cc + 1]; }
                if (doRelu) { v0 = fmaxf(v0, 0.f); v1 = fmaxf(v1, 0.f); }
                if (C) *(float2*)(C + rb + cc) = make_float2(v0, v1);
                if (Chi) {
                    *(uint32_t*)(Chi + rb + cc) = packbf(v0, v1);
                    *(uint32_t*)(Clo + rb + cc) = packbf(bfres(v0), bfres(v1));
                }
            }
        }
    }
}

// ---------------- fused router (all layers) ----------------
__global__ void router_all(const float* __restrict__ embed, const float* __restrict__ f0r,
                           const float* __restrict__ fr, const int* __restrict__ seqlen,
                           float* __restrict__ gtokA, int* __restrict__ listsA,
                           int* __restrict__ cntA, float* __restrict__ impA)
{
    int l = blockIdx.y;
    const float* R = (l == 0) ? f0r : fr + (size_t)(l - 1) * DMODEL * NEXP;
    float* gtok = gtokA + (size_t)l * NTOK;
    int* lists = listsA + (size_t)l * NEXP * NTOK;
    int* cnt = cntA + l * NEXP;
    float* imp = impA + l * NEXP;

    int gw = (blockIdx.x * blockDim.x + threadIdx.x) >> 5;
    int lane = threadIdx.x & 31;
    if (gw >= NTOK) return;
    const float* xr = embed + (size_t)gw * DMODEL;
    float l0 = 0, l1 = 0, l2 = 0, l3 = 0;
    for (int d = lane; d < DMODEL; d += 32) {
        float v = xr[d];
        const float* rr = R + d * 4;
        l0 += v * rr[0]; l1 += v * rr[1]; l2 += v * rr[2]; l3 += v * rr[3];
    }
    for (int off = 16; off; off >>= 1) {
        l0 += __shfl_xor_sync(0xffffffffu, l0, off);
        l1 += __shfl_xor_sync(0xffffffffu, l1, off);
        l2 += __shfl_xor_sync(0xffffffffu, l2, off);
        l3 += __shfl_xor_sync(0xffffffffu, l3, off);
    }
    if (lane == 0) {
        float mx = fmaxf(fmaxf(l0, l1), fmaxf(l2, l3));
        float e0 = __expf(l0 - mx), e1 = __expf(l1 - mx);
        float e2 = __expf(l2 - mx), e3 = __expf(l3 - mx);
        float inv = 1.f / (e0 + e1 + e2 + e3);
        float s0 = e0 * inv, s1 = e1 * inv, s2 = e2 * inv, s3 = e3 * inv;
        int em = 0; float gm = s0;
        if (s1 > gm) { gm = s1; em = 1; }
        if (s2 > gm) { gm = s2; em = 2; }
        if (s3 > gm) { gm = s3; em = 3; }
        int b = gw >> 9, t = gw & 511;
        if (t < seqlen[b]) {
            atomicAdd(&imp[0], s0); atomicAdd(&imp[1], s1);
            atomicAdd(&imp[2], s2); atomicAdd(&imp[3], s3);
        }
        gtok[gw] = gm;
        int slot = atomicAdd(&cnt[em], 1);
        lists[em * NTOK + slot] = gw;
    }
}

// ---------------- FSMN (+optional PE, emits split(cur)) ----------------
__global__ void fsmn_kernel(const float* __restrict__ P, const float* __restrict__ fb,
                            const float* __restrict__ fa, const float* __restrict__ skipin,
                            float* __restrict__ outp, int doPE)
{
    int idx = blockIdx.x * 256 + threadIdx.x;
    if (idx >= NTOK * DMODEL) return;
    int d = idx & 511;
    int t = (idx >> 9) & 511;
    float v = P[idx];
    #pragma unroll
    for (int k = 0; k < 4; k++) {
        int off = (k + 1) * 2;
        if (t - off >= 0) v += fb[k * DMODEL + d] * P[idx - off * DMODEL];
    }
    if (t + 1 < TLEN) v += fa[d] * P[idx + DMODEL];
    if (skipin) v += skipin[idx];
    if (doPE) {
        int i = d >> 1;
        float div = __expf(-(float)(2 * i) * (9.2103403719761836f / 512.f));
        float a = (float)t * div;
        v += (d & 1) ? cosf(a) : sinf(a);
    }
    outp[idx] = v;
    __nv_bfloat16 h = __float2bfloat16(v);
    g_ahi[idx] = h;
    g_alo[idx] = __float2bfloat16(v - __bfloat162float(h));
}

// ---------------- memory KV rows ----------------
__global__ void memrows_kernel(const float* __restrict__ mk, const float* __restrict__ mv)
{
    int idx = blockIdx.x * 256 + threadIdx.x;
    if (idx >= BATCH * MMEM * DMODEL) return;
    int d = idx & 511;
    int r = idx >> 9;
    int m = r & 63;
    int b = r >> 6;
    size_t krow = (size_t)(NTOK + b * SFULL + TLEN + m);
    size_t vrow = krow + BSF;
    float kv = mk[m * DMODEL + d];
    float vv = mv[m * DMODEL + d];
    __nv_bfloat16 hk = __float2bfloat16(kv);
    g_qkvh[krow * DMODEL + d] = hk;
    g_qkvl[krow * DMODEL + d] = __float2bfloat16(kv - __bfloat162float(hk));
    __nv_bfloat16 hv = __float2bfloat16(vv);
    g_qkvh[vrow * DMODEL + d] = hv;
    g_qkvl[vrow * DMODEL + d] = __float2bfloat16(vv - __bfloat162float(hv));
}

// ---------------- tensor-core flash attention (skips fully-masked tiles) ----------------
#define AT_PITCH 72
#define AT_QH 0
#define AT_QL (128*AT_PITCH)
#define AT_KH (2*128*AT_PITCH)
#define AT_KL (AT_KH + 64*AT_PITCH)
#define AT_VH (AT_KL + 64*AT_PITCH)
#define AT_VL (AT_VH + 64*AT_PITCH)
#define ATTN_SMEM ((AT_VL + 64*AT_PITCH) * 2)
__global__ __launch_bounds__(256, 1)
void attn_mma(const __nv_bfloat16* __restrict__ qh, const __nv_bfloat16* __restrict__ ql,
              const __nv_bfloat16* __restrict__ kh, const __nv_bfloat16* __restrict__ kl,
              const __nv_bfloat16* __restrict__ vh, const __nv_bfloat16* __restrict__ vl,
              const int* __restrict__ seqlen,
              __nv_bfloat16* __restrict__ Ohi, __nv_bfloat16* __restrict__ Olo)
{
    extern __shared__ __nv_bfloat16 sb[];
    int q0 = blockIdx.x * 128, h = blockIdx.y, b = blockIdx.z;
    int tid = threadIdx.x, wid = tid >> 5, lane = tid & 31;
    int slen = seqlen[b];
    int l8 = lane & 7, mat = lane >> 3, g = lane >> 2, t2 = (lane & 3) * 2;
    int mrow = wid * 16;

    #pragma unroll
    for (int i = 0; i < 4; i++) {
        int u = i * 256 + tid;
        int r = u >> 3, c8 = u & 7;
        size_t src = ((size_t)(b * TLEN + q0 + r)) * DMODEL + h * DH + c8 * 8;
        *(uint4*)&sb[AT_QH + r * AT_PITCH + c8 * 8] = *(const uint4*)(qh + src);
        *(uint4*)&sb[AT_QL + r * AT_PITCH + c8 * 8] = *(const uint4*)(ql + src);
    }

    uint32_t QhB = s2u(sb + AT_QH), QlB = s2u(sb + AT_QL);
    uint32_t KhB = s2u(sb + AT_KH), KlB = s2u(sb + AT_KL);
    uint32_t VhB = s2u(sb + AT_VH), VlB = s2u(sb + AT_VL);

    float o[8][4] = {};
    float m0 = -1e30f, m1 = -1e30f, l0 = 0.f, l1 = 0.f;

    for (int s0 = 0; s0 < SFULL; s0 += 64) {
        if (s0 >= slen && s0 + 64 <= TLEN) continue;
        __syncthreads();
        #pragma unroll
        for (int i = 0; i < 2; i++) {
            int u = i * 256 + tid;
            int r = u >> 3, c8 = u & 7;
            size_t src = ((size_t)(b * SFULL + s0 + r)) * DMODEL + h * DH + c8 * 8;
            uint32_t dst = r * AT_PITCH + c8 * 8;
            *(uint4*)&sb[AT_KH + dst] = *(const uint4*)(kh + src);
            *(uint4*)&sb[AT_KL + dst] = *(const uint4*)(kl + src);
            *(uint4*)&sb[AT_VH + dst] = *(const uint4*)(vh + src);
            *(uint4*)&sb[AT_VL + dst] = *(const uint4*)(vl + src);
        }
        __syncthreads();

        float sc[8][4] = {};
        #pragma unroll
        for (int pass = 0; pass < 3; pass++) {
            uint32_t aB = (pass == 2) ? QlB : QhB;
            uint32_t bB = (pass == 1) ? KlB : KhB;
            #pragma unroll
            for (int kc = 0; kc < 4; kc++) {
                uint32_t af[4];
                ldsm4(af, aB + (uint32_t)((mrow + (mat & 1) * 8 + l8) * AT_PITCH
                                          + kc * 16 + (mat >> 1) * 8) * 2);
                #pragma unroll
                for (int nf = 0; nf < 8; nf++) {
                    uint32_t bf2[2];
                    ldsm2(bf2, bB + (uint32_t)((nf * 8 + l8) * AT_PITCH
                                               + kc * 16 + ((lane >> 3) & 1) * 8) * 2);
                    mma_bf16(sc[nf], af, bf2);
                }
            }
        }

        float rm0 = -1e30f, rm1 = -1e30f;
        #pragma unroll
        for (int nf = 0; nf < 8; nf++) {
            #pragma unroll
            for (int j = 0; j < 4; j++) {
                int sg = s0 + nf * 8 + t2 + (j & 1);
                float v = sc[nf][j] * 0.125f;
                sc[nf][j] = (sg >= slen && sg < TLEN) ? -1e9f : v;
            }
            rm0 = fmaxf(rm0, fmaxf(sc[nf][0], sc[nf][1]));
            rm1 = fmaxf(rm1, fmaxf(sc[nf][2], sc[nf][3]));
        }
        rm0 = fmaxf(rm0, __shfl_xor_sync(0xffffffffu, rm0, 1));
        rm0 = fmaxf(rm0, __shfl_xor_sync(0xffffffffu, rm0, 2));
        rm1 = fmaxf(rm1, __shfl_xor_sync(0xffffffffu, rm1, 1));
        rm1 = fmaxf(rm1, __shfl_xor_sync(0xffffffffu, rm1, 2));
        float mn0 = fmaxf(m0, rm0), mn1 = fmaxf(m1, rm1);
        float e0 = __expf(m0 - mn0), e1 = __expf(m1 - mn1);
        float rs0 = 0.f, rs1 = 0.f;
        #pragma unroll
        for (int nf = 0; nf < 8; nf++) {
            sc[nf][0] = __expf(sc[nf][0] - mn0); rs0 += sc[nf][0];
            sc[nf][1] = __expf(sc[nf][1] - mn0); rs0 += sc[nf][1];
            sc[nf][2] = __expf(sc[nf][2] - mn1); rs1 += sc[nf][2];
            sc[nf][3] = __expf(sc[nf][3] - mn1); rs1 += sc[nf][3];
        }
        rs0 += __shfl_xor_sync(0xffffffffu, rs0, 1);
        rs0 += __shfl_xor_sync(0xffffffffu, rs0, 2);
        rs1 += __shfl_xor_sync(0xffffffffu, rs1, 1);
        rs1 += __shfl_xor_sync(0xffffffffu, rs1, 2);
        l0 = l0 * e0 + rs0; l1 = l1 * e1 + rs1;
        m0 = mn0; m1 = mn1;
        #pragma unroll
        for (int nf = 0; nf < 8; nf++) {
            o[nf][0] *= e0; o[nf][1] *= e0; o[nf][2] *= e1; o[nf][3] *= e1;
        }

        uint32_t phi[4][4], plo[4][4];
        #pragma unroll
        for (int kc = 0; kc < 4; kc++) {
            float* A = sc[2 * kc];
            float* B = sc[2 * kc + 1];
            phi[kc][0] = packbf(A[0], A[1]); phi[kc][1] = packbf(A[2], A[3]);
            phi[kc][2] = packbf(B[0], B[1]); phi[kc][3] = packbf(B[2], B[3]);
            plo[kc][0] = packbf(bfres(A[0]), bfres(A[1]));
            plo[kc][1] = packbf(bfres(A[2]), bfres(A[3]));
            plo[kc][2] = packbf(bfres(B[0]), bfres(B[1]));
            plo[kc][3] = packbf(bfres(B[2]), bfres(B[3]));
        }

        #pragma unroll
        for (int pass = 0; pass < 3; pass++) {
            uint32_t vB = (pass == 1) ? VlB : VhB;
            #pragma unroll
            for (int kc = 0; kc < 4; kc++) {
                const uint32_t* pf = (pass == 2) ? plo[kc] : phi[kc];
                #pragma unroll
                for (int nf = 0; nf < 8; nf++) {
                    uint32_t bf2[2];
                    ldsm2t(bf2, vB + (uint32_t)((kc * 16 + ((lane >> 3) & 1) * 8 + l8) * AT_PITCH
                                                + nf * 8) * 2);
                    mma_bf16(o[nf], pf, bf2);
                }
            }
        }
    }

    float inv0 = 1.f / l0, inv1 = 1.f / l1;
    int r0 = q0 + mrow + g;
    #pragma unroll
    for (int nf = 0; nf < 8; nf++) {
        int cc = h * DH + nf * 8 + t2;
        size_t i0 = ((size_t)(b * TLEN + r0)) * DMODEL + cc;
        size_t i1 = ((size_t)(b * TLEN + r0 + 8)) * DMODEL + cc;
        float v0 = o[nf][0] * inv0, v1 = o[nf][1] * inv0;
        float w0 = o[nf][2] * inv1, w1 = o[nf][3] * inv1;
        *(uint32_t*)(Ohi + i0) = packbf(v0, v1);
        *(uint32_t*)(Olo + i0) = packbf(bfres(v0), bfres(v1));
        *(uint32_t*)(Ohi + i1) = packbf(w0, w1);
        *(uint32_t*)(Olo + i1) = packbf(bfres(w0), bfres(w1));
    }
}

// ---------------- layernorm (emits split(cur)) ----------------
__global__ void ln_kernel(const float* __restrict__ X, float* __restrict__ Y,
                          const float* __restrict__ gw, const float* __restrict__ bw)
{
    __shared__ float red[128];
    int row = blockIdx.x, tid = threadIdx.x;
    const float* xr = X + (size_t)row * DMODEL;
    float v[4]; float s = 0.f;
    #pragma unroll
    for (int i = 0; i < 4; i++) { v[i] = xr[tid + 128 * i]; s += v[i]; }
    red[tid] = s; __syncthreads();
    for (int off = 64; off > 0; off >>= 1) {
        if (tid < off) red[tid] += red[tid + off];
        __syncthreads();
    }
    float mu = red[0] * (1.f / 512.f);
    __syncthreads();
    float s2 = 0.f;
    #pragma unroll
    for (int i = 0; i < 4; i++) { float d = v[i] - mu; s2 += d * d; }
    red[tid] = s2; __syncthreads();
    for (int off = 64; off > 0; off >>= 1) {
        if (tid < off) red[tid] += red[tid + off];
        __syncthreads();
    }
    float inv = rsqrtf(red[0] * (1.f / 512.f) + 1e-5f);
    #pragma unroll
    for (int i = 0; i < 4; i++) {
        int c = tid + 128 * i;
        float y = (v[i] - mu) * inv * gw[c] + bw[c];
        size_t idx = (size_t)row * DMODEL + c;
        Y[idx] = y;
        __nv_bfloat16 h = __float2bfloat16(y);
        g_ahi[idx] = h;
        g_alo[idx] = __float2bfloat16(y - __bfloat162float(h));
    }
}

// ---------------- aux ----------------
__global__ void aux_kernel(float* __restrict__ dst)
{
    float tot = 0.f;
    for (int l = 0; l < NLAYER; l++) {
        float m = 0.f;
        for (int e = 0; e < NEXP; e++) m += g_imp[l * 4 + e];
        m *= 0.25f;
        float var = 0.f;
        for (int e = 0; e < NEXP; e++) { float d = g_imp[l * 4 + e] - m; var += d * d; }
        var *= 0.25f;
        tot += var / (m * m + 1e-9f);
    }
    dst[0] = tot;
}

// ---------------- launcher (R9 schedule) ----------------
extern "C" void kernel_launch(void* const* d_in, const int* in_sizes, int n_in,
                              void* d_out, int out_size)
{
    const float* x         = (const float*)d_in[0];
    const int*   seq       = (const int*)  d_in[1];
    const float* emb_w1    = (const float*)d_in[2];
    const float* emb_b1    = (const float*)d_in[3];
    const float* emb_w2    = (const float*)d_in[4];
    const float* emb_wo    = (const float*)d_in[5];
    const float* f0_w1     = (const float*)d_in[6];
    const float* f0_b1     = (const float*)d_in[7];
    const float* f0_w2     = (const float*)d_in[8];
    const float* f0_router = (const float*)d_in[9];
    const float* f0_fb     = (const float*)d_in[10];
    const float* f0_fa     = (const float*)d_in[11];
    const float* f_w1      = (const float*)d_in[12];
    const float* f_b1      = (const float*)d_in[13];
    const float* f_w2      = (const float*)d_in[14];
    const float* f_router  = (const float*)d_in[15];
    const float* f_fb      = (const float*)d_in[16];
    const float* f_fa      = (const float*)d_in[17];
    const float* wq        = (const float*)d_in[18];
    const float* wk        = (const float*)d_in[19];
    const float* wv        = (const float*)d_in[20];
    const float* wvo       = (const float*)d_in[21];
    const float* mk        = (const float*)d_in[22];
    const float* mv        = (const float*)d_in[23];
    const float* lng       = (const float*)d_in[24];
    const float* lnb       = (const float*)d_in[25];
    const float* out_w     = (const float*)d_in[26];
    const float* out_b     = (const float*)d_in[27];
    float* out = (float*)d_out;

    float *embed, *cur, *p, *tmp, *gtok, *imp;
    int *cnt, *lists, *maps;
    __nv_bfloat16 *whi, *wlo, *ahi, *alo, *bhi, *blo, *ehi, *elo, *xhi, *xlo, *qkvh, *qkvl;
    cudaGetSymbolAddress((void**)&embed, g_embed);
    cudaGetSymbolAddress((void**)&cur,   g_cur);
    cudaGetSymbolAddress((void**)&p,     g_p);
    cudaGetSymbolAddress((void**)&tmp,   g_tmp);
    cudaGetSymbolAddress((void**)&gtok,  g_gtok);
    cudaGetSymbolAddress((void**)&imp,   g_imp);
    cudaGetSymbolAddress((void**)&cnt,   g_cnt);
    cudaGetSymbolAddress((void**)&lists, g_lists);
    cudaGetSymbolAddress((void**)&maps,  g_maps);
    cudaGetSymbolAddress((void**)&whi,   g_whi);
    cudaGetSymbolAddress((void**)&wlo,   g_wlo);
    cudaGetSymbolAddress((void**)&ahi,   g_ahi);
    cudaGetSymbolAddress((void**)&alo,   g_alo);
    cudaGetSymbolAddress((void**)&bhi,   g_bhi);
    cudaGetSymbolAddress((void**)&blo,   g_blo);
    cudaGetSymbolAddress((void**)&ehi,   g_ehi);
    cudaGetSymbolAddress((void**)&elo,   g_elo);
    cudaGetSymbolAddress((void**)&xhi,   g_xhi);
    cudaGetSymbolAddress((void**)&xlo,   g_xlo);
    cudaGetSymbolAddress((void**)&qkvh,  g_qkvh);
    cudaGetSymbolAddress((void**)&qkvl,  g_qkvl);

    cudaFuncSetAttribute(attn_mma, cudaFuncAttributeMaxDynamicSharedMemorySize, ATTN_SMEM);
    cudaFuncSetAttribute(tgemm<128>, cudaFuncAttributeMaxDynamicSharedMemorySize, TG_SMEM128);
    cudaFuncSetAttribute(tgemm<64>,  cudaFuncAttributeMaxDynamicSharedMemorySize, TG_SMEM64);

    cudaStream_t s1;
    cudaStreamCreate(&s1);
    cudaEvent_t evF, evJ, evE0, evE1;
    cudaEventCreateWithFlags(&evF, cudaEventDisableTiming);
    cudaEventCreateWithFlags(&evJ, cudaEventDisableTiming);
    cudaEventCreateWithFlags(&evE0, cudaEventDisableTiming);
    cudaEventCreateWithFlags(&evE1, cudaEventDisableTiming);

    auto TG = [&](unsigned woff, const __nv_bfloat16* Ah, const __nv_bfloat16* Al,
                  float* C, __nv_bfloat16* Ch, __nv_bfloat16* Cl,
                  int M, int N, int K,
                  const float* bias, int relu, const int* ga, const int* sc,
                  const float* rs, const float* res, const int* Md,
                  int E = 1, int sB = 0, int sBias = 0, int sList = 0,
                  cudaStream_t st = 0) {
        dim3 grid(N / 128, (M + 127) / 128, E);
        tgemm<128><<<grid, 256, TG_SMEM128, st>>>(Ah, Al, whi + woff, wlo + woff, C, Ch, Cl,
                                                  N, K, M, bias, relu, ga, sc, rs, res, Md,
                                                  sB, sBias, sList);
    };
    auto TG64 = [&](unsigned woff, const __nv_bfloat16* Ah, const __nv_bfloat16* Al,
                    float* C, __nv_bfloat16* Ch, __nv_bfloat16* Cl,
                    int M, int N, int K,
                    const float* bias, int relu, const int* ga, const int* sc,
                    const float* rs, const float* res, const int* Md,
                    int E, int sB, int sBias, int sList) {
        dim3 grid(N / 128, (M + 63) / 64, E);
        tgemm<64><<<grid, 256, TG_SMEM64>>>(Ah, Al, whi + woff, wlo + woff, C, Ch, Cl,
                                            N, K, M, bias, relu, ga, sc, rs, res, Md,
                                            sB, sBias, sList);
    };
    auto WS = [&](const float* W, unsigned off, int nelem, cudaStream_t st) {
        wsplit<<<(nelem / 4 + 255) / 256, 256, 0, st>>>(W, whi + off, wlo + off, nelem / 4);
    };

    init_kernel<<<1, 1024>>>();

    // main-stream prep
    xsplit<<<(NTOK * KPAD + 255) / 256, 256>>>(x);
    wsplit_pad<<<(KPAD * 1024 / 4 + 255) / 256, 256>>>(emb_w1, whi + OFF_EMBW1,
                                                       wlo + OFF_EMBW1, 1024, KPAD * 1024 / 4);
    wsplit_pad<<<(NEXP * KPAD * 1024 / 4 + 255) / 256, 256>>>(f0_w1, whi + OFF_F0W1,
                                                              wlo + OFF_F0W1, 1024,
                                                              NEXP * KPAD * 1024 / 4);
    WS(emb_w2, OFF_EMBW2, 1024 * 512, 0);
    WS(f0_w2,  OFF_F0W2, 4 * 1024 * 512, 0);

    // side-stream weight splits
    cudaEventRecord(evF, 0);
    cudaStreamWaitEvent(s1, evF, 0);
    WS(emb_wo, OFF_EMBWO, 512 * 4096, s1);
    WS(f_w1, OFF_FW1, 28 * 512 * 1024, s1);
    WS(f_w2, OFF_FW2, 28 * 1024 * 512, s1);
    for (int bi = 0; bi < 2; bi++) {
        WS(wq + (size_t)bi * MAT_SZ, OFF_QKV + bi * 3u * MAT_SZ + 0u * MAT_SZ, MAT_SZ, s1);
        WS(wk + (size_t)bi * MAT_SZ, OFF_QKV + bi * 3u * MAT_SZ + 1u * MAT_SZ, MAT_SZ, s1);
        WS(wv + (size_t)bi * MAT_SZ, OFF_QKV + bi * 3u * MAT_SZ + 2u * MAT_SZ, MAT_SZ, s1);
    }
    WS(wvo,   OFF_WO, 2 * 512 * 512, s1);
    WS(out_w, OFF_OUTW, 512 * 4096, s1);
    cudaEventRecord(evJ, s1);

    // embed sub-network
    TG(OFF_EMBW1, xhi, xlo, 0, bhi, blo, NTOK, DHID, KPAD, emb_b1, 1, 0, 0, 0, 0, 0);
    TG(OFF_EMBW2, bhi, blo, embed, ehi, elo, NTOK, DMODEL, DHID, 0, 0, 0, 0, 0, 0, 0);
    cudaEventRecord(evE0, 0);

    // embed_out on side stream
    cudaStreamWaitEvent(s1, evE0, 0);
    TG(OFF_EMBWO, ehi, elo, out + (size_t)NTOK * DOUT, 0, 0, NTOK, DOUT, DMODEL,
       0, 0, 0, 0, 0, 0, 0, 1, 0, 0, 0, s1);
    cudaEventRecord(evE1, s1);

    router_all<<<dim3(NTOK / 8, NLAYER), 256>>>(embed, f0_router, f_router, seq,
                                                gtok, lists, cnt, imp);

    for (int l = 0; l < NLAYER; l++) {
        int* lst = lists + (size_t)l * NEXP * NTOK;
        float* gt = gtok + (size_t)l * NTOK;
        int* ct = cnt + l * 4;

        if (l == 1) cudaStreamWaitEvent(0, evJ, 0);

        if (l == 0) {
            TG64(OFF_F0W1, xhi, xlo, 0, bhi, blo, NTOK, DHID, KPAD,
                 f0_b1, 1, lst, lst, 0, 0, ct, NEXP, KPAD * DHID, DHID, NTOK);
            TG64(OFF_F0W2, bhi, blo, p, 0, 0, NTOK, DMODEL, DHID, 0, 0, lst, lst,
                 gt, 0, ct, NEXP, DMODEL * DHID, 0, NTOK);
        } else {
            TG64(OFF_FW1 + (unsigned)(l - 1) * 4u * DMODEL * DHID, ahi, alo,
                 0, bhi, blo, NTOK, DHID, DMODEL,
                 f_b1 + (size_t)(l - 1) * NEXP * DHID, 1, lst, lst, 0, 0, ct,
                 NEXP, DMODEL * DHID, DHID, NTOK);
            TG64(OFF_FW2 + (unsigned)(l - 1) * 4u * DHID * DMODEL, bhi, blo,
                 p, 0, 0, NTOK, DMODEL, DHID,
                 0, 0, lst, lst, gt, 0, ct,
                 NEXP, DHID * DMODEL, 0, NTOK);
        }
        const float* fbL = (l == 0) ? f0_fb : f_fb + (size_t)(l - 1) * 4 * DMODEL;
        const float* faL = (l == 0) ? f0_fa : f_fa + (size_t)(l - 1) * DMODEL;
        fsmn_kernel<<<NTOK * DMODEL / 256, 256>>>(p, fbL, faL,
                                                  (l == 0) ? (const float*)0 : cur, cur,
                                                  l == 3 ? 1 : 0);

        if (l == 3 || l == 7) {
            int bi = l / 4;
            TG(OFF_QKV + (unsigned)bi * 3u * MAT_SZ, ahi, alo, 0, qkvh, qkvl,
               NTOK, DMODEL, DMODEL, 0, 0, 0, maps, 0, 0, 0, 3, MAT_SZ, 0, NTOK);
            memrows_kernel<<<BATCH * MMEM * DMODEL / 256, 256>>>(
                mk + (size_t)bi * MMEM * DMODEL, mv + (size_t)bi * MMEM * DMODEL);
            attn_mma<<<dim3(TLEN / 128, NHEAD, BATCH), 256, ATTN_SMEM>>>(
                qkvh, qkvl,
                qkvh + (size_t)NTOK * DMODEL, qkvl + (size_t)NTOK * DMODEL,
                qkvh + (size_t)(NTOK + BSF) * DMODEL, qkvl + (size_t)(NTOK + BSF) * DMODEL,
                seq, bhi, blo);
            TG(OFF_WO + (unsigned)bi * MAT_SZ, bhi, blo, tmp, 0, 0,
               NTOK, DMODEL, DMODEL, 0, 0, 0, 0, 0, cur, 0);
            ln_kernel<<<NTOK, 128>>>(tmp, cur, lng + bi * DMODEL, lnb + bi * DMODEL);
        }
    }

    TG(OFF_OUTW, ahi, alo, out, 0, 0, NTOK, DOUT, DMODEL, out_b, 0, 0, 0, 0, 0, 0);
    cudaStreamWaitEvent(0, evE1, 0);
    aux_kernel<<<1, 1>>>(out + 2 * (size_t)NTOK * DOUT);
}

// round 15
// speedup vs baseline: 1.4601x; 1.0345x over previous
#include <cuda_runtime.h>
#include <cuda_bf16.h>
#include <math.h>
#include <stdint.h>

// ---------------- problem constants ----------------
#define BATCH 4
#define TLEN  512
#define NTOK  (BATCH*TLEN)
#define DIN   80
#define KPAD  96
#define DOUT  4096
#define DMODEL 512
#define DHID  1024
#define NEXP  4
#define NLAYER 8
#define NHEAD 8
#define DH    64
#define MMEM  64
#define SFULL (TLEN+MMEM)
#define BSF   (BATCH*SFULL)
#define QKV_ROWS (NTOK + 2*BSF)

// ---------------- device scratch ----------------
__device__ float g_embed[NTOK*DMODEL];
__device__ float g_cur[NTOK*DMODEL];
__device__ float g_p[NTOK*DMODEL];
__device__ float g_tmp[NTOK*DMODEL];
__device__ float g_gtok[NLAYER*NTOK];
__device__ float g_imp[NLAYER*NEXP];
__device__ int   g_cnt[NLAYER*NEXP];
__device__ int   g_lists[NLAYER*NEXP*NTOK];
__device__ int   g_maps[3*NTOK];

#define WPOOL (40u*1024u*1024u)
__device__ __nv_bfloat16 g_whi[WPOOL];
__device__ __nv_bfloat16 g_wlo[WPOOL];
__device__ __nv_bfloat16 g_ahi[NTOK*DMODEL];
__device__ __nv_bfloat16 g_alo[NTOK*DMODEL];
__device__ __nv_bfloat16 g_bhi[NTOK*DHID];
__device__ __nv_bfloat16 g_blo[NTOK*DHID];
__device__ __nv_bfloat16 g_ehi[NTOK*DMODEL];
__device__ __nv_bfloat16 g_elo[NTOK*DMODEL];
__device__ __nv_bfloat16 g_xhi[NTOK*KPAD];
__device__ __nv_bfloat16 g_xlo[NTOK*KPAD];
__device__ __nv_bfloat16 g_qkvh[QKV_ROWS*DMODEL];
__device__ __nv_bfloat16 g_qkvl[QKV_ROWS*DMODEL];

#define OFF_EMBW2 0u
#define OFF_EMBWO (OFF_EMBW2 + 512u*1024u)
#define OFF_F0W2  (OFF_EMBWO + 4096u*512u)
#define OFF_FW1   (OFF_F0W2 + 4u*512u*1024u)
#define OFF_FW2   (OFF_FW1 + 28u*1024u*512u)
#define OFF_QKV   (OFF_FW2 + 28u*512u*1024u)
#define OFF_WO    (OFF_QKV + 6u*512u*512u)
#define OFF_OUTW  (OFF_WO + 2u*512u*512u)
#define OFF_EMBW1 (OFF_OUTW + 512u*4096u)
#define OFF_F0W1  (OFF_EMBW1 + 96u*1024u)
#define MAT_SZ    (512u*512u)

// ---------------- helpers ----------------
__device__ __forceinline__ uint32_t s2u(const void* p) {
    uint32_t a;
    asm("{ .reg .u64 t; cvta.to.shared.u64 t, %1; cvt.u32.u64 %0, t; }" : "=r"(a) : "l"(p));
    return a;
}
__device__ __forceinline__ void ldsm4(uint32_t* r, uint32_t addr) {
    asm volatile("ldmatrix.sync.aligned.m8n8.x4.shared.b16 {%0,%1,%2,%3}, [%4];"
        : "=r"(r[0]), "=r"(r[1]), "=r"(r[2]), "=r"(r[3]) : "r"(addr));
}
__device__ __forceinline__ void ldsm2(uint32_t* r, uint32_t addr) {
    asm volatile("ldmatrix.sync.aligned.m8n8.x2.shared.b16 {%0,%1}, [%2];"
        : "=r"(r[0]), "=r"(r[1]) : "r"(addr));
}
__device__ __forceinline__ void ldsm2t(uint32_t* r, uint32_t addr) {
    asm volatile("ldmatrix.sync.aligned.m8n8.x2.trans.shared.b16 {%0,%1}, [%2];"
        : "=r"(r[0]), "=r"(r[1]) : "r"(addr));
}
__device__ __forceinline__ void mma_bf16(float* c, const uint32_t* a, const uint32_t* b) {
    asm volatile("mma.sync.aligned.m16n8k16.row.col.f32.bf16.bf16.f32 "
        "{%0,%1,%2,%3}, {%4,%5,%6,%7}, {%8,%9}, {%0,%1,%2,%3};"
        : "+f"(c[0]), "+f"(c[1]), "+f"(c[2]), "+f"(c[3])
        : "r"(a[0]), "r"(a[1]), "r"(a[2]), "r"(a[3]), "r"(b[0]), "r"(b[1]));
}
__device__ __forceinline__ uint32_t packbf(float a, float b) {
    __nv_bfloat162 h = __floats2bfloat162_rn(a, b);
    return *(uint32_t*)&h;
}
__device__ __forceinline__ float bfres(float x) {
    return x - __bfloat162float(__float2bfloat16(x));
}
#define CPA(dst, src, sz) asm volatile("cp.async.ca.shared.global [%0], [%1], 16, %2;" \
    :: "r"(dst), "l"(src), "r"(sz))
#define CPC() asm volatile("cp.async.commit_group;" ::: "memory")
#define CPW() asm volatile("cp.async.wait_group 0;" ::: "memory")

// ---------------- init ----------------
__global__ void init_kernel() {
    int t = threadIdx.x;
    if (t < NLAYER*NEXP) { g_cnt[t] = 0; g_imp[t] = 0.f; }
    for (int i = t; i < NTOK; i += blockDim.x) {
        int kv = (i >> 9) * SFULL + (i & 511);
        g_maps[i] = i;
        g_maps[NTOK + i] = NTOK + kv;
        g_maps[2 * NTOK + i] = NTOK + BSF + kv;
    }
}

// ---------------- streaming weight split ----------------
__global__ void wsplit(const float* __restrict__ W, __nv_bfloat16* __restrict__ hi,
                       __nv_bfloat16* __restrict__ lo, int n4)
{
    int i = blockIdx.x * 256 + threadIdx.x;
    if (i >= n4) return;
    float4 v = ((const float4*)W)[i];
    __nv_bfloat162 h01 = __floats2bfloat162_rn(v.x, v.y);
    __nv_bfloat162 h23 = __floats2bfloat162_rn(v.z, v.w);
    __nv_bfloat162 l01 = __floats2bfloat162_rn(v.x - __bfloat162float(h01.x),
                                               v.y - __bfloat162float(h01.y));
    __nv_bfloat162 l23 = __floats2bfloat162_rn(v.z - __bfloat162float(h23.x),
                                               v.w - __bfloat162float(h23.y));
    uint2 hw, lw;
    hw.x = *(uint32_t*)&h01; hw.y = *(uint32_t*)&h23;
    lw.x = *(uint32_t*)&l01; lw.y = *(uint32_t*)&l23;
    *(uint2*)(hi + (size_t)i * 4) = hw;
    *(uint2*)(lo + (size_t)i * 4) = lw;
}

// ---------------- weight split with K pad 80->96 ----------------
__global__ void wsplit_pad(const float* __restrict__ W, __nv_bfloat16* __restrict__ hi,
                           __nv_bfloat16* __restrict__ lo, int N, int total4)
{
    int i = blockIdx.x * 256 + threadIdx.x;
    if (i >= total4) return;
    int elem = i * 4;
    int z = elem / (KPAD * N);
    int rem = elem - z * KPAD * N;
    int k = rem / N, n = rem - k * N;
    float4 v = make_float4(0.f, 0.f, 0.f, 0.f);
    if (k < DIN) v = *(const float4*)(W + (size_t)z * DIN * N + (size_t)k * N + n);
    __nv_bfloat162 h01 = __floats2bfloat162_rn(v.x, v.y);
    __nv_bfloat162 h23 = __floats2bfloat162_rn(v.z, v.w);
    __nv_bfloat162 l01 = __floats2bfloat162_rn(v.x - __bfloat162float(h01.x),
                                               v.y - __bfloat162float(h01.y));
    __nv_bfloat162 l23 = __floats2bfloat162_rn(v.z - __bfloat162float(h23.x),
                                               v.w - __bfloat162float(h23.y));
    uint2 hw, lw;
    hw.x = *(uint32_t*)&h01; hw.y = *(uint32_t*)&h23;
    lw.x = *(uint32_t*)&l01; lw.y = *(uint32_t*)&l23;
    *(uint2*)(hi + (size_t)elem) = hw;
    *(uint2*)(lo + (size_t)elem) = lw;
}

// ---------------- x split with pad 80->96 ----------------
__global__ void xsplit(const float* __restrict__ x)
{
    int i = blockIdx.x * 256 + threadIdx.x;
    if (i >= NTOK * KPAD) return;
    int row = i / KPAD, c = i - row * KPAD;
    float v = (c < DIN) ? x[(size_t)row * DIN + c] : 0.f;
    __nv_bfloat16 h = __float2bfloat16(v);
    g_xhi[i] = h;
    g_xlo[i] = __float2bfloat16(v - __bfloat162float(h));
}

// ---------------- bf16 TC GEMM (2-stage cp.async, templated M tile) ----------------
#define KC 32
#define APITCHB 80
#define BPITCHB 272
#define B_TILE (KC*BPITCHB)
#define TG_SMEM128 (2*(2*128*APITCHB + 2*B_TILE))
#define TG_SMEM64  (2*(2*64*APITCHB + 2*B_TILE))
template<int MTILE>
__global__ __launch_bounds__(256, 2)
void tgemm(const __nv_bfloat16* __restrict__ Ahi, const __nv_bfloat16* __restrict__ Alo,
           const __nv_bfloat16* __restrict__ Bhi, const __nv_bfloat16* __restrict__ Blo,
           float* __restrict__ C,
           __nv_bfloat16* __restrict__ Chi, __nv_bfloat16* __restrict__ Clo,
           int N, int K, int Mstatic,
           const float* __restrict__ bias, int doRelu,
           const int* __restrict__ gatherA, const int* __restrict__ scatterC,
           const float* __restrict__ rowScale, const float* __restrict__ residual,
           const int* __restrict__ Mdev, int strideB, int strideBias, int strideList)
{
    constexpr int MF = MTILE / 32;
    constexpr int A_T = MTILE * APITCHB;
    constexpr int STG_T = 2 * A_T + 2 * B_TILE;
    extern __shared__ char smem[];
    int e = blockIdx.z;
    const __nv_bfloat16* Bhz = Bhi + (size_t)e * strideB;
    const __nv_bfloat16* Blz = Blo + (size_t)e * strideB;
    const float* biasz = bias ? bias + (size_t)e * strideBias : (const float*)0;
    const int* gA = gatherA ? gatherA + (size_t)e * strideList : (const int*)0;
    const int* sC = scatterC ? scatterC + (size_t)e * strideList : (const int*)0;
    int Ml = Mdev ? Mdev[e] : Mstatic;
    int row0 = blockIdx.y * MTILE;
    if (row0 >= Ml) return;
    int col0 = blockIdx.x * 128;
    int tid = threadIdx.x, wid = tid >> 5, lane = tid & 31;
    uint32_t sb = s2u(smem);

    int arow[2], lr[2], lu[2];
    bool aok[2];
    #pragma unroll
    for (int i = 0; i < 2; i++) {
        int unit = tid + i * 256;
        aok[i] = (unit < MTILE * 4);
        lr[i] = unit >> 2;
        lu[i] = unit & 3;
        int gr = row0 + lr[i];
        arow[i] = (aok[i] && gr < Ml) ? (gA ? gA[gr] : gr) : -1;
    }

    auto issue = [&](int c, int stage) {
        int k0 = c * KC;
        uint32_t base = sb + stage * STG_T;
        #pragma unroll
        for (int i = 0; i < 2; i++) {
            if (aok[i]) {
                uint32_t offA = (uint32_t)(lr[i] * APITCHB + lu[i] * 16);
                int ar = arow[i] >= 0 ? arow[i] : 0;
                uint32_t asz = arow[i] >= 0 ? 16u : 0u;
                CPA(base + offA, (const char*)(Ahi + (size_t)ar * K + k0 + lu[i] * 8), asz);
                CPA(base + A_T + offA, (const char*)(Alo + (size_t)ar * K + k0 + lu[i] * 8), asz);
            }
            int unit = tid + i * 256;
            int bk = unit >> 4, bc16 = unit & 15;
            uint32_t offB = (uint32_t)(bk * BPITCHB + bc16 * 16);
            const char* bh = (const char*)(Bhz + (size_t)(k0 + bk) * N + col0 + bc16 * 8);
            const char* bl = (const char*)(Blz + (size_t)(k0 + bk) * N + col0 + bc16 * 8);
            CPA(base + 2u * A_T + offB, bh, 16u);
            CPA(base + 2u * A_T + B_TILE + offB, bl, 16u);
        }
    };

    float acc[MF][4][4] = {};
    int wm = wid >> 2, wn = wid & 3;
    int m_base = wm * (MTILE / 2), n_base = wn * 32;
    int l8 = lane & 7, mat = lane >> 3, bsel = (lane >> 3) & 1;

    int nc = K / KC;
    issue(0, 0); CPC();

    for (int c = 0; c < nc; c++) {
        CPW();
        __syncthreads();
        if (c + 1 < nc) { issue(c + 1, (c + 1) & 1); CPC(); }

        uint32_t base = sb + (c & 1) * STG_T;
        uint32_t ahB = base, alB = base + A_T;
        uint32_t bhB = base + 2u * A_T, blB = base + 2u * A_T + B_TILE;
        #pragma unroll
        for (int ks = 0; ks < 2; ks++) {
            int kb = ks * 16;
            uint32_t aoff = (uint32_t)(kb + (mat >> 1) * 8) * 2;
            uint32_t af[MF][4], bfh[4][2], bfl[4][2];
            #pragma unroll
            for (int mf = 0; mf < MF; mf++)
                ldsm4(af[mf], ahB + (uint32_t)(m_base + mf * 16 + (mat & 1) * 8 + l8) * APITCHB + aoff);
            #pragma unroll
            for (int nf = 0; nf < 4; nf++)
                ldsm2t(bfh[nf], bhB + (uint32_t)(kb + bsel * 8 + l8) * BPITCHB
                                    + (uint32_t)(n_base + nf * 8) * 2);
            #pragma unroll
            for (int mf = 0; mf < MF; mf++)
                #pragma unroll
                for (int nf = 0; nf < 4; nf++)
                    mma_bf16(acc[mf][nf], af[mf], bfh[nf]);
            #pragma unroll
            for (int nf = 0; nf < 4; nf++)
                ldsm2t(bfl[nf], blB + (uint32_t)(kb + bsel * 8 + l8) * BPITCHB
                                    + (uint32_t)(n_base + nf * 8) * 2);
            #pragma unroll
            for (int mf = 0; mf < MF; mf++)
                #pragma unroll
                for (int nf = 0; nf < 4; nf++)
                    mma_bf16(acc[mf][nf], af[mf], bfl[nf]);
            #pragma unroll
            for (int mf = 0; mf < MF; mf++)
                ldsm4(af[mf], alB + (uint32_t)(m_base + mf * 16 + (mat & 1) * 8 + l8) * APITCHB + aoff);
            #pragma unroll
            for (int mf = 0; mf < MF; mf++)
                #pragma unroll
                for (int nf = 0; nf < 4; nf++)
                    mma_bf16(acc[mf][nf], af[mf], bfh[nf]);
        }
    }

    int g = lane >> 2, t2 = (lane & 3) * 2;
    #pragma unroll
    for (int mf = 0; mf < MF; mf++) {
        #pragma unroll
        for (int half = 0; half < 2; half++) {
            int r = row0 + m_base + mf * 16 + g + half * 8;
            if (r >= Ml) continue;
            int orow = sC ? sC[r] : r;
            float sc = rowScale ? rowScale[orow] : 1.f;
            size_t rb = (size_t)orow * N;
            #pragma unroll
            for (int nf = 0; nf < 4; nf++) {
                int cc = col0 + n_base + nf * 8 + t2;
                float v0 = acc[mf][nf][half * 2 + 0] * sc;
                float v1 = acc[mf][nf][half * 2 + 1] * sc;
                if (biasz) { v0 += biasz[cc]; v1 += biasz[cc + 1]; }
                if (residual) { v0 += residual[rb + cc]; v1 += residual[rb + cc + 1]; }
                if (doRelu) { v0 = fmaxf(v0, 0.f); v1 = fmaxf(v1, 0.f); }
                if (C) *(float2*)(C + rb + cc) = make_float2(v0, v1);
                if (Chi) {
                    *(uint32_t*)(Chi + rb + cc) = packbf(v0, v1);
                    *(uint32_t*)(Clo + rb + cc) = packbf(bfres(v0), bfres(v1));
                }
            }
        }
    }
}

// ---------------- fused router (all layers) ----------------
__global__ void router_all(const float* __restrict__ embed, const float* __restrict__ f0r,
                           const float* __restrict__ fr, const int* __restrict__ seqlen,
                           float* __restrict__ gtokA, int* __restrict__ listsA,
                           int* __restrict__ cntA, float* __restrict__ impA)
{
    int l = blockIdx.y;
    const float* R = (l == 0) ? f0r : fr + (size_t)(l - 1) * DMODEL * NEXP;
    float* gtok = gtokA + (size_t)l * NTOK;
    int* lists = listsA + (size_t)l * NEXP * NTOK;
    int* cnt = cntA + l * NEXP;
    float* imp = impA + l * NEXP;

    int gw = (blockIdx.x * blockDim.x + threadIdx.x) >> 5;
    int lane = threadIdx.x & 31;
    if (gw >= NTOK) return;
    const float* xr = embed + (size_t)gw * DMODEL;
    float l0 = 0, l1 = 0, l2 = 0, l3 = 0;
    for (int d = lane; d < DMODEL; d += 32) {
        float v = xr[d];
        const float* rr = R + d * 4;
        l0 += v * rr[0]; l1 += v * rr[1]; l2 += v * rr[2]; l3 += v * rr[3];
    }
    for (int off = 16; off; off >>= 1) {
        l0 += __shfl_xor_sync(0xffffffffu, l0, off);
        l1 += __shfl_xor_sync(0xffffffffu, l1, off);
        l2 += __shfl_xor_sync(0xffffffffu, l2, off);
        l3 += __shfl_xor_sync(0xffffffffu, l3, off);
    }
    if (lane == 0) {
        float mx = fmaxf(fmaxf(l0, l1), fmaxf(l2, l3));
        float e0 = __expf(l0 - mx), e1 = __expf(l1 - mx);
        float e2 = __expf(l2 - mx), e3 = __expf(l3 - mx);
        float inv = 1.f / (e0 + e1 + e2 + e3);
        float s0 = e0 * inv, s1 = e1 * inv, s2 = e2 * inv, s3 = e3 * inv;
        int em = 0; float gm = s0;
        if (s1 > gm) { gm = s1; em = 1; }
        if (s2 > gm) { gm = s2; em = 2; }
        if (s3 > gm) { gm = s3; em = 3; }
        int b = gw >> 9, t = gw & 511;
        if (t < seqlen[b]) {
            atomicAdd(&imp[0], s0); atomicAdd(&imp[1], s1);
            atomicAdd(&imp[2], s2); atomicAdd(&imp[3], s3);
        }
        gtok[gw] = gm;
        int slot = atomicAdd(&cnt[em], 1);
        lists[em * NTOK + slot] = gw;
    }
}

// ---------------- FSMN (+optional PE, emits split(cur)) ----------------
__global__ void fsmn_kernel(const float* __restrict__ P, const float* __restrict__ fb,
                            const float* __restrict__ fa, const float* __restrict__ skipin,
                            float* __restrict__ outp, int doPE)
{
    int idx = blockIdx.x * 256 + threadIdx.x;
    if (idx >= NTOK * DMODEL) return;
    int d = idx & 511;
    int t = (idx >> 9) & 511;
    float v = P[idx];
    #pragma unroll
    for (int k = 0; k < 4; k++) {
        int off = (k + 1) * 2;
        if (t - off >= 0) v += fb[k * DMODEL + d] * P[idx - off * DMODEL];
    }
    if (t + 1 < TLEN) v += fa[d] * P[idx + DMODEL];
    if (skipin) v += skipin[idx];
    if (doPE) {
        int i = d >> 1;
        float div = __expf(-(float)(2 * i) * (9.2103403719761836f / 512.f));
        float a = (float)t * div;
        v += (d & 1) ? cosf(a) : sinf(a);
    }
    outp[idx] = v;
    __nv_bfloat16 h = __float2bfloat16(v);
    g_ahi[idx] = h;
    g_alo[idx] = __float2bfloat16(v - __bfloat162float(h));
}

// ---------------- memory KV rows ----------------
__global__ void memrows_kernel(const float* __restrict__ mk, const float* __restrict__ mv)
{
    int idx = blockIdx.x * 256 + threadIdx.x;
    if (idx >= BATCH * MMEM * DMODEL) return;
    int d = idx & 511;
    int r = idx >> 9;
    int m = r & 63;
    int b = r >> 6;
    size_t krow = (size_t)(NTOK + b * SFULL + TLEN + m);
    size_t vrow = krow + BSF;
    float kv = mk[m * DMODEL + d];
    float vv = mv[m * DMODEL + d];
    __nv_bfloat16 hk = __float2bfloat16(kv);
    g_qkvh[krow * DMODEL + d] = hk;
    g_qkvl[krow * DMODEL + d] = __float2bfloat16(kv - __bfloat162float(hk));
    __nv_bfloat16 hv = __float2bfloat16(vv);
    g_qkvh[vrow * DMODEL + d] = hv;
    g_qkvl[vrow * DMODEL + d] = __float2bfloat16(vv - __bfloat162float(hv));
}

// ---------------- tensor-core flash attention (skips fully-masked tiles) ----------------
#define AT_PITCH 72
#define AT_QH 0
#define AT_QL (128*AT_PITCH)
#define AT_KH (2*128*AT_PITCH)
#define AT_KL (AT_KH + 64*AT_PITCH)
#define AT_VH (AT_KL + 64*AT_PITCH)
#define AT_VL (AT_VH + 64*AT_PITCH)
#define ATTN_SMEM ((AT_VL + 64*AT_PITCH) * 2)
__global__ __launch_bounds__(256, 1)
void attn_mma(const __nv_bfloat16* __restrict__ qh, const __nv_bfloat16* __restrict__ ql,
              const __nv_bfloat16* __restrict__ kh, const __nv_bfloat16* __restrict__ kl,
              const __nv_bfloat16* __restrict__ vh, const __nv_bfloat16* __restrict__ vl,
              const int* __restrict__ seqlen,
              __nv_bfloat16* __restrict__ Ohi, __nv_bfloat16* __restrict__ Olo)
{
    extern __shared__ __nv_bfloat16 sb[];
    int q0 = blockIdx.x * 128, h = blockIdx.y, b = blockIdx.z;
    int tid = threadIdx.x, wid = tid >> 5, lane = tid & 31;
    int slen = seqlen[b];
    int l8 = lane & 7, mat = lane >> 3, g = lane >> 2, t2 = (lane & 3) * 2;
    int mrow = wid * 16;

    #pragma unroll
    for (int i = 0; i < 4; i++) {
        int u = i * 256 + tid;
        int r = u >> 3, c8 = u & 7;
        size_t src = ((size_t)(b * TLEN + q0 + r)) * DMODEL + h * DH + c8 * 8;
        *(uint4*)&sb[AT_QH + r * AT_PITCH + c8 * 8] = *(const uint4*)(qh + src);
        *(uint4*)&sb[AT_QL + r * AT_PITCH + c8 * 8] = *(const uint4*)(ql + src);
    }

    uint32_t QhB = s2u(sb + AT_QH), QlB = s2u(sb + AT_QL);
    uint32_t KhB = s2u(sb + AT_KH), KlB = s2u(sb + AT_KL);
    uint32_t VhB = s2u(sb + AT_VH), VlB = s2u(sb + AT_VL);

    float o[8][4] = {};
    float m0 = -1e30f, m1 = -1e30f, l0 = 0.f, l1 = 0.f;

    for (int s0 = 0; s0 < SFULL; s0 += 64) {
        if (s0 >= slen && s0 + 64 <= TLEN) continue;
        __syncthreads();
        #pragma unroll
        for (int i = 0; i < 2; i++) {
            int u = i * 256 + tid;
            int r = u >> 3, c8 = u & 7;
            size_t src = ((size_t)(b * SFULL + s0 + r)) * DMODEL + h * DH + c8 * 8;
            uint32_t dst = r * AT_PITCH + c8 * 8;
            *(uint4*)&sb[AT_KH + dst] = *(const uint4*)(kh + src);
            *(uint4*)&sb[AT_KL + dst] = *(const uint4*)(kl + src);
            *(uint4*)&sb[AT_VH + dst] = *(const uint4*)(vh + src);
            *(uint4*)&sb[AT_VL + dst] = *(const uint4*)(vl + src);
        }
        __syncthreads();

        float sc[8][4] = {};
        #pragma unroll
        for (int pass = 0; pass < 3; pass++) {
            uint32_t aB = (pass == 2) ? QlB : QhB;
            uint32_t bB = (pass == 1) ? KlB : KhB;
            #pragma unroll
            for (int kc = 0; kc < 4; kc++) {
                uint32_t af[4];
                ldsm4(af, aB + (uint32_t)((mrow + (mat & 1) * 8 + l8) * AT_PITCH
                                          + kc * 16 + (mat >> 1) * 8) * 2);
                #pragma unroll
                for (int nf = 0; nf < 8; nf++) {
                    uint32_t bf2[2];
                    ldsm2(bf2, bB + (uint32_t)((nf * 8 + l8) * AT_PITCH
                                               + kc * 16 + ((lane >> 3) & 1) * 8) * 2);
                    mma_bf16(sc[nf], af, bf2);
                }
            }
        }

        float rm0 = -1e30f, rm1 = -1e30f;
        #pragma unroll
        for (int nf = 0; nf < 8; nf++) {
            #pragma unroll
            for (int j = 0; j < 4; j++) {
                int sg = s0 + nf * 8 + t2 + (j & 1);
                float v = sc[nf][j] * 0.125f;
                sc[nf][j] = (sg >= slen && sg < TLEN) ? -1e9f : v;
            }
            rm0 = fmaxf(rm0, fmaxf(sc[nf][0], sc[nf][1]));
            rm1 = fmaxf(rm1, fmaxf(sc[nf][2], sc[nf][3]));
        }
        rm0 = fmaxf(rm0, __shfl_xor_sync(0xffffffffu, rm0, 1));
        rm0 = fmaxf(rm0, __shfl_xor_sync(0xffffffffu, rm0, 2));
        rm1 = fmaxf(rm1, __shfl_xor_sync(0xffffffffu, rm1, 1));
        rm1 = fmaxf(rm1, __shfl_xor_sync(0xffffffffu, rm1, 2));
        float mn0 = fmaxf(m0, rm0), mn1 = fmaxf(m1, rm1);
        float e0 = __expf(m0 - mn0), e1 = __expf(m1 - mn1);
        float rs0 = 0.f, rs1 = 0.f;
        #pragma unroll
        for (int nf = 0; nf < 8; nf++) {
            sc[nf][0] = __expf(sc[nf][0] - mn0); rs0 += sc[nf][0];
            sc[nf][1] = __expf(sc[nf][1] - mn0); rs0 += sc[nf][1];
            sc[nf][2] = __expf(sc[nf][2] - mn1); rs1 += sc[nf][2];
            sc[nf][3] = __expf(sc[nf][3] - mn1); rs1 += sc[nf][3];
        }
        rs0 += __shfl_xor_sync(0xffffffffu, rs0, 1);
        rs0 += __shfl_xor_sync(0xffffffffu, rs0, 2);
        rs1 += __shfl_xor_sync(0xffffffffu, rs1, 1);
        rs1 += __shfl_xor_sync(0xffffffffu, rs1, 2);
        l0 = l0 * e0 + rs0; l1 = l1 * e1 + rs1;
        m0 = mn0; m1 = mn1;
        #pragma unroll
        for (int nf = 0; nf < 8; nf++) {
            o[nf][0] *= e0; o[nf][1] *= e0; o[nf][2] *= e1; o[nf][3] *= e1;
        }

        uint32_t phi[4][4], plo[4][4];
        #pragma unroll
        for (int kc = 0; kc < 4; kc++) {
            float* A = sc[2 * kc];
            float* B = sc[2 * kc + 1];
            phi[kc][0] = packbf(A[0], A[1]); phi[kc][1] = packbf(A[2], A[3]);
            phi[kc][2] = packbf(B[0], B[1]); phi[kc][3] = packbf(B[2], B[3]);
            plo[kc][0] = packbf(bfres(A[0]), bfres(A[1]));
            plo[kc][1] = packbf(bfres(A[2]), bfres(A[3]));
            plo[kc][2] = packbf(bfres(B[0]), bfres(B[1]));
            plo[kc][3] = packbf(bfres(B[2]), bfres(B[3]));
        }

        #pragma unroll
        for (int pass = 0; pass < 3; pass++) {
            uint32_t vB = (pass == 1) ? VlB : VhB;
            #pragma unroll
            for (int kc = 0; kc < 4; kc++) {
                const uint32_t* pf = (pass == 2) ? plo[kc] : phi[kc];
                #pragma unroll
                for (int nf = 0; nf < 8; nf++) {
                    uint32_t bf2[2];
                    ldsm2t(bf2, vB + (uint32_t)((kc * 16 + ((lane >> 3) & 1) * 8 + l8) * AT_PITCH
                                                + nf * 8) * 2);
                    mma_bf16(o[nf], pf, bf2);
                }
            }
        }
    }

    float inv0 = 1.f / l0, inv1 = 1.f / l1;
    int r0 = q0 + mrow + g;
    #pragma unroll
    for (int nf = 0; nf < 8; nf++) {
        int cc = h * DH + nf * 8 + t2;
        size_t i0 = ((size_t)(b * TLEN + r0)) * DMODEL + cc;
        size_t i1 = ((size_t)(b * TLEN + r0 + 8)) * DMODEL + cc;
        float v0 = o[nf][0] * inv0, v1 = o[nf][1] * inv0;
        float w0 = o[nf][2] * inv1, w1 = o[nf][3] * inv1;
        *(uint32_t*)(Ohi + i0) = packbf(v0, v1);
        *(uint32_t*)(Olo + i0) = packbf(bfres(v0), bfres(v1));
        *(uint32_t*)(Ohi + i1) = packbf(w0, w1);
        *(uint32_t*)(Olo + i1) = packbf(bfres(w0), bfres(w1));
    }
}

// ---------------- layernorm (emits split(cur)) ----------------
__global__ void ln_kernel(const float* __restrict__ X, float* __restrict__ Y,
                          const float* __restrict__ gw, const float* __restrict__ bw)
{
    __shared__ float red[128];
    int row = blockIdx.x, tid = threadIdx.x;
    const float* xr = X + (size_t)row * DMODEL;
    float v[4]; float s = 0.f;
    #pragma unroll
    for (int i = 0; i < 4; i++) { v[i] = xr[tid + 128 * i]; s += v[i]; }
    red[tid] = s; __syncthreads();
    for (int off = 64; off > 0; off >>= 1) {
        if (tid < off) red[tid] += red[tid + off];
        __syncthreads();
    }
    float mu = red[0] * (1.f / 512.f);
    __syncthreads();
    float s2 = 0.f;
    #pragma unroll
    for (int i = 0; i < 4; i++) { float d = v[i] - mu; s2 += d * d; }
    red[tid] = s2; __syncthreads();
    for (int off = 64; off > 0; off >>= 1) {
        if (tid < off) red[tid] += red[tid + off];
        __syncthreads();
    }
    float inv = rsqrtf(red[0] * (1.f / 512.f) + 1e-5f);
    #pragma unroll
    for (int i = 0; i < 4; i++) {
        int c = tid + 128 * i;
        float y = (v[i] - mu) * inv * gw[c] + bw[c];
        size_t idx = (size_t)row * DMODEL + c;
        Y[idx] = y;
        __nv_bfloat16 h = __float2bfloat16(y);
        g_ahi[idx] = h;
        g_alo[idx] = __float2bfloat16(y - __bfloat162float(h));
    }
}

// ---------------- aux ----------------
__global__ void aux_kernel(float* __restrict__ dst)
{
    float tot = 0.f;
    for (int l = 0; l < NLAYER; l++) {
        float m = 0.f;
        for (int e = 0; e < NEXP; e++) m += g_imp[l * 4 + e];
        m *= 0.25f;
        float var = 0.f;
        for (int e = 0; e < NEXP; e++) { float d = g_imp[l * 4 + e] - m; var += d * d; }
        var *= 0.25f;
        tot += var / (m * m + 1e-9f);
    }
    dst[0] = tot;
}

// ---------------- launcher ----------------
extern "C" void kernel_launch(void* const* d_in, const int* in_sizes, int n_in,
                              void* d_out, int out_size)
{
    const float* x         = (const float*)d_in[0];
    const int*   seq       = (const int*)  d_in[1];
    const float* emb_w1    = (const float*)d_in[2];
    const float* emb_b1    = (const float*)d_in[3];
    const float* emb_w2    = (const float*)d_in[4];
    const float* emb_wo    = (const float*)d_in[5];
    const float* f0_w1     = (const float*)d_in[6];
    const float* f0_b1     = (const float*)d_in[7];
    const float* f0_w2     = (const float*)d_in[8];
    const float* f0_router = (const float*)d_in[9];
    const float* f0_fb     = (const float*)d_in[10];
    const float* f0_fa     = (const float*)d_in[11];
    const float* f_w1      = (const float*)d_in[12];
    const float* f_b1      = (const float*)d_in[13];
    const float* f_w2      = (const float*)d_in[14];
    const float* f_router  = (const float*)d_in[15];
    const float* f_fb      = (const float*)d_in[16];
    const float* f_fa      = (const float*)d_in[17];
    const float* wq        = (const float*)d_in[18];
    const float* wk        = (const float*)d_in[19];
    const float* wv        = (const float*)d_in[20];
    const float* wvo       = (const float*)d_in[21];
    const float* mk        = (const float*)d_in[22];
    const float* mv        = (const float*)d_in[23];
    const float* lng       = (const float*)d_in[24];
    const float* lnb       = (const float*)d_in[25];
    const float* out_w     = (const float*)d_in[26];
    const float* out_b     = (const float*)d_in[27];
    float* out = (float*)d_out;

    float *embed, *cur, *p, *tmp, *gtok, *imp;
    int *cnt, *lists, *maps;
    __nv_bfloat16 *whi, *wlo, *ahi, *alo, *bhi, *blo, *ehi, *elo, *xhi, *xlo, *qkvh, *qkvl;
    cudaGetSymbolAddress((void**)&embed, g_embed);
    cudaGetSymbolAddress((void**)&cur,   g_cur);
    cudaGetSymbolAddress((void**)&p,     g_p);
    cudaGetSymbolAddress((void**)&tmp,   g_tmp);
    cudaGetSymbolAddress((void**)&gtok,  g_gtok);
    cudaGetSymbolAddress((void**)&imp,   g_imp);
    cudaGetSymbolAddress((void**)&cnt,   g_cnt);
    cudaGetSymbolAddress((void**)&lists, g_lists);
    cudaGetSymbolAddress((void**)&maps,  g_maps);
    cudaGetSymbolAddress((void**)&whi,   g_whi);
    cudaGetSymbolAddress((void**)&wlo,   g_wlo);
    cudaGetSymbolAddress((void**)&ahi,   g_ahi);
    cudaGetSymbolAddress((void**)&alo,   g_alo);
    cudaGetSymbolAddress((void**)&bhi,   g_bhi);
    cudaGetSymbolAddress((void**)&blo,   g_blo);
    cudaGetSymbolAddress((void**)&ehi,   g_ehi);
    cudaGetSymbolAddress((void**)&elo,   g_elo);
    cudaGetSymbolAddress((void**)&xhi,   g_xhi);
    cudaGetSymbolAddress((void**)&xlo,   g_xlo);
    cudaGetSymbolAddress((void**)&qkvh,  g_qkvh);
    cudaGetSymbolAddress((void**)&qkvl,  g_qkvl);

    cudaFuncSetAttribute(attn_mma, cudaFuncAttributeMaxDynamicSharedMemorySize, ATTN_SMEM);
    cudaFuncSetAttribute(tgemm<128>, cudaFuncAttributeMaxDynamicSharedMemorySize, TG_SMEM128);
    cudaFuncSetAttribute(tgemm<64>,  cudaFuncAttributeMaxDynamicSharedMemorySize, TG_SMEM64);

    cudaStream_t s1;
    cudaStreamCreate(&s1);
    cudaEvent_t evF, evJ, evE0, evE1;
    cudaEventCreateWithFlags(&evF, cudaEventDisableTiming);
    cudaEventCreateWithFlags(&evJ, cudaEventDisableTiming);
    cudaEventCreateWithFlags(&evE0, cudaEventDisableTiming);
    cudaEventCreateWithFlags(&evE1, cudaEventDisableTiming);

    auto TG = [&](unsigned woff, const __nv_bfloat16* Ah, const __nv_bfloat16* Al,
                  float* C, __nv_bfloat16* Ch, __nv_bfloat16* Cl,
                  int M, int N, int K,
                  const float* bias, int relu, const int* ga, const int* sc,
                  const float* rs, const float* res, const int* Md,
                  int E = 1, int sB = 0, int sBias = 0, int sList = 0,
                  cudaStream_t st = 0) {
        dim3 grid(N / 128, (M + 127) / 128, E);
        tgemm<128><<<grid, 256, TG_SMEM128, st>>>(Ah, Al, whi + woff, wlo + woff, C, Ch, Cl,
                                                  N, K, M, bias, relu, ga, sc, rs, res, Md,
                                                  sB, sBias, sList);
    };
    auto TG64 = [&](unsigned woff, const __nv_bfloat16* Ah, const __nv_bfloat16* Al,
                    float* C, __nv_bfloat16* Ch, __nv_bfloat16* Cl,
                    int M, int N, int K,
                    const float* bias, int relu, const int* ga, const int* sc,
                    const float* rs, const float* res, const int* Md,
                    int E = 1, int sB = 0, int sBias = 0, int sList = 0,
                    cudaStream_t st = 0) {
        dim3 grid(N / 128, (M + 63) / 64, E);
        tgemm<64><<<grid, 256, TG_SMEM64, st>>>(Ah, Al, whi + woff, wlo + woff, C, Ch, Cl,
                                                N, K, M, bias, relu, ga, sc, rs, res, Md,
                                                sB, sBias, sList);
    };
    auto WS = [&](const float* W, unsigned off, int nelem, cudaStream_t st) {
        wsplit<<<(nelem / 4 + 255) / 256, 256, 0, st>>>(W, whi + off, wlo + off, nelem / 4);
    };

    init_kernel<<<1, 1024>>>();

    // main-stream prep
    xsplit<<<(NTOK * KPAD + 255) / 256, 256>>>(x);
    wsplit_pad<<<(KPAD * 1024 / 4 + 255) / 256, 256>>>(emb_w1, whi + OFF_EMBW1,
                                                       wlo + OFF_EMBW1, 1024, KPAD * 1024 / 4);
    wsplit_pad<<<(NEXP * KPAD * 1024 / 4 + 255) / 256, 256>>>(f0_w1, whi + OFF_F0W1,
                                                              wlo + OFF_F0W1, 1024,
                                                              NEXP * KPAD * 1024 / 4);
    WS(emb_w2, OFF_EMBW2, 1024 * 512, 0);
    WS(f0_w2,  OFF_F0W2, 4 * 1024 * 512, 0);

    // side-stream weight splits
    cudaEventRecord(evF, 0);
    cudaStreamWaitEvent(s1, evF, 0);
    WS(emb_wo, OFF_EMBWO, 512 * 4096, s1);
    WS(f_w1, OFF_FW1, 28 * 512 * 1024, s1);
    WS(f_w2, OFF_FW2, 28 * 1024 * 512, s1);
    for (int bi = 0; bi < 2; bi++) {
        WS(wq + (size_t)bi * MAT_SZ, OFF_QKV + bi * 3u * MAT_SZ + 0u * MAT_SZ, MAT_SZ, s1);
        WS(wk + (size_t)bi * MAT_SZ, OFF_QKV + bi * 3u * MAT_SZ + 1u * MAT_SZ, MAT_SZ, s1);
        WS(wv + (size_t)bi * MAT_SZ, OFF_QKV + bi * 3u * MAT_SZ + 2u * MAT_SZ, MAT_SZ, s1);
    }
    WS(wvo,   OFF_WO, 2 * 512 * 512, s1);
    WS(out_w, OFF_OUTW, 512 * 4096, s1);
    cudaEventRecord(evJ, s1);

    // embed sub-network (64-tiles: better chip fill at these grid sizes)
    TG64(OFF_EMBW1, xhi, xlo, 0, bhi, blo, NTOK, DHID, KPAD, emb_b1, 1, 0, 0, 0, 0, 0);
    TG64(OFF_EMBW2, bhi, blo, embed, ehi, elo, NTOK, DMODEL, DHID, 0, 0, 0, 0, 0, 0, 0);
    cudaEventRecord(evE0, 0);

    // embed_out on side stream (512 CTAs -> keep 128-tile)
    cudaStreamWaitEvent(s1, evE0, 0);
    TG(OFF_EMBWO, ehi, elo, out + (size_t)NTOK * DOUT, 0, 0, NTOK, DOUT, DMODEL,
       0, 0, 0, 0, 0, 0, 0, 1, 0, 0, 0, s1);
    cudaEventRecord(evE1, s1);

    router_all<<<dim3(NTOK / 8, NLAYER), 256>>>(embed, f0_router, f_router, seq,
                                                gtok, lists, cnt, imp);

    for (int l = 0; l < NLAYER; l++) {
        int* lst = lists + (size_t)l * NEXP * NTOK;
        float* gt = gtok + (size_t)l * NTOK;
        int* ct = cnt + l * 4;

        if (l == 1) cudaStreamWaitEvent(0, evJ, 0);

        if (l == 0) {
            TG64(OFF_F0W1, xhi, xlo, 0, bhi, blo, NTOK, DHID, KPAD,
                 f0_b1, 1, lst, lst, 0, 0, ct, NEXP, KPAD * DHID, DHID, NTOK);
            TG64(OFF_F0W2, bhi, blo, p, 0, 0, NTOK, DMODEL, DHID, 0, 0, lst, lst,
                 gt, 0, ct, NEXP, DMODEL * DHID, 0, NTOK);
        } else {
            TG64(OFF_FW1 + (unsigned)(l - 1) * 4u * DMODEL * DHID, ahi, alo,
                 0, bhi, blo, NTOK, DHID, DMODEL,
                 f_b1 + (size_t)(l - 1) * NEXP * DHID, 1, lst, lst, 0, 0, ct,
                 NEXP, DMODEL * DHID, DHID, NTOK);
            TG64(OFF_FW2 + (unsigned)(l - 1) * 4u * DHID * DMODEL, bhi, blo,
                 p, 0, 0, NTOK, DMODEL, DHID,
                 0, 0, lst, lst, gt, 0, ct,
                 NEXP, DHID * DMODEL, 0, NTOK);
        }
        const float* fbL = (l == 0) ? f0_fb : f_fb + (size_t)(l - 1) * 4 * DMODEL;
        const float* faL = (l == 0) ? f0_fa : f_fa + (size_t)(l - 1) * DMODEL;
        fsmn_kernel<<<NTOK * DMODEL / 256, 256>>>(p, fbL, faL,
                                                  (l == 0) ? (const float*)0 : cur, cur,
                                                  l == 3 ? 1 : 0);

        if (l == 3 || l == 7) {
            int bi = l / 4;
            TG64(OFF_QKV + (unsigned)bi * 3u * MAT_SZ, ahi, alo, 0, qkvh, qkvl,
                 NTOK, DMODEL, DMODEL, 0, 0, 0, maps, 0, 0, 0, 3, MAT_SZ, 0, NTOK);
            memrows_kernel<<<BATCH * MMEM * DMODEL / 256, 256>>>(
                mk + (size_t)bi * MMEM * DMODEL, mv + (size_t)bi * MMEM * DMODEL);
            attn_mma<<<dim3(TLEN / 128, NHEAD, BATCH), 256, ATTN_SMEM>>>(
                qkvh, qkvl,
                qkvh + (size_t)NTOK * DMODEL, qkvl + (size_t)NTOK * DMODEL,
                qkvh + (size_t)(NTOK + BSF) * DMODEL, qkvl + (size_t)(NTOK + BSF) * DMODEL,
                seq, bhi, blo);
            TG64(OFF_WO + (unsigned)bi * MAT_SZ, bhi, blo, tmp, 0, 0,
                 NTOK, DMODEL, DMODEL, 0, 0, 0, 0, 0, cur, 0);
            ln_kernel<<<NTOK, 128>>>(tmp, cur, lng + bi * DMODEL, lnb + bi * DMODEL);
        }
    }

    TG(OFF_OUTW, ahi, alo, out, 0, 0, NTOK, DOUT, DMODEL, out_b, 0, 0, 0, 0, 0, 0);
    cudaStreamWaitEvent(0, evE1, 0);
    aux_kernel<<<1, 1>>>(out + 2 * (size_t)NTOK * DOUT);
}

// round 16
// speedup vs baseline: 1.4670x; 1.0047x over previous
#include <cuda_runtime.h>
#include <cuda_bf16.h>
#include <math.h>
#include <stdint.h>

// ---------------- problem constants ----------------
#define BATCH 4
#define TLEN  512
#define NTOK  (BATCH*TLEN)
#define DIN   80
#define KPAD  96
#define DOUT  4096
#define DMODEL 512
#define DHID  1024
#define NEXP  4
#define NLAYER 8
#define NHEAD 8
#define DH    64
#define MMEM  64
#define SFULL (TLEN+MMEM)
#define BSF   (BATCH*SFULL)
#define QKV_ROWS (NTOK + 2*BSF)

// ---------------- device scratch ----------------
__device__ float g_embed[NTOK*DMODEL];
__device__ float g_cur[NTOK*DMODEL];
__device__ float g_p[NTOK*DMODEL];
__device__ float g_tmp[NTOK*DMODEL];
__device__ float g_gtok[NLAYER*NTOK];
__device__ float g_imp[NLAYER*NEXP];
__device__ int   g_cnt[NLAYER*NEXP];
__device__ int   g_lists[NLAYER*NEXP*NTOK];
__device__ int   g_maps[3*NTOK];

#define WPOOL (40u*1024u*1024u)
__device__ __nv_bfloat16 g_whi[WPOOL];
__device__ __nv_bfloat16 g_wlo[WPOOL];
__device__ __nv_bfloat16 g_ahi[NTOK*DMODEL];
__device__ __nv_bfloat16 g_alo[NTOK*DMODEL];
__device__ __nv_bfloat16 g_bhi[NTOK*DHID];
__device__ __nv_bfloat16 g_blo[NTOK*DHID];
__device__ __nv_bfloat16 g_ehi[NTOK*DMODEL];
__device__ __nv_bfloat16 g_elo[NTOK*DMODEL];
__device__ __nv_bfloat16 g_xhi[NTOK*KPAD];
__device__ __nv_bfloat16 g_xlo[NTOK*KPAD];
__device__ __nv_bfloat16 g_qkvh[QKV_ROWS*DMODEL];
__device__ __nv_bfloat16 g_qkvl[QKV_ROWS*DMODEL];

#define OFF_EMBW2 0u
#define OFF_EMBWO (OFF_EMBW2 + 512u*1024u)
#define OFF_F0W2  (OFF_EMBWO + 4096u*512u)
#define OFF_FW1   (OFF_F0W2 + 4u*512u*1024u)
#define OFF_FW2   (OFF_FW1 + 28u*1024u*512u)
#define OFF_QKV   (OFF_FW2 + 28u*512u*1024u)
#define OFF_WO    (OFF_QKV + 6u*512u*512u)
#define OFF_OUTW  (OFF_WO + 2u*512u*512u)
#define OFF_EMBW1 (OFF_OUTW + 512u*4096u)
#define OFF_F0W1  (OFF_EMBW1 + 96u*1024u)
#define MAT_SZ    (512u*512u)

// ---------------- helpers ----------------
__device__ __forceinline__ uint32_t s2u(const void* p) {
    uint32_t a;
    asm("{ .reg .u64 t; cvta.to.shared.u64 t, %1; cvt.u32.u64 %0, t; }" : "=r"(a) : "l"(p));
    return a;
}
__device__ __forceinline__ void ldsm4(uint32_t* r, uint32_t addr) {
    asm volatile("ldmatrix.sync.aligned.m8n8.x4.shared.b16 {%0,%1,%2,%3}, [%4];"
        : "=r"(r[0]), "=r"(r[1]), "=r"(r[2]), "=r"(r[3]) : "r"(addr));
}
__device__ __forceinline__ void ldsm2(uint32_t* r, uint32_t addr) {
    asm volatile("ldmatrix.sync.aligned.m8n8.x2.shared.b16 {%0,%1}, [%2];"
        : "=r"(r[0]), "=r"(r[1]) : "r"(addr));
}
__device__ __forceinline__ void ldsm2t(uint32_t* r, uint32_t addr) {
    asm volatile("ldmatrix.sync.aligned.m8n8.x2.trans.shared.b16 {%0,%1}, [%2];"
        : "=r"(r[0]), "=r"(r[1]) : "r"(addr));
}
__device__ __forceinline__ void mma_bf16(float* c, const uint32_t* a, const uint32_t* b) {
    asm volatile("mma.sync.aligned.m16n8k16.row.col.f32.bf16.bf16.f32 "
        "{%0,%1,%2,%3}, {%4,%5,%6,%7}, {%8,%9}, {%0,%1,%2,%3};"
        : "+f"(c[0]), "+f"(c[1]), "+f"(c[2]), "+f"(c[3])
        : "r"(a[0]), "r"(a[1]), "r"(a[2]), "r"(a[3]), "r"(b[0]), "r"(b[1]));
}
__device__ __forceinline__ uint32_t packbf(float a, float b) {
    __nv_bfloat162 h = __floats2bfloat162_rn(a, b);
    return *(uint32_t*)&h;
}
__device__ __forceinline__ float bfres(float x) {
    return x - __bfloat162float(__float2bfloat16(x));
}
#define CPA(dst, src, sz) asm volatile("cp.async.ca.shared.global [%0], [%1], 16, %2;" \
    :: "r"(dst), "l"(src), "r"(sz))
#define CPC() asm volatile("cp.async.commit_group;" ::: "memory")
#define CPW() asm volatile("cp.async.wait_group 0;" ::: "memory")

// ---------------- init ----------------
__global__ void init_kernel() {
    int t = threadIdx.x;
    if (t < NLAYER*NEXP) { g_cnt[t] = 0; g_imp[t] = 0.f; }
    for (int i = t; i < NTOK; i += blockDim.x) {
        int kv = (i >> 9) * SFULL + (i & 511);
        g_maps[i] = i;
        g_maps[NTOK + i] = NTOK + kv;
        g_maps[2 * NTOK + i] = NTOK + BSF + kv;
    }
}

// ---------------- streaming weight split ----------------
__global__ void wsplit(const float* __restrict__ W, __nv_bfloat16* __restrict__ hi,
                       __nv_bfloat16* __restrict__ lo, int n4)
{
    int i = blockIdx.x * 256 + threadIdx.x;
    if (i >= n4) return;
    float4 v = ((const float4*)W)[i];
    __nv_bfloat162 h01 = __floats2bfloat162_rn(v.x, v.y);
    __nv_bfloat162 h23 = __floats2bfloat162_rn(v.z, v.w);
    __nv_bfloat162 l01 = __floats2bfloat162_rn(v.x - __bfloat162float(h01.x),
                                               v.y - __bfloat162float(h01.y));
    __nv_bfloat162 l23 = __floats2bfloat162_rn(v.z - __bfloat162float(h23.x),
                                               v.w - __bfloat162float(h23.y));
    uint2 hw, lw;
    hw.x = *(uint32_t*)&h01; hw.y = *(uint32_t*)&h23;
    lw.x = *(uint32_t*)&l01; lw.y = *(uint32_t*)&l23;
    *(uint2*)(hi + (size_t)i * 4) = hw;
    *(uint2*)(lo + (size_t)i * 4) = lw;
}

// ---------------- weight split with K pad 80->96 ----------------
__global__ void wsplit_pad(const float* __restrict__ W, __nv_bfloat16* __restrict__ hi,
                           __nv_bfloat16* __restrict__ lo, int N, int total4)
{
    int i = blockIdx.x * 256 + threadIdx.x;
    if (i >= total4) return;
    int elem = i * 4;
    int z = elem / (KPAD * N);
    int rem = elem - z * KPAD * N;
    int k = rem / N, n = rem - k * N;
    float4 v = make_float4(0.f, 0.f, 0.f, 0.f);
    if (k < DIN) v = *(const float4*)(W + (size_t)z * DIN * N + (size_t)k * N + n);
    __nv_bfloat162 h01 = __floats2bfloat162_rn(v.x, v.y);
    __nv_bfloat162 h23 = __floats2bfloat162_rn(v.z, v.w);
    __nv_bfloat162 l01 = __floats2bfloat162_rn(v.x - __bfloat162float(h01.x),
                                               v.y - __bfloat162float(h01.y));
    __nv_bfloat162 l23 = __floats2bfloat162_rn(v.z - __bfloat162float(h23.x),
                                               v.w - __bfloat162float(h23.y));
    uint2 hw, lw;
    hw.x = *(uint32_t*)&h01; hw.y = *(uint32_t*)&h23;
    lw.x = *(uint32_t*)&l01; lw.y = *(uint32_t*)&l23;
    *(uint2*)(hi + (size_t)elem) = hw;
    *(uint2*)(lo + (size_t)elem) = lw;
}

// ---------------- x split with pad 80->96 ----------------
__global__ void xsplit(const float* __restrict__ x)
{
    int i = blockIdx.x * 256 + threadIdx.x;
    if (i >= NTOK * KPAD) return;
    int row = i / KPAD, c = i - row * KPAD;
    float v = (c < DIN) ? x[(size_t)row * DIN + c] : 0.f;
    __nv_bfloat16 h = __float2bfloat16(v);
    g_xhi[i] = h;
    g_xlo[i] = __float2bfloat16(v - __bfloat162float(h));
}

// ---------------- bf16 TC GEMM (2-stage cp.async, templated M tile) ----------------
#define KC 32
#define APITCHB 80
#define BPITCHB 272
#define B_TILE (KC*BPITCHB)
#define TG_SMEM128 (2*(2*128*APITCHB + 2*B_TILE))
#define TG_SMEM64  (2*(2*64*APITCHB + 2*B_TILE))
#define TG_SMEM32  (2*(2*32*APITCHB + 2*B_TILE))
template<int MTILE>
__global__ __launch_bounds__(256, 2)
void tgemm(const __nv_bfloat16* __restrict__ Ahi, const __nv_bfloat16* __restrict__ Alo,
           const __nv_bfloat16* __restrict__ Bhi, const __nv_bfloat16* __restrict__ Blo,
           float* __restrict__ C,
           __nv_bfloat16* __restrict__ Chi, __nv_bfloat16* __restrict__ Clo,
           int N, int K, int Mstatic,
           const float* __restrict__ bias, int doRelu,
           const int* __restrict__ gatherA, const int* __restrict__ scatterC,
           const float* __restrict__ rowScale, const float* __restrict__ residual,
           const int* __restrict__ Mdev, int strideB, int strideBias, int strideList)
{
    constexpr int MF = (MTILE >= 64) ? MTILE / 32 : 1;
    constexpr int A_T = MTILE * APITCHB;
    constexpr int STG_T = 2 * A_T + 2 * B_TILE;
    extern __shared__ char smem[];
    int e = blockIdx.z;
    const __nv_bfloat16* Bhz = Bhi + (size_t)e * strideB;
    const __nv_bfloat16* Blz = Blo + (size_t)e * strideB;
    const float* biasz = bias ? bias + (size_t)e * strideBias : (const float*)0;
    const int* gA = gatherA ? gatherA + (size_t)e * strideList : (const int*)0;
    const int* sC = scatterC ? scatterC + (size_t)e * strideList : (const int*)0;
    int Ml = Mdev ? Mdev[e] : Mstatic;
    int row0 = blockIdx.y * MTILE;
    if (row0 >= Ml) return;
    int col0 = blockIdx.x * 128;
    int tid = threadIdx.x, wid = tid >> 5, lane = tid & 31;
    uint32_t sb = s2u(smem);

    int arow[2], lr[2], lu[2];
    bool aok[2];
    #pragma unroll
    for (int i = 0; i < 2; i++) {
        int unit = tid + i * 256;
        aok[i] = (unit < MTILE * 4);
        lr[i] = unit >> 2;
        lu[i] = unit & 3;
        int gr = row0 + lr[i];
        arow[i] = (aok[i] && gr < Ml) ? (gA ? gA[gr] : gr) : -1;
    }

    auto issue = [&](int c, int stage) {
        int k0 = c * KC;
        uint32_t base = sb + stage * STG_T;
        #pragma unroll
        for (int i = 0; i < 2; i++) {
            if (aok[i]) {
                uint32_t offA = (uint32_t)(lr[i] * APITCHB + lu[i] * 16);
                int ar = arow[i] >= 0 ? arow[i] : 0;
                uint32_t asz = arow[i] >= 0 ? 16u : 0u;
                CPA(base + offA, (const char*)(Ahi + (size_t)ar * K + k0 + lu[i] * 8), asz);
                CPA(base + A_T + offA, (const char*)(Alo + (size_t)ar * K + k0 + lu[i] * 8), asz);
            }
            int unit = tid + i * 256;
            int bk = unit >> 4, bc16 = unit & 15;
            uint32_t offB = (uint32_t)(bk * BPITCHB + bc16 * 16);
            const char* bh = (const char*)(Bhz + (size_t)(k0 + bk) * N + col0 + bc16 * 8);
            const char* bl = (const char*)(Blz + (size_t)(k0 + bk) * N + col0 + bc16 * 8);
            CPA(base + 2u * A_T + offB, bh, 16u);
            CPA(base + 2u * A_T + B_TILE + offB, bl, 16u);
        }
    };

    float acc[MF][4][4] = {};
    int wm = wid >> 2, wn = wid & 3;
    int m_base = wm * (MTILE / 2), n_base = wn * 32;
    int l8 = lane & 7, mat = lane >> 3, bsel = (lane >> 3) & 1;

    int nc = K / KC;
    issue(0, 0); CPC();

    for (int c = 0; c < nc; c++) {
        CPW();
        __syncthreads();
        if (c + 1 < nc) { issue(c + 1, (c + 1) & 1); CPC(); }

        uint32_t base = sb + (c & 1) * STG_T;
        uint32_t ahB = base, alB = base + A_T;
        uint32_t bhB = base + 2u * A_T, blB = base + 2u * A_T + B_TILE;
        #pragma unroll
        for (int ks = 0; ks < 2; ks++) {
            int kb = ks * 16;
            uint32_t aoff = (uint32_t)(kb + (mat >> 1) * 8) * 2;
            uint32_t af[MF][4], bfh[4][2], bfl[4][2];
            #pragma unroll
            for (int mf = 0; mf < MF; mf++)
                ldsm4(af[mf], ahB + (uint32_t)(m_base + mf * 16 + (mat & 1) * 8 + l8) * APITCHB + aoff);
            #pragma unroll
            for (int nf = 0; nf < 4; nf++)
                ldsm2t(bfh[nf], bhB + (uint32_t)(kb + bsel * 8 + l8) * BPITCHB
                                    + (uint32_t)(n_base + nf * 8) * 2);
            #pragma unroll
            for (int mf = 0; mf < MF; mf++)
                #pragma unroll
                for (int nf = 0; nf < 4; nf++)
                    mma_bf16(acc[mf][nf], af[mf], bfh[nf]);
            #pragma unroll
            for (int nf = 0; nf < 4; nf++)
                ldsm2t(bfl[nf], blB + (uint32_t)(kb + bsel * 8 + l8) * BPITCHB
                                    + (uint32_t)(n_base + nf * 8) * 2);
            #pragma unroll
            for (int mf = 0; mf < MF; mf++)
                #pragma unroll
                for (int nf = 0; nf < 4; nf++)
                    mma_bf16(acc[mf][nf], af[mf], bfl[nf]);
            #pragma unroll
            for (int mf = 0; mf < MF; mf++)
                ldsm4(af[mf], alB + (uint32_t)(m_base + mf * 16 + (mat & 1) * 8 + l8) * APITCHB + aoff);
            #pragma unroll
            for (int mf = 0; mf < MF; mf++)
                #pragma unroll
                for (int nf = 0; nf < 4; nf++)
                    mma_bf16(acc[mf][nf], af[mf], bfh[nf]);
        }
    }

    int g = lane >> 2, t2 = (lane & 3) * 2;
    #pragma unroll
    for (int mf = 0; mf < MF; mf++) {
        #pragma unroll
        for (int half = 0; half < 2; half++) {
            int r = row0 + m_base + mf * 16 + g + half * 8;
            if (r >= Ml) continue;
            int orow = sC ? sC[r] : r;
            float sc = rowScale ? rowScale[orow] : 1.f;
            size_t rb = (size_t)orow * N;
            #pragma unroll
            for (int nf = 0; nf < 4; nf++) {
                int cc = col0 + n_base + nf * 8 + t2;
                float v0 = acc[mf][nf][half * 2 + 0] * sc;
                float v1 = acc[mf][nf][half * 2 + 1] * sc;
                if (biasz) { v0 += biasz[cc]; v1 += biasz[cc + 1]; }
                if (residual) { v0 += residual[rb + cc]; v1 += residual[rb + cc + 1]; }
                if (doRelu) { v0 = fmaxf(v0, 0.f); v1 = fmaxf(v1, 0.f); }
                if (C) *(float2*)(C + rb + cc) = make_float2(v0, v1);
                if (Chi) {
                    *(uint32_t*)(Chi + rb + cc) = packbf(v0, v1);
                    *(uint32_t*)(Clo + rb + cc) = packbf(bfres(v0), bfres(v1));
                }
            }
        }
    }
}

// ---------------- fused router (all layers) ----------------
__global__ void router_all(const float* __restrict__ embed, const float* __restrict__ f0r,
                           const float* __restrict__ fr, const int* __restrict__ seqlen,
                           float* __restrict__ gtokA, int* __restrict__ listsA,
                           int* __restrict__ cntA, float* __restrict__ impA)
{
    int l = blockIdx.y;
    const float* R = (l == 0) ? f0r : fr + (size_t)(l - 1) * DMODEL * NEXP;
    float* gtok = gtokA + (size_t)l * NTOK;
    int* lists = listsA + (size_t)l * NEXP * NTOK;
    int* cnt = cntA + l * NEXP;
    float* imp = impA + l * NEXP;

    int gw = (blockIdx.x * blockDim.x + threadIdx.x) >> 5;
    int lane = threadIdx.x & 31;
    if (gw >= NTOK) return;
    const float* xr = embed + (size_t)gw * DMODEL;
    float l0 = 0, l1 = 0, l2 = 0, l3 = 0;
    for (int d = lane; d < DMODEL; d += 32) {
        float v = xr[d];
        const float* rr = R + d * 4;
        l0 += v * rr[0]; l1 += v * rr[1]; l2 += v * rr[2]; l3 += v * rr[3];
    }
    for (int off = 16; off; off >>= 1) {
        l0 += __shfl_xor_sync(0xffffffffu, l0, off);
        l1 += __shfl_xor_sync(0xffffffffu, l1, off);
        l2 += __shfl_xor_sync(0xffffffffu, l2, off);
        l3 += __shfl_xor_sync(0xffffffffu, l3, off);
    }
    if (lane == 0) {
        float mx = fmaxf(fmaxf(l0, l1), fmaxf(l2, l3));
        float e0 = __expf(l0 - mx), e1 = __expf(l1 - mx);
        float e2 = __expf(l2 - mx), e3 = __expf(l3 - mx);
        float inv = 1.f / (e0 + e1 + e2 + e3);
        float s0 = e0 * inv, s1 = e1 * inv, s2 = e2 * inv, s3 = e3 * inv;
        int em = 0; float gm = s0;
        if (s1 > gm) { gm = s1; em = 1; }
        if (s2 > gm) { gm = s2; em = 2; }
        if (s3 > gm) { gm = s3; em = 3; }
        int b = gw >> 9, t = gw & 511;
        if (t < seqlen[b]) {
            atomicAdd(&imp[0], s0); atomicAdd(&imp[1], s1);
            atomicAdd(&imp[2], s2); atomicAdd(&imp[3], s3);
        }
        gtok[gw] = gm;
        int slot = atomicAdd(&cnt[em], 1);
        lists[em * NTOK + slot] = gw;
    }
}

// ---------------- FSMN (+optional PE, emits split(cur)) ----------------
__global__ void fsmn_kernel(const float* __restrict__ P, const float* __restrict__ fb,
                            const float* __restrict__ fa, const float* __restrict__ skipin,
                            float* __restrict__ outp, int doPE)
{
    int idx = blockIdx.x * 256 + threadIdx.x;
    if (idx >= NTOK * DMODEL) return;
    int d = idx & 511;
    int t = (idx >> 9) & 511;
    float v = P[idx];
    #pragma unroll
    for (int k = 0; k < 4; k++) {
        int off = (k + 1) * 2;
        if (t - off >= 0) v += fb[k * DMODEL + d] * P[idx - off * DMODEL];
    }
    if (t + 1 < TLEN) v += fa[d] * P[idx + DMODEL];
    if (skipin) v += skipin[idx];
    if (doPE) {
        int i = d >> 1;
        float div = __expf(-(float)(2 * i) * (9.2103403719761836f / 512.f));
        float a = (float)t * div;
        v += (d & 1) ? cosf(a) : sinf(a);
    }
    outp[idx] = v;
    __nv_bfloat16 h = __float2bfloat16(v);
    g_ahi[idx] = h;
    g_alo[idx] = __float2bfloat16(v - __bfloat162float(h));
}

// ---------------- memory KV rows ----------------
__global__ void memrows_kernel(const float* __restrict__ mk, const float* __restrict__ mv)
{
    int idx = blockIdx.x * 256 + threadIdx.x;
    if (idx >= BATCH * MMEM * DMODEL) return;
    int d = idx & 511;
    int r = idx >> 9;
    int m = r & 63;
    int b = r >> 6;
    size_t krow = (size_t)(NTOK + b * SFULL + TLEN + m);
    size_t vrow = krow + BSF;
    float kv = mk[m * DMODEL + d];
    float vv = mv[m * DMODEL + d];
    __nv_bfloat16 hk = __float2bfloat16(kv);
    g_qkvh[krow * DMODEL + d] = hk;
    g_qkvl[krow * DMODEL + d] = __float2bfloat16(kv - __bfloat162float(hk));
    __nv_bfloat16 hv = __float2bfloat16(vv);
    g_qkvh[vrow * DMODEL + d] = hv;
    g_qkvl[vrow * DMODEL + d] = __float2bfloat16(vv - __bfloat162float(hv));
}

// ---------------- tensor-core flash attention (skips fully-masked tiles) ----------------
#define AT_PITCH 72
#define AT_QH 0
#define AT_QL (128*AT_PITCH)
#define AT_KH (2*128*AT_PITCH)
#define AT_KL (AT_KH + 64*AT_PITCH)
#define AT_VH (AT_KL + 64*AT_PITCH)
#define AT_VL (AT_VH + 64*AT_PITCH)
#define ATTN_SMEM ((AT_VL + 64*AT_PITCH) * 2)
__global__ __launch_bounds__(256, 1)
void attn_mma(const __nv_bfloat16* __restrict__ qh, const __nv_bfloat16* __restrict__ ql,
              const __nv_bfloat16* __restrict__ kh, const __nv_bfloat16* __restrict__ kl,
              const __nv_bfloat16* __restrict__ vh, const __nv_bfloat16* __restrict__ vl,
              const int* __restrict__ seqlen,
              __nv_bfloat16* __restrict__ Ohi, __nv_bfloat16* __restrict__ Olo)
{
    extern __shared__ __nv_bfloat16 sb[];
    int q0 = blockIdx.x * 128, h = blockIdx.y, b = blockIdx.z;
    int tid = threadIdx.x, wid = tid >> 5, lane = tid & 31;
    int slen = seqlen[b];
    int l8 = lane & 7, mat = lane >> 3, g = lane >> 2, t2 = (lane & 3) * 2;
    int mrow = wid * 16;

    #pragma unroll
    for (int i = 0; i < 4; i++) {
        int u = i * 256 + tid;
        int r = u >> 3, c8 = u & 7;
        size_t src = ((size_t)(b * TLEN + q0 + r)) * DMODEL + h * DH + c8 * 8;
        *(uint4*)&sb[AT_QH + r * AT_PITCH + c8 * 8] = *(const uint4*)(qh + src);
        *(uint4*)&sb[AT_QL + r * AT_PITCH + c8 * 8] = *(const uint4*)(ql + src);
    }

    uint32_t QhB = s2u(sb + AT_QH), QlB = s2u(sb + AT_QL);
    uint32_t KhB = s2u(sb + AT_KH), KlB = s2u(sb + AT_KL);
    uint32_t VhB = s2u(sb + AT_VH), VlB = s2u(sb + AT_VL);

    float o[8][4] = {};
    float m0 = -1e30f, m1 = -1e30f, l0 = 0.f, l1 = 0.f;

    for (int s0 = 0; s0 < SFULL; s0 += 64) {
        if (s0 >= slen && s0 + 64 <= TLEN) continue;
        __syncthreads();
        #pragma unroll
        for (int i = 0; i < 2; i++) {
            int u = i * 256 + tid;
            int r = u >> 3, c8 = u & 7;
            size_t src = ((size_t)(b * SFULL + s0 + r)) * DMODEL + h * DH + c8 * 8;
            uint32_t dst = r * AT_PITCH + c8 * 8;
            *(uint4*)&sb[AT_KH + dst] = *(const uint4*)(kh + src);
            *(uint4*)&sb[AT_KL + dst] = *(const uint4*)(kl + src);
            *(uint4*)&sb[AT_VH + dst] = *(const uint4*)(vh + src);
            *(uint4*)&sb[AT_VL + dst] = *(const uint4*)(vl + src);
        }
        __syncthreads();

        float sc[8][4] = {};
        #pragma unroll
        for (int pass = 0; pass < 3; pass++) {
            uint32_t aB = (pass == 2) ? QlB : QhB;
            uint32_t bB = (pass == 1) ? KlB : KhB;
            #pragma unroll
            for (int kc = 0; kc < 4; kc++) {
                uint32_t af[4];
                ldsm4(af, aB + (uint32_t)((mrow + (mat & 1) * 8 + l8) * AT_PITCH
                                          + kc * 16 + (mat >> 1) * 8) * 2);
                #pragma unroll
                for (int nf = 0; nf < 8; nf++) {
                    uint32_t bf2[2];
                    ldsm2(bf2, bB + (uint32_t)((nf * 8 + l8) * AT_PITCH
                                               + kc * 16 + ((lane >> 3) & 1) * 8) * 2);
                    mma_bf16(sc[nf], af, bf2);
                }
            }
        }

        float rm0 = -1e30f, rm1 = -1e30f;
        #pragma unroll
        for (int nf = 0; nf < 8; nf++) {
            #pragma unroll
            for (int j = 0; j < 4; j++) {
                int sg = s0 + nf * 8 + t2 + (j & 1);
                float v = sc[nf][j] * 0.125f;
                sc[nf][j] = (sg >= slen && sg < TLEN) ? -1e9f : v;
            }
            rm0 = fmaxf(rm0, fmaxf(sc[nf][0], sc[nf][1]));
            rm1 = fmaxf(rm1, fmaxf(sc[nf][2], sc[nf][3]));
        }
        rm0 = fmaxf(rm0, __shfl_xor_sync(0xffffffffu, rm0, 1));
        rm0 = fmaxf(rm0, __shfl_xor_sync(0xffffffffu, rm0, 2));
        rm1 = fmaxf(rm1, __shfl_xor_sync(0xffffffffu, rm1, 1));
        rm1 = fmaxf(rm1, __shfl_xor_sync(0xffffffffu, rm1, 2));
        float mn0 = fmaxf(m0, rm0), mn1 = fmaxf(m1, rm1);
        float e0 = __expf(m0 - mn0), e1 = __expf(m1 - mn1);
        float rs0 = 0.f, rs1 = 0.f;
        #pragma unroll
        for (int nf = 0; nf < 8; nf++) {
            sc[nf][0] = __expf(sc[nf][0] - mn0); rs0 += sc[nf][0];
            sc[nf][1] = __expf(sc[nf][1] - mn0); rs0 += sc[nf][1];
            sc[nf][2] = __expf(sc[nf][2] - mn1); rs1 += sc[nf][2];
            sc[nf][3] = __expf(sc[nf][3] - mn1); rs1 += sc[nf][3];
        }
        rs0 += __shfl_xor_sync(0xffffffffu, rs0, 1);
        rs0 += __shfl_xor_sync(0xffffffffu, rs0, 2);
        rs1 += __shfl_xor_sync(0xffffffffu, rs1, 1);
        rs1 += __shfl_xor_sync(0xffffffffu, rs1, 2);
        l0 = l0 * e0 + rs0; l1 = l1 * e1 + rs1;
        m0 = mn0; m1 = mn1;
        #pragma unroll
        for (int nf = 0; nf < 8; nf++) {
            o[nf][0] *= e0; o[nf][1] *= e0; o[nf][2] *= e1; o[nf][3] *= e1;
        }

        uint32_t phi[4][4], plo[4][4];
        #pragma unroll
        for (int kc = 0; kc < 4; kc++) {
            float* A = sc[2 * kc];
            float* B = sc[2 * kc + 1];
            phi[kc][0] = packbf(A[0], A[1]); phi[kc][1] = packbf(A[2], A[3]);
            phi[kc][2] = packbf(B[0], B[1]); phi[kc][3] = packbf(B[2], B[3]);
            plo[kc][0] = packbf(bfres(A[0]), bfres(A[1]));
            plo[kc][1] = packbf(bfres(A[2]), bfres(A[3]));
            plo[kc][2] = packbf(bfres(B[0]), bfres(B[1]));
            plo[kc][3] = packbf(bfres(B[2]), bfres(B[3]));
        }

        #pragma unroll
        for (int pass = 0; pass < 3; pass++) {
            uint32_t vB = (pass == 1) ? VlB : VhB;
            #pragma unroll
            for (int kc = 0; kc < 4; kc++) {
                const uint32_t* pf = (pass == 2) ? plo[kc] : phi[kc];
                #pragma unroll
                for (int nf = 0; nf < 8; nf++) {
                    uint32_t bf2[2];
                    ldsm2t(bf2, vB + (uint32_t)((kc * 16 + ((lane >> 3) & 1) * 8 + l8) * AT_PITCH
                                                + nf * 8) * 2);
                    mma_bf16(o[nf], pf, bf2);
                }
            }
        }
    }

    float inv0 = 1.f / l0, inv1 = 1.f / l1;
    int r0 = q0 + mrow + g;
    #pragma unroll
    for (int nf = 0; nf < 8; nf++) {
        int cc = h * DH + nf * 8 + t2;
        size_t i0 = ((size_t)(b * TLEN + r0)) * DMODEL + cc;
        size_t i1 = ((size_t)(b * TLEN + r0 + 8)) * DMODEL + cc;
        float v0 = o[nf][0] * inv0, v1 = o[nf][1] * inv0;
        float w0 = o[nf][2] * inv1, w1 = o[nf][3] * inv1;
        *(uint32_t*)(Ohi + i0) = packbf(v0, v1);
        *(uint32_t*)(Olo + i0) = packbf(bfres(v0), bfres(v1));
        *(uint32_t*)(Ohi + i1) = packbf(w0, w1);
        *(uint32_t*)(Olo + i1) = packbf(bfres(w0), bfres(w1));
    }
}

// ---------------- layernorm (emits split(cur)) ----------------
__global__ void ln_kernel(const float* __restrict__ X, float* __restrict__ Y,
                          const float* __restrict__ gw, const float* __restrict__ bw)
{
    __shared__ float red[128];
    int row = blockIdx.x, tid = threadIdx.x;
    const float* xr = X + (size_t)row * DMODEL;
    float v[4]; float s = 0.f;
    #pragma unroll
    for (int i = 0; i < 4; i++) { v[i] = xr[tid + 128 * i]; s += v[i]; }
    red[tid] = s; __syncthreads();
    for (int off = 64; off > 0; off >>= 1) {
        if (tid < off) red[tid] += red[tid + off];
        __syncthreads();
    }
    float mu = red[0] * (1.f / 512.f);
    __syncthreads();
    float s2 = 0.f;
    #pragma unroll
    for (int i = 0; i < 4; i++) { float d = v[i] - mu; s2 += d * d; }
    red[tid] = s2; __syncthreads();
    for (int off = 64; off > 0; off >>= 1) {
        if (tid < off) red[tid] += red[tid + off];
        __syncthreads();
    }
    float inv = rsqrtf(red[0] * (1.f / 512.f) + 1e-5f);
    #pragma unroll
    for (int i = 0; i < 4; i++) {
        int c = tid + 128 * i;
        float y = (v[i] - mu) * inv * gw[c] + bw[c];
        size_t idx = (size_t)row * DMODEL + c;
        Y[idx] = y;
        __nv_bfloat16 h = __float2bfloat16(y);
        g_ahi[idx] = h;
        g_alo[idx] = __float2bfloat16(y - __bfloat162float(h));
    }
}

// ---------------- aux ----------------
__global__ void aux_kernel(float* __restrict__ dst)
{
    float tot = 0.f;
    for (int l = 0; l < NLAYER; l++) {
        float m = 0.f;
        for (int e = 0; e < NEXP; e++) m += g_imp[l * 4 + e];
        m *= 0.25f;
        float var = 0.f;
        for (int e = 0; e < NEXP; e++) { float d = g_imp[l * 4 + e] - m; var += d * d; }
        var *= 0.25f;
        tot += var / (m * m + 1e-9f);
    }
    dst[0] = tot;
}

// ---------------- launcher ----------------
extern "C" void kernel_launch(void* const* d_in, const int* in_sizes, int n_in,
                              void* d_out, int out_size)
{
    const float* x         = (const float*)d_in[0];
    const int*   seq       = (const int*)  d_in[1];
    const float* emb_w1    = (const float*)d_in[2];
    const float* emb_b1    = (const float*)d_in[3];
    const float* emb_w2    = (const float*)d_in[4];
    const float* emb_wo    = (const float*)d_in[5];
    const float* f0_w1     = (const float*)d_in[6];
    const float* f0_b1     = (const float*)d_in[7];
    const float* f0_w2     = (const float*)d_in[8];
    const float* f0_router = (const float*)d_in[9];
    const float* f0_fb     = (const float*)d_in[10];
    const float* f0_fa     = (const float*)d_in[11];
    const float* f_w1      = (const float*)d_in[12];
    const float* f_b1      = (const float*)d_in[13];
    const float* f_w2      = (const float*)d_in[14];
    const float* f_router  = (const float*)d_in[15];
    const float* f_fb      = (const float*)d_in[16];
    const float* f_fa      = (const float*)d_in[17];
    const float* wq        = (const float*)d_in[18];
    const float* wk        = (const float*)d_in[19];
    const float* wv        = (const float*)d_in[20];
    const float* wvo       = (const float*)d_in[21];
    const float* mk        = (const float*)d_in[22];
    const float* mv        = (const float*)d_in[23];
    const float* lng       = (const float*)d_in[24];
    const float* lnb       = (const float*)d_in[25];
    const float* out_w     = (const float*)d_in[26];
    const float* out_b     = (const float*)d_in[27];
    float* out = (float*)d_out;

    float *embed, *cur, *p, *tmp, *gtok, *imp;
    int *cnt, *lists, *maps;
    __nv_bfloat16 *whi, *wlo, *ahi, *alo, *bhi, *blo, *ehi, *elo, *xhi, *xlo, *qkvh, *qkvl;
    cudaGetSymbolAddress((void**)&embed, g_embed);
    cudaGetSymbolAddress((void**)&cur,   g_cur);
    cudaGetSymbolAddress((void**)&p,     g_p);
    cudaGetSymbolAddress((void**)&tmp,   g_tmp);
    cudaGetSymbolAddress((void**)&gtok,  g_gtok);
    cudaGetSymbolAddress((void**)&imp,   g_imp);
    cudaGetSymbolAddress((void**)&cnt,   g_cnt);
    cudaGetSymbolAddress((void**)&lists, g_lists);
    cudaGetSymbolAddress((void**)&maps,  g_maps);
    cudaGetSymbolAddress((void**)&whi,   g_whi);
    cudaGetSymbolAddress((void**)&wlo,   g_wlo);
    cudaGetSymbolAddress((void**)&ahi,   g_ahi);
    cudaGetSymbolAddress((void**)&alo,   g_alo);
    cudaGetSymbolAddress((void**)&bhi,   g_bhi);
    cudaGetSymbolAddress((void**)&blo,   g_blo);
    cudaGetSymbolAddress((void**)&ehi,   g_ehi);
    cudaGetSymbolAddress((void**)&elo,   g_elo);
    cudaGetSymbolAddress((void**)&xhi,   g_xhi);
    cudaGetSymbolAddress((void**)&xlo,   g_xlo);
    cudaGetSymbolAddress((void**)&qkvh,  g_qkvh);
    cudaGetSymbolAddress((void**)&qkvl,  g_qkvl);

    cudaFuncSetAttribute(attn_mma, cudaFuncAttributeMaxDynamicSharedMemorySize, ATTN_SMEM);
    cudaFuncSetAttribute(tgemm<128>, cudaFuncAttributeMaxDynamicSharedMemorySize, TG_SMEM128);
    cudaFuncSetAttribute(tgemm<64>,  cudaFuncAttributeMaxDynamicSharedMemorySize, TG_SMEM64);
    cudaFuncSetAttribute(tgemm<32>,  cudaFuncAttributeMaxDynamicSharedMemorySize, TG_SMEM32);

    cudaStream_t s1;
    cudaStreamCreate(&s1);
    cudaEvent_t evF, evJ, evE0, evE1;
    cudaEventCreateWithFlags(&evF, cudaEventDisableTiming);
    cudaEventCreateWithFlags(&evJ, cudaEventDisableTiming);
    cudaEventCreateWithFlags(&evE0, cudaEventDisableTiming);
    cudaEventCreateWithFlags(&evE1, cudaEventDisableTiming);

    auto TG = [&](unsigned woff, const __nv_bfloat16* Ah, const __nv_bfloat16* Al,
                  float* C, __nv_bfloat16* Ch, __nv_bfloat16* Cl,
                  int M, int N, int K,
                  const float* bias, int relu, const int* ga, const int* sc,
                  const float* rs, const float* res, const int* Md,
                  int E = 1, int sB = 0, int sBias = 0, int sList = 0,
                  cudaStream_t st = 0) {
        dim3 grid(N / 128, (M + 127) / 128, E);
        tgemm<128><<<grid, 256, TG_SMEM128, st>>>(Ah, Al, whi + woff, wlo + woff, C, Ch, Cl,
                                                  N, K, M, bias, relu, ga, sc, rs, res, Md,
                                                  sB, sBias, sList);
    };
    auto TG64 = [&](unsigned woff, const __nv_bfloat16* Ah, const __nv_bfloat16* Al,
                    float* C, __nv_bfloat16* Ch, __nv_bfloat16* Cl,
                    int M, int N, int K,
                    const float* bias, int relu, const int* ga, const int* sc,
                    const float* rs, const float* res, const int* Md,
                    int E = 1, int sB = 0, int sBias = 0, int sList = 0,
                    cudaStream_t st = 0) {
        dim3 grid(N / 128, (M + 63) / 64, E);
        tgemm<64><<<grid, 256, TG_SMEM64, st>>>(Ah, Al, whi + woff, wlo + woff, C, Ch, Cl,
                                                N, K, M, bias, relu, ga, sc, rs, res, Md,
                                                sB, sBias, sList);
    };
    auto TG32 = [&](unsigned woff, const __nv_bfloat16* Ah, const __nv_bfloat16* Al,
                    float* C, __nv_bfloat16* Ch, __nv_bfloat16* Cl,
                    int M, int N, int K,
                    const float* bias, int relu, const int* ga, const int* sc,
                    const float* rs, const float* res, const int* Md,
                    int E = 1, int sB = 0, int sBias = 0, int sList = 0,
                    cudaStream_t st = 0) {
        dim3 grid(N / 128, (M + 31) / 32, E);
        tgemm<32><<<grid, 256, TG_SMEM32, st>>>(Ah, Al, whi + woff, wlo + woff, C, Ch, Cl,
                                                N, K, M, bias, relu, ga, sc, rs, res, Md,
                                                sB, sBias, sList);
    };
    auto WS = [&](const float* W, unsigned off, int nelem, cudaStream_t st) {
        wsplit<<<(nelem / 4 + 255) / 256, 256, 0, st>>>(W, whi + off, wlo + off, nelem / 4);
    };

    init_kernel<<<1, 1024>>>();

    // main-stream prep
    xsplit<<<(NTOK * KPAD + 255) / 256, 256>>>(x);
    wsplit_pad<<<(KPAD * 1024 / 4 + 255) / 256, 256>>>(emb_w1, whi + OFF_EMBW1,
                                                       wlo + OFF_EMBW1, 1024, KPAD * 1024 / 4);
    wsplit_pad<<<(NEXP * KPAD * 1024 / 4 + 255) / 256, 256>>>(f0_w1, whi + OFF_F0W1,
                                                              wlo + OFF_F0W1, 1024,
                                                              NEXP * KPAD * 1024 / 4);
    WS(emb_w2, OFF_EMBW2, 1024 * 512, 0);
    WS(f0_w2,  OFF_F0W2, 4 * 1024 * 512, 0);

    // side-stream weight splits
    cudaEventRecord(evF, 0);
    cudaStreamWaitEvent(s1, evF, 0);
    WS(emb_wo, OFF_EMBWO, 512 * 4096, s1);
    WS(f_w1, OFF_FW1, 28 * 512 * 1024, s1);
    WS(f_w2, OFF_FW2, 28 * 1024 * 512, s1);
    for (int bi = 0; bi < 2; bi++) {
        WS(wq + (size_t)bi * MAT_SZ, OFF_QKV + bi * 3u * MAT_SZ + 0u * MAT_SZ, MAT_SZ, s1);
        WS(wk + (size_t)bi * MAT_SZ, OFF_QKV + bi * 3u * MAT_SZ + 1u * MAT_SZ, MAT_SZ, s1);
        WS(wv + (size_t)bi * MAT_SZ, OFF_QKV + bi * 3u * MAT_SZ + 2u * MAT_SZ, MAT_SZ, s1);
    }
    WS(wvo,   OFF_WO, 2 * 512 * 512, s1);
    WS(out_w, OFF_OUTW, 512 * 4096, s1);
    cudaEventRecord(evJ, s1);

    // embed sub-network
    TG64(OFF_EMBW1, xhi, xlo, 0, bhi, blo, NTOK, DHID, KPAD, emb_b1, 1, 0, 0, 0, 0, 0);
    TG64(OFF_EMBW2, bhi, blo, embed, ehi, elo, NTOK, DMODEL, DHID, 0, 0, 0, 0, 0, 0, 0);
    cudaEventRecord(evE0, 0);

    // embed_out on side stream (512 CTAs -> keep 128-tile)
    cudaStreamWaitEvent(s1, evE0, 0);
    TG(OFF_EMBWO, ehi, elo, out + (size_t)NTOK * DOUT, 0, 0, NTOK, DOUT, DMODEL,
       0, 0, 0, 0, 0, 0, 0, 1, 0, 0, 0, s1);
    cudaEventRecord(evE1, s1);

    router_all<<<dim3(NTOK / 8, NLAYER), 256>>>(embed, f0_router, f_router, seq,
                                                gtok, lists, cnt, imp);

    for (int l = 0; l < NLAYER; l++) {
        int* lst = lists + (size_t)l * NEXP * NTOK;
        float* gt = gtok + (size_t)l * NTOK;
        int* ct = cnt + l * 4;

        if (l == 1) cudaStreamWaitEvent(0, evJ, 0);

        if (l == 0) {
            TG64(OFF_F0W1, xhi, xlo, 0, bhi, blo, NTOK, DHID, KPAD,
                 f0_b1, 1, lst, lst, 0, 0, ct, NEXP, KPAD * DHID, DHID, NTOK);
            TG32(OFF_F0W2, bhi, blo, p, 0, 0, NTOK, DMODEL, DHID, 0, 0, lst, lst,
                 gt, 0, ct, NEXP, DMODEL * DHID, 0, NTOK);
        } else {
            TG64(OFF_FW1 + (unsigned)(l - 1) * 4u * DMODEL * DHID, ahi, alo,
                 0, bhi, blo, NTOK, DHID, DMODEL,
                 f_b1 + (size_t)(l - 1) * NEXP * DHID, 1, lst, lst, 0, 0, ct,
                 NEXP, DMODEL * DHID, DHID, NTOK);
            TG32(OFF_FW2 + (unsigned)(l - 1) * 4u * DHID * DMODEL, bhi, blo,
                 p, 0, 0, NTOK, DMODEL, DHID,
                 0, 0, lst, lst, gt, 0, ct,
                 NEXP, DHID * DMODEL, 0, NTOK);
        }
        const float* fbL = (l == 0) ? f0_fb : f_fb + (size_t)(l - 1) * 4 * DMODEL;
        const float* faL = (l == 0) ? f0_fa : f_fa + (size_t)(l - 1) * DMODEL;
        fsmn_kernel<<<NTOK * DMODEL / 256, 256>>>(p, fbL, faL,
                                                  (l == 0) ? (const float*)0 : cur, cur,
                                                  l == 3 ? 1 : 0);

        if (l == 3 || l == 7) {
            int bi = l / 4;
            TG64(OFF_QKV + (unsigned)bi * 3u * MAT_SZ, ahi, alo, 0, qkvh, qkvl,
                 NTOK, DMODEL, DMODEL, 0, 0, 0, maps, 0, 0, 0, 3, MAT_SZ, 0, NTOK);
            memrows_kernel<<<BATCH * MMEM * DMODEL / 256, 256>>>(
                mk + (size_t)bi * MMEM * DMODEL, mv + (size_t)bi * MMEM * DMODEL);
            attn_mma<<<dim3(TLEN / 128, NHEAD, BATCH), 256, ATTN_SMEM>>>(
                qkvh, qkvl,
                qkvh + (size_t)NTOK * DMODEL, qkvl + (size_t)NTOK * DMODEL,
                qkvh + (size_t)(NTOK + BSF) * DMODEL, qkvl + (size_t)(NTOK + BSF) * DMODEL,
                seq, bhi, blo);
            TG32(OFF_WO + (unsigned)bi * MAT_SZ, bhi, blo, tmp, 0, 0,
                 NTOK, DMODEL, DMODEL, 0, 0, 0, 0, 0, cur, 0);
            ln_kernel<<<NTOK, 128>>>(tmp, cur, lng + bi * DMODEL, lnb + bi * DMODEL);
        }
    }

    TG(OFF_OUTW, ahi, alo, out, 0, 0, NTOK, DOUT, DMODEL, out_b, 0, 0, 0, 0, 0, 0);
    cudaStreamWaitEvent(0, evE1, 0);
    aux_kernel<<<1, 1>>>(out + 2 * (size_t)NTOK * DOUT);
}